// round 1
// baseline (speedup 1.0000x reference)
#include <cuda_runtime.h>
#include <cstdint>
#include <cstdio>

// ---------------- problem dims (fixed) ----------------
#define NTOK   18000      // F*H*W = 12*30*50
#define DIMC   1536
#define NHEAD  12
#define HDIM   128
#define NBLK   150        // FB*HB*WB = 3*5*10
#define PBLK   120        // P1*P2*P3 = 4*6*5
#define EPSF   1e-6f

typedef unsigned long long ull;

// ---------------- f32x2 helpers (Blackwell packed fp32) ----------------
__device__ __forceinline__ ull ffma2(ull a, ull b, ull c) {
    ull d;
    asm("fma.rn.f32x2 %0, %1, %2, %3;" : "=l"(d) : "l"(a), "l"(b), "l"(c));
    return d;
}
__device__ __forceinline__ ull pack2(float x, float y) {
    ull r;
    asm("mov.b64 %0, {%1, %2};" : "=l"(r) : "f"(x), "f"(y));
    return r;
}
__device__ __forceinline__ void unpack2(ull v, float& x, float& y) {
    asm("mov.b64 {%0, %1}, %2;" : "=f"(x), "=f"(y) : "l"(v));
}

// ---------------- scratch (static device globals; no runtime alloc) ----------------
__device__ float Qbuf[NTOK * DIMC];            // 110.6 MB
__device__ float Kbuf[NTOK * DIMC];
__device__ float Vbuf[NTOK * DIMC];
__device__ float AObuf[NTOK * DIMC];
__device__ float KVbuf[NHEAD * NBLK * HDIM * HDIM];    // 118 MB
__device__ float KVMIXbuf[NHEAD * NBLK * HDIM * HDIM]; // 118 MB
__device__ float KSUMbuf[NHEAD * NBLK * HDIM];
__device__ float QKbuf[NHEAD * NBLK * PBLK];
__device__ float NORMbuf[NHEAD * NBLK * PBLK];
__device__ float WBLKbuf[NBLK * NBLK];

// token index for (block nb, in-block pos p)
__device__ __forceinline__ int tok_of(int nb, int p) {
    int fb = nb / 50, hb = (nb / 10) % 5, wb = nb % 10;
    int p1 = p / 30, p2 = (p / 5) % 6, p3 = p % 5;
    int f = fb * 4 + p1, h = hb * 6 + p2, w = wb * 5 + p3;
    return (f * 30 + h) * 50 + w;
}

// ---------------- W_BLK: 150x150 block mixing matrix ----------------
// mat[i][j] = 1 - d(i,j)/sqrt(101); column-normalized (sum over rows = 1).
__global__ void wblk_kernel() {
    int j = blockIdx.x;            // column
    int i = threadIdx.x;           // row
    __shared__ double ssum[256];
    double m = 0.0;
    if (i < NBLK) {
        int fi = i / 50, hi = (i / 10) % 5, wi = i % 10;
        int fj = j / 50, hj = (j / 10) % 5, wj = j % 10;
        double df = fi - fj, dh = hi - hj, dw = wi - wj;
        double d = sqrt(df * df + dh * dh + dw * dw);
        m = 1.0 - d / sqrt(101.0);
    }
    ssum[i] = m;
    __syncthreads();
    for (int s = 128; s > 0; s >>= 1) {
        if (i < s) ssum[i] += ssum[i + s];
        __syncthreads();
    }
    if (i < NBLK) WBLKbuf[i * NBLK + j] = (float)(m / ssum[0]);
}

// ---------------- GEMM: C[m,n] = sum_k A[m,k]*B[n,k] + bias[n] ----------------
// 128x128x16 tile, 256 threads, 8x8 micro-tile, f32x2 packed FMA.
__global__ __launch_bounds__(256, 2) void gemm_nt_bias(
    const float* __restrict__ A, const float* __restrict__ B,
    const float* __restrict__ bias, float* __restrict__ C,
    int M, int N, int K)
{
    __shared__ __align__(16) float As[16][128];
    __shared__ __align__(16) float Bs[16][128];
    int tid = threadIdx.x;
    int m0 = blockIdx.x * 128, n0 = blockIdx.y * 128;
    int tx = tid & 15, ty = tid >> 4;
    int lr = tid >> 1;          // tile row 0..127
    int lk = (tid & 1) * 8;     // k offset 0 or 8
    const float* Ap = A + (size_t)(m0 + lr) * K + lk;
    const float* Bp = B + (size_t)(n0 + lr) * K + lk;
    bool aval = (m0 + lr) < M;

    ull acc[8][4];
#pragma unroll
    for (int i = 0; i < 8; i++)
#pragma unroll
        for (int jj = 0; jj < 4; jj++) acc[i][jj] = 0ULL;

    for (int k0 = 0; k0 < K; k0 += 16) {
        float4 a0 = make_float4(0.f, 0.f, 0.f, 0.f), a1 = a0;
        if (aval) {
            a0 = *(const float4*)(Ap + k0);
            a1 = *(const float4*)(Ap + k0 + 4);
        }
        float4 b0 = *(const float4*)(Bp + k0);
        float4 b1 = *(const float4*)(Bp + k0 + 4);
        As[lk + 0][lr] = a0.x; As[lk + 1][lr] = a0.y; As[lk + 2][lr] = a0.z; As[lk + 3][lr] = a0.w;
        As[lk + 4][lr] = a1.x; As[lk + 5][lr] = a1.y; As[lk + 6][lr] = a1.z; As[lk + 7][lr] = a1.w;
        Bs[lk + 0][lr] = b0.x; Bs[lk + 1][lr] = b0.y; Bs[lk + 2][lr] = b0.z; Bs[lk + 3][lr] = b0.w;
        Bs[lk + 4][lr] = b1.x; Bs[lk + 5][lr] = b1.y; Bs[lk + 6][lr] = b1.z; Bs[lk + 7][lr] = b1.w;
        __syncthreads();
#pragma unroll
        for (int k = 0; k < 16; k++) {
            float4 af0 = *(const float4*)&As[k][ty * 8];
            float4 af1 = *(const float4*)&As[k][ty * 8 + 4];
            ulonglong2 bp0 = *(const ulonglong2*)&Bs[k][tx * 8];
            ulonglong2 bp1 = *(const ulonglong2*)&Bs[k][tx * 8 + 4];
            ull bb0 = bp0.x, bb1 = bp0.y, bb2 = bp1.x, bb3 = bp1.y;
            float a[8] = {af0.x, af0.y, af0.z, af0.w, af1.x, af1.y, af1.z, af1.w};
#pragma unroll
            for (int i = 0; i < 8; i++) {
                ull a2 = pack2(a[i], a[i]);
                acc[i][0] = ffma2(a2, bb0, acc[i][0]);
                acc[i][1] = ffma2(a2, bb1, acc[i][1]);
                acc[i][2] = ffma2(a2, bb2, acc[i][2]);
                acc[i][3] = ffma2(a2, bb3, acc[i][3]);
            }
        }
        __syncthreads();
    }
#pragma unroll
    for (int i = 0; i < 8; i++) {
        int m = m0 + ty * 8 + i;
        if (m < M) {
#pragma unroll
            for (int jj = 0; jj < 4; jj++) {
                float v0, v1;
                unpack2(acc[i][jj], v0, v1);
                int c0 = n0 + tx * 8 + 2 * jj;
                C[(size_t)m * N + c0]     = v0 + bias[c0];
                C[(size_t)m * N + c0 + 1] = v1 + bias[c0 + 1];
            }
        }
    }
}

// ---------------- rmsnorm + relu + eps (in place on Q / K) ----------------
__global__ void rmsnorm_kernel(const float* __restrict__ nqw, const float* __restrict__ nkw) {
    int n = blockIdx.x;
    float* buf = blockIdx.y ? Kbuf : Qbuf;
    const float* w = blockIdx.y ? nkw : nqw;
    int tid = threadIdx.x;
    size_t base = (size_t)n * DIMC;
    float vals[6];
    float ss = 0.f;
#pragma unroll
    for (int t = 0; t < 6; t++) {
        float v = buf[base + tid + t * 256];
        vals[t] = v;
        ss += v * v;
    }
    for (int o = 16; o > 0; o >>= 1) ss += __shfl_xor_sync(0xffffffffu, ss, o);
    __shared__ float red[8];
    __shared__ float stot;
    if ((tid & 31) == 0) red[tid >> 5] = ss;
    __syncthreads();
    if (tid == 0) {
        float t = 0.f;
        for (int i = 0; i < 8; i++) t += red[i];
        stot = t;
    }
    __syncthreads();
    float sc = 1.0f / sqrtf(stot * (1.0f / DIMC) + EPSF);
#pragma unroll
    for (int t = 0; t < 6; t++) {
        int c = tid + t * 256;
        float v = vals[t] * sc * w[c];
        buf[base + c] = fmaxf(v, 0.f) + EPSF;
    }
}

// ---------------- ksum[h,nb,d] = sum_p k_blocked (pre-rope) ----------------
__global__ void ksum_kernel() {
    int b = blockIdx.x;                 // h*150 + nb
    int hh = b / NBLK, nb = b % NBLK;
    int d = threadIdx.x;
    float acc = 0.f;
    for (int p = 0; p < PBLK; p++) {
        int t = tok_of(nb, p);
        acc += Kbuf[(size_t)t * DIMC + hh * HDIM + d];
    }
    KSUMbuf[b * HDIM + d] = acc;
}

// ---------------- qk[h,nb,p] = dot(q_blocked(pre-rope), ksum) ----------------
__global__ void qk_kernel() {
    int b = blockIdx.x;
    int hh = b / NBLK, nb = b % NBLK;
    int tid = threadIdx.x;
    __shared__ float ks[HDIM];
    ks[tid] = KSUMbuf[b * HDIM + tid];
    __syncthreads();
    if (tid < PBLK) {
        int t = tok_of(nb, tid);
        const float* q = Qbuf + (size_t)t * DIMC + hh * HDIM;
        float acc = 0.f;
#pragma unroll 4
        for (int d = 0; d < HDIM; d++) acc += q[d] * ks[d];
        QKbuf[b * PBLK + tid] = acc;
    }
}

// ---------------- RoPE in place on Q and K ----------------
__global__ void rope_kernel(const float* __restrict__ fc, const float* __restrict__ fs) {
    int idx = blockIdx.x * 256 + threadIdx.x;   // over NTOK*NHEAD*64
    if (idx >= NTOK * NHEAD * 64) return;
    int n = idx / (NHEAD * 64);
    int r = idx % (NHEAD * 64);
    int nh = r / 64, c = r % 64;
    float* buf = blockIdx.y ? Kbuf : Qbuf;
    int f = n / 1500, rem = n % 1500;
    int h = rem / 50, w = rem % 50;
    int pos = (c < 22) ? f : ((c < 43) ? h : w);
    float cs = fc[pos * 64 + c];
    float sn = fs[pos * 64 + c];
    size_t base = (size_t)n * DIMC + nh * HDIM + 2 * c;
    float x0 = buf[base], x1 = buf[base + 1];
    buf[base]     = x0 * cs - x1 * sn;
    buf[base + 1] = x0 * sn + x1 * cs;
}

// ---------------- kv[h,nb,d,e] = sum_p k_rope[p,d]*v[p,e] ----------------
__global__ __launch_bounds__(256) void kv_kernel() {
    extern __shared__ __align__(16) float sm[];
    float* sK = sm;            // [120][128]
    float* sV = sm + PBLK * HDIM;
    int b = blockIdx.x;
    int hh = b / NBLK, nb = b % NBLK;
    int tid = threadIdx.x;
    for (int idx = tid; idx < PBLK * HDIM; idx += 256) {
        int p = idx >> 7, d = idx & 127;
        int t = tok_of(nb, p);
        size_t g = (size_t)t * DIMC + hh * HDIM + d;
        sK[idx] = Kbuf[g];
        sV[idx] = Vbuf[g];
    }
    __syncthreads();
    int tx = tid & 15, ty = tid >> 4;
    int e0 = tx * 8, d0 = ty * 8;
    ull acc[8][4];
#pragma unroll
    for (int i = 0; i < 8; i++)
#pragma unroll
        for (int jj = 0; jj < 4; jj++) acc[i][jj] = 0ULL;
    for (int p = 0; p < PBLK; p++) {
        float4 k1 = *(const float4*)&sK[p * HDIM + d0];
        float4 k2 = *(const float4*)&sK[p * HDIM + d0 + 4];
        ulonglong2 v1 = *(const ulonglong2*)&sV[p * HDIM + e0];
        ulonglong2 v2 = *(const ulonglong2*)&sV[p * HDIM + e0 + 4];
        ull bb0 = v1.x, bb1 = v1.y, bb2 = v2.x, bb3 = v2.y;
        float a[8] = {k1.x, k1.y, k1.z, k1.w, k2.x, k2.y, k2.z, k2.w};
#pragma unroll
        for (int i = 0; i < 8; i++) {
            ull a2 = pack2(a[i], a[i]);
            acc[i][0] = ffma2(a2, bb0, acc[i][0]);
            acc[i][1] = ffma2(a2, bb1, acc[i][1]);
            acc[i][2] = ffma2(a2, bb2, acc[i][2]);
            acc[i][3] = ffma2(a2, bb3, acc[i][3]);
        }
    }
    float* dst = KVbuf + (size_t)b * HDIM * HDIM;
#pragma unroll
    for (int i = 0; i < 8; i++) {
#pragma unroll
        for (int jj = 0; jj < 4; jj++) {
            float v0x, v1x;
            unpack2(acc[i][jj], v0x, v1x);
            int e = e0 + 2 * jj;
            dst[(d0 + i) * HDIM + e]     = v0x;
            dst[(d0 + i) * HDIM + e + 1] = v1x;
        }
    }
}

// ---------------- kvmix[h,o,:] = sum_i W[o,i] * kv[h,i,:] ----------------
__global__ __launch_bounds__(256) void mix_kernel() {
    extern __shared__ __align__(16) float sm[];
    float* Ws = sm;                 // 150*150
    float* tB = sm + NBLK * NBLK;   // 150*128
    int hh = blockIdx.y, xt = blockIdx.x;   // xt: 128-wide slice of 16384
    int tid = threadIdx.x;
    for (int idx = tid; idx < NBLK * NBLK; idx += 256) Ws[idx] = WBLKbuf[idx];
    const float* src = KVbuf + (size_t)hh * NBLK * HDIM * HDIM + xt * 128;
    for (int idx = tid; idx < NBLK * 128; idx += 256) {
        int i = idx >> 7, c = idx & 127;
        tB[idx] = src[(size_t)i * HDIM * HDIM + c];
    }
    __syncthreads();
    int tx = tid & 15, ty = tid >> 4;
    ull acc[10][4];
#pragma unroll
    for (int oo = 0; oo < 10; oo++)
#pragma unroll
        for (int jj = 0; jj < 4; jj++) acc[oo][jj] = 0ULL;
    for (int i = 0; i < NBLK; i++) {
        ulonglong2 b1 = *(const ulonglong2*)&tB[i * 128 + tx * 8];
        ulonglong2 b2 = *(const ulonglong2*)&tB[i * 128 + tx * 8 + 4];
        ull bb0 = b1.x, bb1 = b1.y, bb2 = b2.x, bb3 = b2.y;
#pragma unroll
        for (int oo = 0; oo < 10; oo++) {
            int o = ty + 16 * oo;
            if (o < NBLK) {
                float w = Ws[o * NBLK + i];
                ull w2 = pack2(w, w);
                acc[oo][0] = ffma2(w2, bb0, acc[oo][0]);
                acc[oo][1] = ffma2(w2, bb1, acc[oo][1]);
                acc[oo][2] = ffma2(w2, bb2, acc[oo][2]);
                acc[oo][3] = ffma2(w2, bb3, acc[oo][3]);
            }
        }
    }
#pragma unroll
    for (int oo = 0; oo < 10; oo++) {
        int o = ty + 16 * oo;
        if (o < NBLK) {
            float* dst = KVMIXbuf + ((size_t)hh * NBLK + o) * HDIM * HDIM + xt * 128 + tx * 8;
#pragma unroll
            for (int jj = 0; jj < 4; jj++) {
                float v0x, v1x;
                unpack2(acc[oo][jj], v0x, v1x);
                dst[2 * jj]     = v0x;
                dst[2 * jj + 1] = v1x;
            }
        }
    }
}

// ---------------- norm[h,o,p] = eps + sum_i W[o,i]*qk[h,i,p] ----------------
__global__ void norm_kernel() {
    int b = blockIdx.x;
    int hh = b / NBLK, o = b % NBLK;
    int p = threadIdx.x;
    if (p >= PBLK) return;
    float acc = EPSF;
    for (int i = 0; i < NBLK; i++)
        acc += WBLKbuf[o * NBLK + i] * QKbuf[(hh * NBLK + i) * PBLK + p];
    NORMbuf[b * PBLK + p] = acc;
}

// ---------------- out[h,nb,p,e] = (sum_d qr[p,d]*kvmix[d,e]) / norm[p] ----------------
__global__ __launch_bounds__(256) void out_kernel() {
    extern __shared__ __align__(16) float sm[];
    float* sQt = sm;                  // [128][120]  (d-major, transposed)
    float* sKV = sm + HDIM * PBLK;    // [128][128]
    int b = blockIdx.x;
    int hh = b / NBLK, nb = b % NBLK;
    int tid = threadIdx.x;
    for (int idx = tid; idx < PBLK * HDIM; idx += 256) {
        int p = idx >> 7, d = idx & 127;
        int t = tok_of(nb, p);
        sQt[d * PBLK + p] = Qbuf[(size_t)t * DIMC + hh * HDIM + d];
    }
    const float* kvsrc = KVMIXbuf + (size_t)b * HDIM * HDIM;
    for (int idx = tid; idx < HDIM * HDIM; idx += 256) sKV[idx] = kvsrc[idx];
    __syncthreads();
    int tx = tid & 15, ty = tid >> 4;
    if (ty >= 15) return;             // 15*8 = 120 rows
    int e0 = tx * 8, p0 = ty * 8;
    ull acc[8][4];
#pragma unroll
    for (int i = 0; i < 8; i++)
#pragma unroll
        for (int jj = 0; jj < 4; jj++) acc[i][jj] = 0ULL;
    for (int d = 0; d < HDIM; d++) {
        float4 q1 = *(const float4*)&sQt[d * PBLK + p0];
        float4 q2 = *(const float4*)&sQt[d * PBLK + p0 + 4];
        ulonglong2 k1 = *(const ulonglong2*)&sKV[d * HDIM + e0];
        ulonglong2 k2 = *(const ulonglong2*)&sKV[d * HDIM + e0 + 4];
        ull bb0 = k1.x, bb1 = k1.y, bb2 = k2.x, bb3 = k2.y;
        float a[8] = {q1.x, q1.y, q1.z, q1.w, q2.x, q2.y, q2.z, q2.w};
#pragma unroll
        for (int i = 0; i < 8; i++) {
            ull a2 = pack2(a[i], a[i]);
            acc[i][0] = ffma2(a2, bb0, acc[i][0]);
            acc[i][1] = ffma2(a2, bb1, acc[i][1]);
            acc[i][2] = ffma2(a2, bb2, acc[i][2]);
            acc[i][3] = ffma2(a2, bb3, acc[i][3]);
        }
    }
#pragma unroll
    for (int i = 0; i < 8; i++) {
        int p = p0 + i;
        float inv = 1.0f / NORMbuf[b * PBLK + p];
        int t = tok_of(nb, p);
        float* dst = AObuf + (size_t)t * DIMC + hh * HDIM + e0;
#pragma unroll
        for (int jj = 0; jj < 4; jj++) {
            float v0x, v1x;
            unpack2(acc[i][jj], v0x, v1x);
            dst[2 * jj]     = v0x * inv;
            dst[2 * jj + 1] = v1x * inv;
        }
    }
}

// ---------------- launch ----------------
extern "C" void kernel_launch(void* const* d_in, const int* in_sizes, int n_in,
                              void* d_out, int out_size) {
    const float* x   = (const float*)d_in[0];
    // d_in[1] seq_lens, d_in[2] grid_sizes: fixed, unused
    const float* fc  = (const float*)d_in[3];
    const float* fs  = (const float*)d_in[4];
    const float* wq  = (const float*)d_in[5];
    const float* bq  = (const float*)d_in[6];
    const float* wk  = (const float*)d_in[7];
    const float* bk  = (const float*)d_in[8];
    const float* wv  = (const float*)d_in[9];
    const float* bv  = (const float*)d_in[10];
    const float* wo  = (const float*)d_in[11];
    const float* bo  = (const float*)d_in[12];
    const float* nqw = (const float*)d_in[13];
    const float* nkw = (const float*)d_in[14];
    float* out = (float*)d_out;

    void *pq, *pk, *pv, *pao;
    cudaGetSymbolAddress(&pq, Qbuf);
    cudaGetSymbolAddress(&pk, Kbuf);
    cudaGetSymbolAddress(&pv, Vbuf);
    cudaGetSymbolAddress(&pao, AObuf);

    const int KV_SMEM  = (PBLK * HDIM * 2) * 4;            // 122880
    const int MIX_SMEM = (NBLK * NBLK + NBLK * 128) * 4;   // 166800
    const int OUT_SMEM = (HDIM * PBLK + HDIM * HDIM) * 4;  // 126976
    cudaFuncSetAttribute(kv_kernel,  cudaFuncAttributeMaxDynamicSharedMemorySize, KV_SMEM);
    cudaFuncSetAttribute(mix_kernel, cudaFuncAttributeMaxDynamicSharedMemorySize, MIX_SMEM);
    cudaFuncSetAttribute(out_kernel, cudaFuncAttributeMaxDynamicSharedMemorySize, OUT_SMEM);

    wblk_kernel<<<NBLK, 256>>>();

    dim3 gg((NTOK + 127) / 128, DIMC / 128);   // 141 x 12
    gemm_nt_bias<<<gg, 256>>>(x, wq, bq, (float*)pq, NTOK, DIMC, DIMC);
    gemm_nt_bias<<<gg, 256>>>(x, wk, bk, (float*)pk, NTOK, DIMC, DIMC);
    gemm_nt_bias<<<gg, 256>>>(x, wv, bv, (float*)pv, NTOK, DIMC, DIMC);

    rmsnorm_kernel<<<dim3(NTOK, 2), 256>>>(nqw, nkw);

    ksum_kernel<<<NHEAD * NBLK, HDIM>>>();
    qk_kernel<<<NHEAD * NBLK, HDIM>>>();

    rope_kernel<<<dim3((NTOK * NHEAD * 64 + 255) / 256, 2), 256>>>(fc, fs);

    kv_kernel<<<NHEAD * NBLK, 256, KV_SMEM>>>();
    mix_kernel<<<dim3(128, NHEAD), 256, MIX_SMEM>>>();
    norm_kernel<<<NHEAD * NBLK, 128>>>();
    out_kernel<<<NHEAD * NBLK, 256, OUT_SMEM>>>();

    gemm_nt_bias<<<gg, 256>>>((const float*)pao, wo, bo, out, NTOK, DIMC, DIMC);
}

// round 3
// speedup vs baseline: 2.2006x; 2.2006x over previous
#include <cuda_runtime.h>
#include <cuda_bf16.h>
#include <cstdint>
#include <cstdio>

// ---------------- problem dims (fixed) ----------------
#define NTOK   18000      // F*H*W = 12*30*50
#define MPAD   18048      // padded to multiple of 128
#define DIMC   1536
#define NHEAD  12
#define HDIM   128
#define NBLK   150        // FB*HB*WB = 3*5*10
#define PBLK   120        // P1*P2*P3 = 4*6*5
#define EPSF   1e-6f

typedef unsigned long long ull;

// ---------------- f32x2 helpers (Blackwell packed fp32) ----------------
__device__ __forceinline__ ull ffma2(ull a, ull b, ull c) {
    ull d;
    asm("fma.rn.f32x2 %0, %1, %2, %3;" : "=l"(d) : "l"(a), "l"(b), "l"(c));
    return d;
}
__device__ __forceinline__ ull pack2(float x, float y) {
    ull r;
    asm("mov.b64 %0, {%1, %2};" : "=l"(r) : "f"(x), "f"(y));
    return r;
}
__device__ __forceinline__ void unpack2(ull v, float& x, float& y) {
    asm("mov.b64 {%0, %1}, %2;" : "=f"(x), "=f"(y) : "l"(v));
}

// ---------------- mma / ldmatrix helpers (baseline PTX, sm_80+) ----------------
__device__ __forceinline__ uint32_t smem_u32(const void* p) {
    uint32_t a;
    asm("{ .reg .u64 t; cvta.to.shared.u64 t, %1; cvt.u32.u64 %0, t; }" : "=r"(a) : "l"(p));
    return a;
}
__device__ __forceinline__ void cp_async16(uint32_t dst, const void* src) {
    asm volatile("cp.async.cg.shared.global [%0], [%1], 16;" :: "r"(dst), "l"(src) : "memory");
}
__device__ __forceinline__ void ldm_x4(uint32_t* r, uint32_t addr) {
    asm volatile("ldmatrix.sync.aligned.m8n8.x4.shared.b16 {%0,%1,%2,%3}, [%4];"
                 : "=r"(r[0]), "=r"(r[1]), "=r"(r[2]), "=r"(r[3]) : "r"(addr));
}
__device__ __forceinline__ void mma16816(float* c, const uint32_t* a, const uint32_t* b) {
    asm volatile("mma.sync.aligned.m16n8k16.row.col.f32.bf16.bf16.f32 "
                 "{%0,%1,%2,%3}, {%4,%5,%6,%7}, {%8,%9}, {%0,%1,%2,%3};"
                 : "+f"(c[0]), "+f"(c[1]), "+f"(c[2]), "+f"(c[3])
                 : "r"(a[0]), "r"(a[1]), "r"(a[2]), "r"(a[3]), "r"(b[0]), "r"(b[1]));
}

// ---------------- scratch (static device globals; no runtime alloc) ----------------
__device__ float Qbuf[NTOK * DIMC];
__device__ float Kbuf[NTOK * DIMC];
__device__ float Vbuf[NTOK * DIMC];
__device__ float AObuf[NTOK * DIMC];
__device__ float KVbuf[NHEAD * NBLK * HDIM * HDIM];
__device__ float KVMIXbuf[NHEAD * NBLK * HDIM * HDIM];
__device__ float KSUMbuf[NHEAD * NBLK * HDIM];
__device__ float QKbuf[NHEAD * NBLK * PBLK];
__device__ float NORMbuf[NHEAD * NBLK * PBLK];
__device__ float WBLKbuf[NBLK * NBLK];

// bf16 hi/lo split buffers for tensor-core GEMMs
__device__ __nv_bfloat16 Xhi[MPAD * DIMC];
__device__ __nv_bfloat16 Xlo[MPAD * DIMC];
__device__ __nv_bfloat16 AOhi[MPAD * DIMC];
__device__ __nv_bfloat16 AOlo[MPAD * DIMC];
__device__ __nv_bfloat16 Whi4[4][DIMC * DIMC];
__device__ __nv_bfloat16 Wlo4[4][DIMC * DIMC];

// token index for (block nb, in-block pos p)
__device__ __forceinline__ int tok_of(int nb, int p) {
    int fb = nb / 50, hb = (nb / 10) % 5, wb = nb % 10;
    int p1 = p / 30, p2 = (p / 5) % 6, p3 = p % 5;
    int f = fb * 4 + p1, h = hb * 6 + p2, w = wb * 5 + p3;
    return (f * 30 + h) * 50 + w;
}

// ---------------- W_BLK ----------------
__global__ void wblk_kernel() {
    int j = blockIdx.x;
    int i = threadIdx.x;
    __shared__ double ssum[256];
    double m = 0.0;
    if (i < NBLK) {
        int fi = i / 50, hi = (i / 10) % 5, wi = i % 10;
        int fj = j / 50, hj = (j / 10) % 5, wj = j % 10;
        double df = fi - fj, dh = hi - hj, dw = wi - wj;
        double d = sqrt(df * df + dh * dh + dw * dw);
        m = 1.0 - d / sqrt(101.0);
    }
    ssum[i] = m;
    __syncthreads();
    for (int s = 128; s > 0; s >>= 1) {
        if (i < s) ssum[i] += ssum[i + s];
        __syncthreads();
    }
    if (i < NBLK) WBLKbuf[i * NBLK + j] = (float)(m / ssum[0]);
}

// ---------------- fp32 -> bf16 hi/lo split ----------------
__global__ void conv_split(const float* __restrict__ src, __nv_bfloat16* __restrict__ hi,
                           __nv_bfloat16* __restrict__ lo, int n, int ntot) {
    int i = blockIdx.x * 256 + threadIdx.x;
    if (i >= ntot) return;
    float v = (i < n) ? src[i] : 0.f;
    __nv_bfloat16 h = __float2bfloat16(v);
    float rem = v - __bfloat162float(h);
    hi[i] = h;
    lo[i] = __float2bfloat16(rem);
}

// ---------------- tensor-core GEMM: C[m,n] = sum_k A[m,k]*B[n,k] + bias[n] ----------------
// bf16 hi/lo split, 3 mma passes, 128x128 CTA tile, K-chunk 64, double-buffered cp.async.
#define GCH     24          // 1536 / 64
#define TSTRIDE 72          // padded row stride in bf16 elems (144 B) - bank-conflict free
#define TILESZ  (128 * TSTRIDE * 2)        // 18432 B per operand tile
#define BUFSZ   (4 * TILESZ)               // Ahi,Alo,Bhi,Blo  = 73728 B

__global__ __launch_bounds__(256, 1) void gemm_tc(
    const __nv_bfloat16* __restrict__ Ahi, const __nv_bfloat16* __restrict__ Alo,
    const __nv_bfloat16* __restrict__ Bhi, const __nv_bfloat16* __restrict__ Blo,
    const float* __restrict__ bias, float* __restrict__ C, int M)
{
    extern __shared__ __align__(16) char smem[];
    uint32_t sb = smem_u32(smem);
    int tid = threadIdx.x;
    int wid = tid >> 5, lane = tid & 31;
    int m0 = blockIdx.y * 128, n0 = blockIdx.x * 128;

    int wm = (wid & 1) * 64;        // warp m offset within tile
    int wn = (wid >> 1) * 32;       // warp n offset
    int lr = lane >> 2, lc = lane & 3;
    int q = lane >> 3, rr = lane & 7;

    // ldmatrix per-lane base addresses (bytes, within a tile)
    int a_row = (q & 1) * 8 + rr;   // row within m16 tile
    int a_k   = (q >> 1) * 8;       // k offset within k16
    int b_row = (q >> 1) * 8 + rr;  // row within n16 pair
    int b_k   = (q & 1) * 8;
    uint32_t aoffA = ((wm + a_row) * TSTRIDE + a_k) * 2;
    uint32_t aoffB = ((wn + b_row) * TSTRIDE + b_k) * 2;

    float acc[4][4][4];
#pragma unroll
    for (int i = 0; i < 4; i++)
#pragma unroll
        for (int j = 0; j < 4; j++)
#pragma unroll
            for (int r = 0; r < 4; r++) acc[i][j][r] = 0.f;

    // loader: 4096 x 16B segments per chunk; idx = tid + i*256
    auto load_chunk = [&](int c, int buf) {
        size_t kof = (size_t)c * 64;
#pragma unroll
        for (int i = 0; i < 16; i++) {
            int idx = tid + i * 256;
            int t = idx >> 10, row = (idx >> 3) & 127, seg = idx & 7;
            const __nv_bfloat16* g;
            if (t == 0)      g = Ahi + (size_t)(m0 + row) * DIMC + kof + seg * 8;
            else if (t == 1) g = Alo + (size_t)(m0 + row) * DIMC + kof + seg * 8;
            else if (t == 2) g = Bhi + (size_t)(n0 + row) * DIMC + kof + seg * 8;
            else             g = Blo + (size_t)(n0 + row) * DIMC + kof + seg * 8;
            uint32_t dst = sb + buf * BUFSZ + t * TILESZ + row * (TSTRIDE * 2) + seg * 16;
            cp_async16(dst, g);
        }
        asm volatile("cp.async.commit_group;" ::: "memory");
    };

    load_chunk(0, 0);
    for (int c = 0; c < GCH; c++) {
        if (c + 1 < GCH) {
            load_chunk(c + 1, (c + 1) & 1);
            asm volatile("cp.async.wait_group 1;" ::: "memory");
        } else {
            asm volatile("cp.async.wait_group 0;" ::: "memory");
        }
        __syncthreads();
        uint32_t tb = sb + (c & 1) * BUFSZ;
        uint32_t baseAh = tb + aoffA;
        uint32_t baseAl = tb + TILESZ + aoffA;
        uint32_t baseBh = tb + 2 * TILESZ + aoffB;
        uint32_t baseBl = tb + 3 * TILESZ + aoffB;
#pragma unroll
        for (int ks = 0; ks < 4; ks++) {
            uint32_t ko = ks * 32;          // 16 bf16 = 32 bytes
            uint32_t ah[4][4], al[4][4], bh[2][4], bl[2][4];
#pragma unroll
            for (int mt = 0; mt < 4; mt++) {
                ldm_x4(ah[mt], baseAh + mt * (16 * TSTRIDE * 2) + ko);
                ldm_x4(al[mt], baseAl + mt * (16 * TSTRIDE * 2) + ko);
            }
#pragma unroll
            for (int nt2 = 0; nt2 < 2; nt2++) {
                ldm_x4(bh[nt2], baseBh + nt2 * (16 * TSTRIDE * 2) + ko);
                ldm_x4(bl[nt2], baseBl + nt2 * (16 * TSTRIDE * 2) + ko);
            }
#pragma unroll
            for (int mt = 0; mt < 4; mt++) {
#pragma unroll
                for (int nt = 0; nt < 4; nt++) {
                    const uint32_t* ph = &bh[nt >> 1][(nt & 1) * 2];
                    const uint32_t* pl = &bl[nt >> 1][(nt & 1) * 2];
                    mma16816(acc[mt][nt], ah[mt], ph);
                    mma16816(acc[mt][nt], ah[mt], pl);
                    mma16816(acc[mt][nt], al[mt], ph);
                }
            }
        }
        __syncthreads();
    }

    // epilogue
#pragma unroll
    for (int mt = 0; mt < 4; mt++) {
        int m = m0 + wm + mt * 16 + lr;
#pragma unroll
        for (int nt = 0; nt < 4; nt++) {
            int col = n0 + wn + nt * 8 + lc * 2;
            float bx = bias[col], by = bias[col + 1];
            if (m < M) {
                float2 v = make_float2(acc[mt][nt][0] + bx, acc[mt][nt][1] + by);
                *(float2*)(C + (size_t)m * DIMC + col) = v;
            }
            if (m + 8 < M) {
                float2 v = make_float2(acc[mt][nt][2] + bx, acc[mt][nt][3] + by);
                *(float2*)(C + (size_t)(m + 8) * DIMC + col) = v;
            }
        }
    }
}

// ---------------- rmsnorm + relu + eps (in place on Q / K) ----------------
__global__ void rmsnorm_kernel(const float* __restrict__ nqw, const float* __restrict__ nkw) {
    int n = blockIdx.x;
    float* buf = blockIdx.y ? Kbuf : Qbuf;
    const float* w = blockIdx.y ? nkw : nqw;
    int tid = threadIdx.x;
    size_t base = (size_t)n * DIMC;
    float vals[6];
    float ss = 0.f;
#pragma unroll
    for (int t = 0; t < 6; t++) {
        float v = buf[base + tid + t * 256];
        vals[t] = v;
        ss += v * v;
    }
    for (int o = 16; o > 0; o >>= 1) ss += __shfl_xor_sync(0xffffffffu, ss, o);
    __shared__ float red[8];
    __shared__ float stot;
    if ((tid & 31) == 0) red[tid >> 5] = ss;
    __syncthreads();
    if (tid == 0) {
        float t = 0.f;
        for (int i = 0; i < 8; i++) t += red[i];
        stot = t;
    }
    __syncthreads();
    float sc = 1.0f / sqrtf(stot * (1.0f / DIMC) + EPSF);
#pragma unroll
    for (int t = 0; t < 6; t++) {
        int c = tid + t * 256;
        float v = vals[t] * sc * w[c];
        buf[base + c] = fmaxf(v, 0.f) + EPSF;
    }
}

// ---------------- ksum ----------------
__global__ void ksum_kernel() {
    int b = blockIdx.x;
    int hh = b / NBLK, nb = b % NBLK;
    int d = threadIdx.x;
    float acc = 0.f;
    for (int p = 0; p < PBLK; p++) {
        int t = tok_of(nb, p);
        acc += Kbuf[(size_t)t * DIMC + hh * HDIM + d];
    }
    KSUMbuf[b * HDIM + d] = acc;
}

// ---------------- qk ----------------
__global__ void qk_kernel() {
    int b = blockIdx.x;
    int hh = b / NBLK, nb = b % NBLK;
    int tid = threadIdx.x;
    __shared__ float ks[HDIM];
    ks[tid] = KSUMbuf[b * HDIM + tid];
    __syncthreads();
    if (tid < PBLK) {
        int t = tok_of(nb, tid);
        const float* q = Qbuf + (size_t)t * DIMC + hh * HDIM;
        float acc = 0.f;
#pragma unroll 4
        for (int d = 0; d < HDIM; d++) acc += q[d] * ks[d];
        QKbuf[b * PBLK + tid] = acc;
    }
}

// ---------------- RoPE in place on Q and K ----------------
__global__ void rope_kernel(const float* __restrict__ fc, const float* __restrict__ fs) {
    int idx = blockIdx.x * 256 + threadIdx.x;
    if (idx >= NTOK * NHEAD * 64) return;
    int n = idx / (NHEAD * 64);
    int r = idx % (NHEAD * 64);
    int nh = r / 64, c = r % 64;
    float* buf = blockIdx.y ? Kbuf : Qbuf;
    int f = n / 1500, rem = n % 1500;
    int h = rem / 50, w = rem % 50;
    int pos = (c < 22) ? f : ((c < 43) ? h : w);
    float cs = fc[pos * 64 + c];
    float sn = fs[pos * 64 + c];
    size_t base = (size_t)n * DIMC + nh * HDIM + 2 * c;
    float x0 = buf[base], x1 = buf[base + 1];
    buf[base]     = x0 * cs - x1 * sn;
    buf[base + 1] = x0 * sn + x1 * cs;
}

// ---------------- kv ----------------
__global__ __launch_bounds__(256) void kv_kernel() {
    extern __shared__ __align__(16) float sm[];
    float* sK = sm;
    float* sV = sm + PBLK * HDIM;
    int b = blockIdx.x;
    int hh = b / NBLK, nb = b % NBLK;
    int tid = threadIdx.x;
    for (int idx = tid; idx < PBLK * HDIM; idx += 256) {
        int p = idx >> 7, d = idx & 127;
        int t = tok_of(nb, p);
        size_t g = (size_t)t * DIMC + hh * HDIM + d;
        sK[idx] = Kbuf[g];
        sV[idx] = Vbuf[g];
    }
    __syncthreads();
    int tx = tid & 15, ty = tid >> 4;
    int e0 = tx * 8, d0 = ty * 8;
    ull acc[8][4];
#pragma unroll
    for (int i = 0; i < 8; i++)
#pragma unroll
        for (int jj = 0; jj < 4; jj++) acc[i][jj] = 0ULL;
    for (int p = 0; p < PBLK; p++) {
        float4 k1 = *(const float4*)&sK[p * HDIM + d0];
        float4 k2 = *(const float4*)&sK[p * HDIM + d0 + 4];
        ulonglong2 v1 = *(const ulonglong2*)&sV[p * HDIM + e0];
        ulonglong2 v2 = *(const ulonglong2*)&sV[p * HDIM + e0 + 4];
        ull bb0 = v1.x, bb1 = v1.y, bb2 = v2.x, bb3 = v2.y;
        float a[8] = {k1.x, k1.y, k1.z, k1.w, k2.x, k2.y, k2.z, k2.w};
#pragma unroll
        for (int i = 0; i < 8; i++) {
            ull a2 = pack2(a[i], a[i]);
            acc[i][0] = ffma2(a2, bb0, acc[i][0]);
            acc[i][1] = ffma2(a2, bb1, acc[i][1]);
            acc[i][2] = ffma2(a2, bb2, acc[i][2]);
            acc[i][3] = ffma2(a2, bb3, acc[i][3]);
        }
    }
    float* dst = KVbuf + (size_t)b * HDIM * HDIM;
#pragma unroll
    for (int i = 0; i < 8; i++) {
#pragma unroll
        for (int jj = 0; jj < 4; jj++) {
            float v0x, v1x;
            unpack2(acc[i][jj], v0x, v1x);
            int e = e0 + 2 * jj;
            dst[(d0 + i) * HDIM + e]     = v0x;
            dst[(d0 + i) * HDIM + e + 1] = v1x;
        }
    }
}

// ---------------- mix ----------------
__global__ __launch_bounds__(256) void mix_kernel() {
    extern __shared__ __align__(16) float sm[];
    float* Ws = sm;
    float* tB = sm + NBLK * NBLK;
    int hh = blockIdx.y, xt = blockIdx.x;
    int tid = threadIdx.x;
    for (int idx = tid; idx < NBLK * NBLK; idx += 256) Ws[idx] = WBLKbuf[idx];
    const float* src = KVbuf + (size_t)hh * NBLK * HDIM * HDIM + xt * 128;
    for (int idx = tid; idx < NBLK * 128; idx += 256) {
        int i = idx >> 7, c = idx & 127;
        tB[idx] = src[(size_t)i * HDIM * HDIM + c];
    }
    __syncthreads();
    int tx = tid & 15, ty = tid >> 4;
    ull acc[10][4];
#pragma unroll
    for (int oo = 0; oo < 10; oo++)
#pragma unroll
        for (int jj = 0; jj < 4; jj++) acc[oo][jj] = 0ULL;
    for (int i = 0; i < NBLK; i++) {
        ulonglong2 b1 = *(const ulonglong2*)&tB[i * 128 + tx * 8];
        ulonglong2 b2 = *(const ulonglong2*)&tB[i * 128 + tx * 8 + 4];
        ull bb0 = b1.x, bb1 = b1.y, bb2 = b2.x, bb3 = b2.y;
#pragma unroll
        for (int oo = 0; oo < 10; oo++) {
            int o = ty + 16 * oo;
            if (o < NBLK) {
                float w = Ws[o * NBLK + i];
                ull w2 = pack2(w, w);
                acc[oo][0] = ffma2(w2, bb0, acc[oo][0]);
                acc[oo][1] = ffma2(w2, bb1, acc[oo][1]);
                acc[oo][2] = ffma2(w2, bb2, acc[oo][2]);
                acc[oo][3] = ffma2(w2, bb3, acc[oo][3]);
            }
        }
    }
#pragma unroll
    for (int oo = 0; oo < 10; oo++) {
        int o = ty + 16 * oo;
        if (o < NBLK) {
            float* dst = KVMIXbuf + ((size_t)hh * NBLK + o) * HDIM * HDIM + xt * 128 + tx * 8;
#pragma unroll
            for (int jj = 0; jj < 4; jj++) {
                float v0x, v1x;
                unpack2(acc[oo][jj], v0x, v1x);
                dst[2 * jj]     = v0x;
                dst[2 * jj + 1] = v1x;
            }
        }
    }
}

// ---------------- norm ----------------
__global__ void norm_kernel() {
    int b = blockIdx.x;
    int hh = b / NBLK, o = b % NBLK;
    int p = threadIdx.x;
    if (p >= PBLK) return;
    float acc = EPSF;
    for (int i = 0; i < NBLK; i++)
        acc += WBLKbuf[o * NBLK + i] * QKbuf[(hh * NBLK + i) * PBLK + p];
    NORMbuf[b * PBLK + p] = acc;
}

// ---------------- out ----------------
__global__ __launch_bounds__(256) void out_kernel() {
    extern __shared__ __align__(16) float sm[];
    float* sQt = sm;
    float* sKV = sm + HDIM * PBLK;
    int b = blockIdx.x;
    int hh = b / NBLK, nb = b % NBLK;
    int tid = threadIdx.x;
    for (int idx = tid; idx < PBLK * HDIM; idx += 256) {
        int p = idx >> 7, d = idx & 127;
        int t = tok_of(nb, p);
        sQt[d * PBLK + p] = Qbuf[(size_t)t * DIMC + hh * HDIM + d];
    }
    const float* kvsrc = KVMIXbuf + (size_t)b * HDIM * HDIM;
    for (int idx = tid; idx < HDIM * HDIM; idx += 256) sKV[idx] = kvsrc[idx];
    __syncthreads();
    int tx = tid & 15, ty = tid >> 4;
    if (ty >= 15) return;
    int e0 = tx * 8, p0 = ty * 8;
    ull acc[8][4];
#pragma unroll
    for (int i = 0; i < 8; i++)
#pragma unroll
        for (int jj = 0; jj < 4; jj++) acc[i][jj] = 0ULL;
    for (int d = 0; d < HDIM; d++) {
        float4 q1 = *(const float4*)&sQt[d * PBLK + p0];
        float4 q2 = *(const float4*)&sQt[d * PBLK + p0 + 4];
        ulonglong2 k1 = *(const ulonglong2*)&sKV[d * HDIM + e0];
        ulonglong2 k2 = *(const ulonglong2*)&sKV[d * HDIM + e0 + 4];
        ull bb0 = k1.x, bb1 = k1.y, bb2 = k2.x, bb3 = k2.y;
        float a[8] = {q1.x, q1.y, q1.z, q1.w, q2.x, q2.y, q2.z, q2.w};
#pragma unroll
        for (int i = 0; i < 8; i++) {
            ull a2 = pack2(a[i], a[i]);
            acc[i][0] = ffma2(a2, bb0, acc[i][0]);
            acc[i][1] = ffma2(a2, bb1, acc[i][1]);
            acc[i][2] = ffma2(a2, bb2, acc[i][2]);
            acc[i][3] = ffma2(a2, bb3, acc[i][3]);
        }
    }
#pragma unroll
    for (int i = 0; i < 8; i++) {
        int p = p0 + i;
        float inv = 1.0f / NORMbuf[b * PBLK + p];
        int t = tok_of(nb, p);
        float* dst = AObuf + (size_t)t * DIMC + hh * HDIM + e0;
#pragma unroll
        for (int jj = 0; jj < 4; jj++) {
            float v0x, v1x;
            unpack2(acc[i][jj], v0x, v1x);
            dst[2 * jj]     = v0x * inv;
            dst[2 * jj + 1] = v1x * inv;
        }
    }
}

// ---------------- launch ----------------
extern "C" void kernel_launch(void* const* d_in, const int* in_sizes, int n_in,
                              void* d_out, int out_size) {
    const float* x   = (const float*)d_in[0];
    const float* fc  = (const float*)d_in[3];
    const float* fs  = (const float*)d_in[4];
    const float* wq  = (const float*)d_in[5];
    const float* bq  = (const float*)d_in[6];
    const float* wk  = (const float*)d_in[7];
    const float* bk  = (const float*)d_in[8];
    const float* wv  = (const float*)d_in[9];
    const float* bv  = (const float*)d_in[10];
    const float* wo  = (const float*)d_in[11];
    const float* bo  = (const float*)d_in[12];
    const float* nqw = (const float*)d_in[13];
    const float* nkw = (const float*)d_in[14];
    float* out = (float*)d_out;

    void *pq, *pk, *pv, *pao;
    cudaGetSymbolAddress(&pq, Qbuf);
    cudaGetSymbolAddress(&pk, Kbuf);
    cudaGetSymbolAddress(&pv, Vbuf);
    cudaGetSymbolAddress(&pao, AObuf);
    void *pxh, *pxl, *paoh, *paol, *pwh, *pwl;
    cudaGetSymbolAddress(&pxh, Xhi);
    cudaGetSymbolAddress(&pxl, Xlo);
    cudaGetSymbolAddress(&paoh, AOhi);
    cudaGetSymbolAddress(&paol, AOlo);
    cudaGetSymbolAddress(&pwh, Whi4);
    cudaGetSymbolAddress(&pwl, Wlo4);
    __nv_bfloat16* xh = (__nv_bfloat16*)pxh;
    __nv_bfloat16* xl = (__nv_bfloat16*)pxl;
    __nv_bfloat16* aoh = (__nv_bfloat16*)paoh;
    __nv_bfloat16* aol = (__nv_bfloat16*)paol;
    __nv_bfloat16* wh = (__nv_bfloat16*)pwh;
    __nv_bfloat16* wl = (__nv_bfloat16*)pwl;

    const int GEMM_SMEM = 2 * BUFSZ;                       // 147456
    const int KV_SMEM   = (PBLK * HDIM * 2) * 4;
    const int MIX_SMEM  = (NBLK * NBLK + NBLK * 128) * 4;
    const int OUT_SMEM  = (HDIM * PBLK + HDIM * HDIM) * 4;
    cudaFuncSetAttribute(gemm_tc,   cudaFuncAttributeMaxDynamicSharedMemorySize, GEMM_SMEM);
    cudaFuncSetAttribute(kv_kernel, cudaFuncAttributeMaxDynamicSharedMemorySize, KV_SMEM);
    cudaFuncSetAttribute(mix_kernel, cudaFuncAttributeMaxDynamicSharedMemorySize, MIX_SMEM);
    cudaFuncSetAttribute(out_kernel, cudaFuncAttributeMaxDynamicSharedMemorySize, OUT_SMEM);

    wblk_kernel<<<NBLK, 256>>>();

    // convert inputs to bf16 hi/lo
    const int WN = DIMC * DIMC;
    conv_split<<<(MPAD * DIMC) / 256, 256>>>(x, xh, xl, NTOK * DIMC, MPAD * DIMC);
    conv_split<<<WN / 256, 256>>>(wq, wh + 0 * (size_t)WN, wl + 0 * (size_t)WN, WN, WN);
    conv_split<<<WN / 256, 256>>>(wk, wh + 1 * (size_t)WN, wl + 1 * (size_t)WN, WN, WN);
    conv_split<<<WN / 256, 256>>>(wv, wh + 2 * (size_t)WN, wl + 2 * (size_t)WN, WN, WN);
    conv_split<<<WN / 256, 256>>>(wo, wh + 3 * (size_t)WN, wl + 3 * (size_t)WN, WN, WN);

    dim3 gg(DIMC / 128, MPAD / 128);   // (12, 141)
    gemm_tc<<<gg, 256, GEMM_SMEM>>>(xh, xl, wh + 0 * (size_t)WN, wl + 0 * (size_t)WN, bq, (float*)pq, NTOK);
    gemm_tc<<<gg, 256, GEMM_SMEM>>>(xh, xl, wh + 1 * (size_t)WN, wl + 1 * (size_t)WN, bk, (float*)pk, NTOK);
    gemm_tc<<<gg, 256, GEMM_SMEM>>>(xh, xl, wh + 2 * (size_t)WN, wl + 2 * (size_t)WN, bv, (float*)pv, NTOK);

    rmsnorm_kernel<<<dim3(NTOK, 2), 256>>>(nqw, nkw);

    ksum_kernel<<<NHEAD * NBLK, HDIM>>>();
    qk_kernel<<<NHEAD * NBLK, HDIM>>>();

    rope_kernel<<<dim3((NTOK * NHEAD * 64 + 255) / 256, 2), 256>>>(fc, fs);

    kv_kernel<<<NHEAD * NBLK, 256, KV_SMEM>>>();
    mix_kernel<<<dim3(128, NHEAD), 256, MIX_SMEM>>>();
    norm_kernel<<<NHEAD * NBLK, 128>>>();
    out_kernel<<<NHEAD * NBLK, 256, OUT_SMEM>>>();

    conv_split<<<(MPAD * DIMC) / 256, 256>>>((const float*)pao, aoh, aol, NTOK * DIMC, MPAD * DIMC);
    gemm_tc<<<gg, 256, GEMM_SMEM>>>(aoh, aol, wh + 3 * (size_t)WN, wl + 3 * (size_t)WN, bo, out, NTOK);
}

// round 5
// speedup vs baseline: 2.5351x; 1.1520x over previous
#include <cuda_runtime.h>
#include <cuda_bf16.h>
#include <cstdint>
#include <cstdio>

// ---------------- problem dims (fixed) ----------------
#define NTOK   18000      // F*H*W = 12*30*50
#define MPAD   18048      // padded to multiple of 128
#define DIMC   1536
#define NHEAD  12
#define HDIM   128
#define NBLK   150        // FB*HB*WB = 3*5*10
#define PBLK   120        // P1*P2*P3 = 4*6*5
#define EPSF   1e-6f

typedef unsigned long long ull;

// ---------------- f32x2 helpers ----------------
__device__ __forceinline__ ull ffma2(ull a, ull b, ull c) {
    ull d;
    asm("fma.rn.f32x2 %0, %1, %2, %3;" : "=l"(d) : "l"(a), "l"(b), "l"(c));
    return d;
}
__device__ __forceinline__ ull pack2(float x, float y) {
    ull r;
    asm("mov.b64 %0, {%1, %2};" : "=l"(r) : "f"(x), "f"(y));
    return r;
}
__device__ __forceinline__ void unpack2(ull v, float& x, float& y) {
    asm("mov.b64 {%0, %1}, %2;" : "=f"(x), "=f"(y) : "l"(v));
}

// ---------------- mma / ldmatrix helpers ----------------
__device__ __forceinline__ uint32_t smem_u32(const void* p) {
    uint32_t a;
    asm("{ .reg .u64 t; cvta.to.shared.u64 t, %1; cvt.u32.u64 %0, t; }" : "=r"(a) : "l"(p));
    return a;
}
__device__ __forceinline__ void cp_async16(uint32_t dst, const void* src) {
    asm volatile("cp.async.cg.shared.global [%0], [%1], 16;" :: "r"(dst), "l"(src) : "memory");
}
__device__ __forceinline__ void ldm_x4(uint32_t* r, uint32_t addr) {
    asm volatile("ldmatrix.sync.aligned.m8n8.x4.shared.b16 {%0,%1,%2,%3}, [%4];"
                 : "=r"(r[0]), "=r"(r[1]), "=r"(r[2]), "=r"(r[3]) : "r"(addr));
}
__device__ __forceinline__ void mma16816(float* c, const uint32_t* a, const uint32_t* b) {
    asm volatile("mma.sync.aligned.m16n8k16.row.col.f32.bf16.bf16.f32 "
                 "{%0,%1,%2,%3}, {%4,%5,%6,%7}, {%8,%9}, {%0,%1,%2,%3};"
                 : "+f"(c[0]), "+f"(c[1]), "+f"(c[2]), "+f"(c[3])
                 : "r"(a[0]), "r"(a[1]), "r"(a[2]), "r"(a[3]), "r"(b[0]), "r"(b[1]));
}

// ---------------- scratch ----------------
__device__ float Qbuf[NTOK * DIMC];      // pre-rope normed q
__device__ float Kbuf[NTOK * DIMC];      // pre-rope normed k
__device__ float Vbuf[NTOK * DIMC];
__device__ float QRbuf[NTOK * DIMC];     // roped q
__device__ float KRbuf[NTOK * DIMC];     // roped k
__device__ float KVbuf[NHEAD * NBLK * HDIM * HDIM];
__device__ float KVMIXbuf[NHEAD * NBLK * HDIM * HDIM];
__device__ float QKbuf[NHEAD * NBLK * PBLK];
__device__ float NORMbuf[NHEAD * NBLK * PBLK];
__device__ float WBLKbuf[NBLK * NBLK];

__device__ __nv_bfloat16 Xhi[MPAD * DIMC];
__device__ __nv_bfloat16 Xlo[MPAD * DIMC];
__device__ __nv_bfloat16 AOhi[MPAD * DIMC];   // zero-init; pad rows never written
__device__ __nv_bfloat16 AOlo[MPAD * DIMC];
__device__ __nv_bfloat16 Whi4[4][DIMC * DIMC];
__device__ __nv_bfloat16 Wlo4[4][DIMC * DIMC];

__device__ __forceinline__ int tok_of(int nb, int p) {
    int fb = nb / 50, hb = (nb / 10) % 5, wb = nb % 10;
    int p1 = p / 30, p2 = (p / 5) % 6, p3 = p % 5;
    int f = fb * 4 + p1, h = hb * 6 + p2, w = wb * 5 + p3;
    return (f * 30 + h) * 50 + w;
}

// ---------------- W_BLK ----------------
__global__ void wblk_kernel() {
    int j = blockIdx.x;
    int i = threadIdx.x;
    __shared__ double ssum[256];
    double m = 0.0;
    if (i < NBLK) {
        int fi = i / 50, hi = (i / 10) % 5, wi = i % 10;
        int fj = j / 50, hj = (j / 10) % 5, wj = j % 10;
        double df = fi - fj, dh = hi - hj, dw = wi - wj;
        double d = sqrt(df * df + dh * dh + dw * dw);
        m = 1.0 - d / sqrt(101.0);
    }
    ssum[i] = m;
    __syncthreads();
    for (int s = 128; s > 0; s >>= 1) {
        if (i < s) ssum[i] += ssum[i + s];
        __syncthreads();
    }
    if (i < NBLK) WBLKbuf[i * NBLK + j] = (float)(m / ssum[0]);
}

// ---------------- fp32 -> bf16 hi/lo split ----------------
__global__ void conv_split(const float* __restrict__ src, __nv_bfloat16* __restrict__ hi,
                           __nv_bfloat16* __restrict__ lo, int n, int ntot) {
    int i = blockIdx.x * 256 + threadIdx.x;
    if (i >= ntot) return;
    float v = (i < n) ? src[i] : 0.f;
    __nv_bfloat16 h = __float2bfloat16(v);
    hi[i] = h;
    lo[i] = __float2bfloat16(v - __bfloat162float(h));
}

__global__ void conv_w4(const float* __restrict__ w0, const float* __restrict__ w1,
                        const float* __restrict__ w2, const float* __restrict__ w3) {
    int y = blockIdx.y;
    const float* src = (y == 0) ? w0 : (y == 1) ? w1 : (y == 2) ? w2 : w3;
    int i = blockIdx.x * 256 + threadIdx.x;
    float v = src[i];
    __nv_bfloat16 h = __float2bfloat16(v);
    Whi4[y][i] = h;
    Wlo4[y][i] = __float2bfloat16(v - __bfloat162float(h));
}

// ---------------- pipelined tensor-core GEMM core ----------------
// 128x128 tile, K-chunk 32 (64B rows), XOR-swizzled SMEM, 3-stage cp.async ring.
// swizzled addr(row, seg) = row*64 + ((seg ^ ((row>>1)&3)) * 16); always 16B aligned.
#define KC      32
#define NCHUNK  (DIMC / KC)              // 48
#define TILEB   (128 * 64)               // 8192 B per operand tile
#define STAGEB  (4 * TILEB)              // 32768 B
#define GEMM_SMEM (3 * STAGEB)           // 98304 B -> 2 CTAs/SM

__device__ __forceinline__ void gemm_core(
    const __nv_bfloat16* __restrict__ Ahi, const __nv_bfloat16* __restrict__ Alo,
    const __nv_bfloat16* __restrict__ Bhi, const __nv_bfloat16* __restrict__ Blo,
    const float* __restrict__ bias, float* __restrict__ C, int M,
    int m0, int n0, uint32_t sb)
{
    int tid = threadIdx.x;
    int wid = tid >> 5, lane = tid & 31;
    int wm = (wid & 1) * 64;
    int wn = (wid >> 1) * 32;
    int lr = lane >> 2, lc = lane & 3;
    int q = lane >> 3, rr = lane & 7;

    int a_row = (q & 1) * 8 + rr;       // 0..15
    int a_seg0 = q >> 1;                // 0 or 1
    int b_row = (q >> 1) * 8 + rr;
    int b_seg0 = q & 1;
    // swizzle key: bits 1-2 of row (invariant under +8/+16/+64 offsets)
    int swA = (a_row >> 1) & 3;
    int swB = (b_row >> 1) & 3;
    uint32_t rowbA = (uint32_t)(wm + a_row) * 64;
    uint32_t rowbB = (uint32_t)(wn + b_row) * 64;

    float acc[4][4][4];
#pragma unroll
    for (int i = 0; i < 4; i++)
#pragma unroll
        for (int j = 0; j < 4; j++)
#pragma unroll
            for (int r = 0; r < 4; r++) acc[i][j][r] = 0.f;

    // loader: 2048 x 16B segs per chunk -> 8 per thread
    auto load_chunk = [&](int c, int st) {
        size_t kof = (size_t)c * KC;
#pragma unroll
        for (int i = 0; i < 8; i++) {
            int idx = tid + i * 256;
            int t = idx >> 9, row = (idx >> 2) & 127, seg = idx & 3;
            const __nv_bfloat16* g;
            if (t == 0)      g = Ahi + (size_t)(m0 + row) * DIMC + kof + seg * 8;
            else if (t == 1) g = Alo + (size_t)(m0 + row) * DIMC + kof + seg * 8;
            else if (t == 2) g = Bhi + (size_t)(n0 + row) * DIMC + kof + seg * 8;
            else             g = Blo + (size_t)(n0 + row) * DIMC + kof + seg * 8;
            uint32_t dst = sb + st * STAGEB + t * TILEB + row * 64
                         + ((seg ^ ((row >> 1) & 3)) * 16);
            cp_async16(dst, g);
        }
        asm volatile("cp.async.commit_group;" ::: "memory");
    };

    load_chunk(0, 0);
    load_chunk(1, 1);
    int st_load = 2, st_cmp = 0;
    for (int c = 0; c < NCHUNK; c++) {
        if (c == NCHUNK - 1)
            asm volatile("cp.async.wait_group 0;" ::: "memory");
        else
            asm volatile("cp.async.wait_group 1;" ::: "memory");
        __syncthreads();
        if (c + 2 < NCHUNK) {
            load_chunk(c + 2, st_load);
            if (++st_load == 3) st_load = 0;
        }
        uint32_t tb = sb + st_cmp * STAGEB;
        if (++st_cmp == 3) st_cmp = 0;
        uint32_t bAh = tb + rowbA;
        uint32_t bAl = tb + TILEB + rowbA;
        uint32_t bBh = tb + 2 * TILEB + rowbB;
        uint32_t bBl = tb + 3 * TILEB + rowbB;
#pragma unroll
        for (int ks = 0; ks < 2; ks++) {
            uint32_t offA = (uint32_t)(((a_seg0 + ks * 2) ^ swA) * 16);
            uint32_t offB = (uint32_t)(((b_seg0 + ks * 2) ^ swB) * 16);
            uint32_t ah[4][4], bh[2][4], bl[2][4];
#pragma unroll
            for (int mt = 0; mt < 4; mt++)
                ldm_x4(ah[mt], bAh + mt * 1024 + offA);
#pragma unroll
            for (int nt2 = 0; nt2 < 2; nt2++) {
                ldm_x4(bh[nt2], bBh + nt2 * 1024 + offB);
                ldm_x4(bl[nt2], bBl + nt2 * 1024 + offB);
            }
#pragma unroll
            for (int mt = 0; mt < 4; mt++)
#pragma unroll
                for (int nt = 0; nt < 4; nt++) {
                    const uint32_t* ph = &bh[nt >> 1][(nt & 1) * 2];
                    const uint32_t* pl = &bl[nt >> 1][(nt & 1) * 2];
                    mma16816(acc[mt][nt], ah[mt], ph);
                    mma16816(acc[mt][nt], ah[mt], pl);
                }
            uint32_t al[4][4];
#pragma unroll
            for (int mt = 0; mt < 4; mt++)
                ldm_x4(al[mt], bAl + mt * 1024 + offA);
#pragma unroll
            for (int mt = 0; mt < 4; mt++)
#pragma unroll
                for (int nt = 0; nt < 4; nt++)
                    mma16816(acc[mt][nt], al[mt], &bh[nt >> 1][(nt & 1) * 2]);
        }
    }

#pragma unroll
    for (int mt = 0; mt < 4; mt++) {
        int m = m0 + wm + mt * 16 + lr;
#pragma unroll
        for (int nt = 0; nt < 4; nt++) {
            int col = n0 + wn + nt * 8 + lc * 2;
            float bx = bias[col], by = bias[col + 1];
            if (m < M) {
                float2 v = make_float2(acc[mt][nt][0] + bx, acc[mt][nt][1] + by);
                *(float2*)(C + (size_t)m * DIMC + col) = v;
            }
            if (m + 8 < M) {
                float2 v = make_float2(acc[mt][nt][2] + bx, acc[mt][nt][3] + by);
                *(float2*)(C + (size_t)(m + 8) * DIMC + col) = v;
            }
        }
    }
}

__global__ __launch_bounds__(256, 2) void gemm_qkv(
    const float* __restrict__ bq, const float* __restrict__ bk, const float* __restrict__ bv)
{
    extern __shared__ __align__(16) char smem[];
    uint32_t sb = smem_u32(smem);
    int z = blockIdx.z;
    const __nv_bfloat16* Bh = Whi4[z];
    const __nv_bfloat16* Bl = Wlo4[z];
    const float* bias = (z == 0) ? bq : (z == 1) ? bk : bv;
    float* C = (z == 0) ? Qbuf : (z == 1) ? Kbuf : Vbuf;
    gemm_core(Xhi, Xlo, Bh, Bl, bias, C, NTOK, blockIdx.y * 128, blockIdx.x * 128, sb);
}

__global__ __launch_bounds__(256, 2) void gemm_out(const float* __restrict__ bo, float* __restrict__ out)
{
    extern __shared__ __align__(16) char smem[];
    uint32_t sb = smem_u32(smem);
    gemm_core(AOhi, AOlo, Whi4[3], Wlo4[3], bo, out, NTOK, blockIdx.y * 128, blockIdx.x * 128, sb);
}

// ---------------- fused rmsnorm + relu + eps + RoPE ----------------
__global__ void rmsnorm_rope_kernel(const float* __restrict__ nqw, const float* __restrict__ nkw,
                                    const float* __restrict__ fc, const float* __restrict__ fs) {
    int n = blockIdx.x;
    bool isK = blockIdx.y;
    float* buf = isK ? Kbuf : Qbuf;
    float* rbuf = isK ? KRbuf : QRbuf;
    const float* w = isK ? nkw : nqw;
    int tid = threadIdx.x;
    size_t base = (size_t)n * DIMC;
    float2* b2 = (float2*)(buf + base);
    float2* r2 = (float2*)(rbuf + base);
    const float2* w2 = (const float2*)w;

    int f = n / 1500, rem = n % 1500;
    int hh = rem / 50, ww = rem % 50;

    float2 v[3];
    float ss = 0.f;
#pragma unroll
    for (int t = 0; t < 3; t++) {
        v[t] = b2[tid + t * 256];
        ss += v[t].x * v[t].x + v[t].y * v[t].y;
    }
    for (int o = 16; o > 0; o >>= 1) ss += __shfl_xor_sync(0xffffffffu, ss, o);
    __shared__ float red[8];
    __shared__ float stot;
    if ((tid & 31) == 0) red[tid >> 5] = ss;
    __syncthreads();
    if (tid == 0) {
        float t = 0.f;
        for (int i = 0; i < 8; i++) t += red[i];
        stot = t;
    }
    __syncthreads();
    float sc = 1.0f / sqrtf(stot * (1.0f / DIMC) + EPSF);
#pragma unroll
    for (int t = 0; t < 3; t++) {
        int idx = tid + t * 256;
        float2 wv = w2[idx];
        float x0 = fmaxf(v[t].x * sc * wv.x, 0.f) + EPSF;
        float x1 = fmaxf(v[t].y * sc * wv.y, 0.f) + EPSF;
        b2[idx] = make_float2(x0, x1);
        int c = idx & 63;
        int pos = (c < 22) ? f : ((c < 43) ? hh : ww);
        float cs = fc[pos * 64 + c];
        float sn = fs[pos * 64 + c];
        r2[idx] = make_float2(x0 * cs - x1 * sn, x0 * sn + x1 * cs);
    }
}

// ---------------- fused ksum + qk ----------------
__global__ void qk_kernel() {
    int b = blockIdx.x;
    int hh = b / NBLK, nb = b % NBLK;
    int tid = threadIdx.x;
    __shared__ float ks[HDIM];
    float acc = 0.f;
    for (int p = 0; p < PBLK; p++) {
        int t = tok_of(nb, p);
        acc += Kbuf[(size_t)t * DIMC + hh * HDIM + tid];
    }
    ks[tid] = acc;
    __syncthreads();
    if (tid < PBLK) {
        int t = tok_of(nb, tid);
        const float* qp = Qbuf + (size_t)t * DIMC + hh * HDIM;
        float a = 0.f;
#pragma unroll 4
        for (int d = 0; d < HDIM; d++) a += qp[d] * ks[d];
        QKbuf[b * PBLK + tid] = a;
    }
}

// ---------------- kv ----------------
__global__ __launch_bounds__(256) void kv_kernel() {
    extern __shared__ __align__(16) float sm[];
    float* sK = sm;
    float* sV = sm + PBLK * HDIM;
    int b = blockIdx.x;
    int hh = b / NBLK, nb = b % NBLK;
    int tid = threadIdx.x;
    for (int idx = tid; idx < PBLK * HDIM; idx += 256) {
        int p = idx >> 7, d = idx & 127;
        int t = tok_of(nb, p);
        size_t g = (size_t)t * DIMC + hh * HDIM + d;
        sK[idx] = KRbuf[g];
        sV[idx] = Vbuf[g];
    }
    __syncthreads();
    int tx = tid & 15, ty = tid >> 4;
    int e0 = tx * 8, d0 = ty * 8;
    ull acc[8][4];
#pragma unroll
    for (int i = 0; i < 8; i++)
#pragma unroll
        for (int jj = 0; jj < 4; jj++) acc[i][jj] = 0ULL;
    for (int p = 0; p < PBLK; p++) {
        float4 k1 = *(const float4*)&sK[p * HDIM + d0];
        float4 k2 = *(const float4*)&sK[p * HDIM + d0 + 4];
        ulonglong2 v1 = *(const ulonglong2*)&sV[p * HDIM + e0];
        ulonglong2 v2 = *(const ulonglong2*)&sV[p * HDIM + e0 + 4];
        ull bb0 = v1.x, bb1 = v1.y, bb2 = v2.x, bb3 = v2.y;
        float a[8] = {k1.x, k1.y, k1.z, k1.w, k2.x, k2.y, k2.z, k2.w};
#pragma unroll
        for (int i = 0; i < 8; i++) {
            ull a2 = pack2(a[i], a[i]);
            acc[i][0] = ffma2(a2, bb0, acc[i][0]);
            acc[i][1] = ffma2(a2, bb1, acc[i][1]);
            acc[i][2] = ffma2(a2, bb2, acc[i][2]);
            acc[i][3] = ffma2(a2, bb3, acc[i][3]);
        }
    }
    float* dst = KVbuf + (size_t)b * HDIM * HDIM;
#pragma unroll
    for (int i = 0; i < 8; i++) {
#pragma unroll
        for (int jj = 0; jj < 4; jj++) {
            float v0x, v1x;
            unpack2(acc[i][jj], v0x, v1x);
            int e = e0 + 2 * jj;
            dst[(d0 + i) * HDIM + e]     = v0x;
            dst[(d0 + i) * HDIM + e + 1] = v1x;
        }
    }
}

// ---------------- mix ----------------
__global__ __launch_bounds__(256) void mix_kernel() {
    extern __shared__ __align__(16) float sm[];
    float* Ws = sm;
    float* tB = sm + NBLK * NBLK;
    int hh = blockIdx.y, xt = blockIdx.x;
    int tid = threadIdx.x;
    for (int idx = tid; idx < NBLK * NBLK; idx += 256) Ws[idx] = WBLKbuf[idx];
    const float* src = KVbuf + (size_t)hh * NBLK * HDIM * HDIM + xt * 128;
    for (int idx = tid; idx < NBLK * 128; idx += 256) {
        int i = idx >> 7, c = idx & 127;
        tB[idx] = src[(size_t)i * HDIM * HDIM + c];
    }
    __syncthreads();
    int tx = tid & 15, ty = tid >> 4;
    ull acc[10][4];
#pragma unroll
    for (int oo = 0; oo < 10; oo++)
#pragma unroll
        for (int jj = 0; jj < 4; jj++) acc[oo][jj] = 0ULL;
    for (int i = 0; i < NBLK; i++) {
        ulonglong2 b1 = *(const ulonglong2*)&tB[i * 128 + tx * 8];
        ulonglong2 b2 = *(const ulonglong2*)&tB[i * 128 + tx * 8 + 4];
        ull bb0 = b1.x, bb1 = b1.y, bb2 = b2.x, bb3 = b2.y;
#pragma unroll
        for (int oo = 0; oo < 10; oo++) {
            int o = ty + 16 * oo;
            if (o < NBLK) {
                float w = Ws[o * NBLK + i];
                ull w2 = pack2(w, w);
                acc[oo][0] = ffma2(w2, bb0, acc[oo][0]);
                acc[oo][1] = ffma2(w2, bb1, acc[oo][1]);
                acc[oo][2] = ffma2(w2, bb2, acc[oo][2]);
                acc[oo][3] = ffma2(w2, bb3, acc[oo][3]);
            }
        }
    }
#pragma unroll
    for (int oo = 0; oo < 10; oo++) {
        int o = ty + 16 * oo;
        if (o < NBLK) {
            float* dst = KVMIXbuf + ((size_t)hh * NBLK + o) * HDIM * HDIM + xt * 128 + tx * 8;
#pragma unroll
            for (int jj = 0; jj < 4; jj++) {
                float v0x, v1x;
                unpack2(acc[oo][jj], v0x, v1x);
                dst[2 * jj]     = v0x;
                dst[2 * jj + 1] = v1x;
            }
        }
    }
}

// ---------------- norm ----------------
__global__ void norm_kernel() {
    int b = blockIdx.x;
    int hh = b / NBLK, o = b % NBLK;
    int p = threadIdx.x;
    if (p >= PBLK) return;
    float acc = EPSF;
    for (int i = 0; i < NBLK; i++)
        acc += WBLKbuf[o * NBLK + i] * QKbuf[(hh * NBLK + i) * PBLK + p];
    NORMbuf[b * PBLK + p] = acc;
}

// ---------------- out: writes AOhi/AOlo bf16 split directly ----------------
__global__ __launch_bounds__(256) void out_kernel() {
    extern __shared__ __align__(16) float sm[];
    float* sQt = sm;                  // [128][120] d-major
    float* sKV = sm + HDIM * PBLK;    // [128][128]
    int b = blockIdx.x;
    int hh = b / NBLK, nb = b % NBLK;
    int tid = threadIdx.x;
    for (int idx = tid; idx < PBLK * HDIM; idx += 256) {
        int p = idx >> 7, d = idx & 127;
        int t = tok_of(nb, p);
        sQt[d * PBLK + p] = QRbuf[(size_t)t * DIMC + hh * HDIM + d];
    }
    const float* kvsrc = KVMIXbuf + (size_t)b * HDIM * HDIM;
    for (int idx = tid; idx < HDIM * HDIM; idx += 256) sKV[idx] = kvsrc[idx];
    __syncthreads();
    int tx = tid & 15, ty = tid >> 4;
    if (ty >= 15) return;
    int e0 = tx * 8, p0 = ty * 8;
    ull acc[8][4];
#pragma unroll
    for (int i = 0; i < 8; i++)
#pragma unroll
        for (int jj = 0; jj < 4; jj++) acc[i][jj] = 0ULL;
    for (int d = 0; d < HDIM; d++) {
        float4 q1 = *(const float4*)&sQt[d * PBLK + p0];
        float4 q2 = *(const float4*)&sQt[d * PBLK + p0 + 4];
        ulonglong2 k1 = *(const ulonglong2*)&sKV[d * HDIM + e0];
        ulonglong2 k2 = *(const ulonglong2*)&sKV[d * HDIM + e0 + 4];
        ull bb0 = k1.x, bb1 = k1.y, bb2 = k2.x, bb3 = k2.y;
        float a[8] = {q1.x, q1.y, q1.z, q1.w, q2.x, q2.y, q2.z, q2.w};
#pragma unroll
        for (int i = 0; i < 8; i++) {
            ull a2 = pack2(a[i], a[i]);
            acc[i][0] = ffma2(a2, bb0, acc[i][0]);
            acc[i][1] = ffma2(a2, bb1, acc[i][1]);
            acc[i][2] = ffma2(a2, bb2, acc[i][2]);
            acc[i][3] = ffma2(a2, bb3, acc[i][3]);
        }
    }
#pragma unroll
    for (int i = 0; i < 8; i++) {
        int p = p0 + i;
        float inv = 1.0f / NORMbuf[b * PBLK + p];
        int t = tok_of(nb, p);
        size_t gbase = (size_t)t * DIMC + hh * HDIM + e0;
        unsigned short hw[8], lw[8];
#pragma unroll
        for (int jj = 0; jj < 4; jj++) {
            float v0x, v1x;
            unpack2(acc[i][jj], v0x, v1x);
            v0x *= inv; v1x *= inv;
            __nv_bfloat16 h0 = __float2bfloat16(v0x);
            __nv_bfloat16 h1 = __float2bfloat16(v1x);
            hw[2 * jj]     = __bfloat16_as_ushort(h0);
            hw[2 * jj + 1] = __bfloat16_as_ushort(h1);
            lw[2 * jj]     = __bfloat16_as_ushort(__float2bfloat16(v0x - __bfloat162float(h0)));
            lw[2 * jj + 1] = __bfloat16_as_ushort(__float2bfloat16(v1x - __bfloat162float(h1)));
        }
        *(uint4*)(AOhi + gbase) = *(uint4*)hw;
        *(uint4*)(AOlo + gbase) = *(uint4*)lw;
    }
}

// ---------------- launch ----------------
extern "C" void kernel_launch(void* const* d_in, const int* in_sizes, int n_in,
                              void* d_out, int out_size) {
    const float* x   = (const float*)d_in[0];
    const float* fc  = (const float*)d_in[3];
    const float* fs  = (const float*)d_in[4];
    const float* wq  = (const float*)d_in[5];
    const float* bq  = (const float*)d_in[6];
    const float* wk  = (const float*)d_in[7];
    const float* bk  = (const float*)d_in[8];
    const float* wv  = (const float*)d_in[9];
    const float* bv  = (const float*)d_in[10];
    const float* wo  = (const float*)d_in[11];
    const float* bo  = (const float*)d_in[12];
    const float* nqw = (const float*)d_in[13];
    const float* nkw = (const float*)d_in[14];
    float* out = (float*)d_out;

    void *pxh, *pxl;
    cudaGetSymbolAddress(&pxh, Xhi);
    cudaGetSymbolAddress(&pxl, Xlo);

    const int KV_SMEM  = (PBLK * HDIM * 2) * 4;
    const int MIX_SMEM = (NBLK * NBLK + NBLK * 128) * 4;
    const int OUT_SMEM = (HDIM * PBLK + HDIM * HDIM) * 4;
    cudaFuncSetAttribute(gemm_qkv,  cudaFuncAttributeMaxDynamicSharedMemorySize, GEMM_SMEM);
    cudaFuncSetAttribute(gemm_out,  cudaFuncAttributeMaxDynamicSharedMemorySize, GEMM_SMEM);
    cudaFuncSetAttribute(kv_kernel, cudaFuncAttributeMaxDynamicSharedMemorySize, KV_SMEM);
    cudaFuncSetAttribute(mix_kernel, cudaFuncAttributeMaxDynamicSharedMemorySize, MIX_SMEM);
    cudaFuncSetAttribute(out_kernel, cudaFuncAttributeMaxDynamicSharedMemorySize, OUT_SMEM);

    wblk_kernel<<<NBLK, 256>>>();
    conv_split<<<(MPAD * DIMC) / 256, 256>>>(x, (__nv_bfloat16*)pxh, (__nv_bfloat16*)pxl,
                                             NTOK * DIMC, MPAD * DIMC);
    conv_w4<<<dim3((DIMC * DIMC) / 256, 4), 256>>>(wq, wk, wv, wo);

    dim3 gg(DIMC / 128, MPAD / 128, 3);    // (12, 141, 3)
    gemm_qkv<<<gg, 256, GEMM_SMEM>>>(bq, bk, bv);

    rmsnorm_rope_kernel<<<dim3(NTOK, 2), 256>>>(nqw, nkw, fc, fs);

    qk_kernel<<<NHEAD * NBLK, HDIM>>>();
    kv_kernel<<<NHEAD * NBLK, 256, KV_SMEM>>>();
    mix_kernel<<<dim3(128, NHEAD), 256, MIX_SMEM>>>();
    norm_kernel<<<NHEAD * NBLK, 128>>>();
    out_kernel<<<NHEAD * NBLK, 256, OUT_SMEM>>>();

    dim3 go(DIMC / 128, MPAD / 128);
    gemm_out<<<go, 256, GEMM_SMEM>>>(bo, out);
}

// round 6
// speedup vs baseline: 3.1708x; 1.2508x over previous
#include <cuda_runtime.h>
#include <cuda_fp16.h>
#include <cstdint>
#include <cstdio>

// ---------------- problem dims (fixed) ----------------
#define NTOK   18000      // F*H*W = 12*30*50
#define MPAD   18048      // padded to multiple of 128
#define DIMC   1536
#define NHEAD  12
#define HDIM   128
#define NBLK   150        // FB*HB*WB = 3*5*10
#define PBLK   120        // P1*P2*P3 = 4*6*5
#define EPSF   1e-6f

typedef unsigned long long ull;

// ---------------- f32x2 helpers ----------------
__device__ __forceinline__ ull ffma2(ull a, ull b, ull c) {
    ull d;
    asm("fma.rn.f32x2 %0, %1, %2, %3;" : "=l"(d) : "l"(a), "l"(b), "l"(c));
    return d;
}
__device__ __forceinline__ ull pack2(float x, float y) {
    ull r;
    asm("mov.b64 %0, {%1, %2};" : "=l"(r) : "f"(x), "f"(y));
    return r;
}
__device__ __forceinline__ void unpack2(ull v, float& x, float& y) {
    asm("mov.b64 {%0, %1}, %2;" : "=f"(x), "=f"(y) : "l"(v));
}

// ---------------- mma / ldmatrix helpers ----------------
__device__ __forceinline__ uint32_t smem_u32(const void* p) {
    uint32_t a;
    asm("{ .reg .u64 t; cvta.to.shared.u64 t, %1; cvt.u32.u64 %0, t; }" : "=r"(a) : "l"(p));
    return a;
}
__device__ __forceinline__ void cp_async16(uint32_t dst, const void* src) {
    asm volatile("cp.async.cg.shared.global [%0], [%1], 16;" :: "r"(dst), "l"(src) : "memory");
}
__device__ __forceinline__ void ldm_x4(uint32_t* r, uint32_t addr) {
    asm volatile("ldmatrix.sync.aligned.m8n8.x4.shared.b16 {%0,%1,%2,%3}, [%4];"
                 : "=r"(r[0]), "=r"(r[1]), "=r"(r[2]), "=r"(r[3]) : "r"(addr));
}
__device__ __forceinline__ void mma16816(float* c, const uint32_t* a, const uint32_t* b) {
    asm volatile("mma.sync.aligned.m16n8k16.row.col.f32.f16.f16.f32 "
                 "{%0,%1,%2,%3}, {%4,%5,%6,%7}, {%8,%9}, {%0,%1,%2,%3};"
                 : "+f"(c[0]), "+f"(c[1]), "+f"(c[2]), "+f"(c[3])
                 : "r"(a[0]), "r"(a[1]), "r"(a[2]), "r"(a[3]), "r"(b[0]), "r"(b[1]));
}

// ---------------- scratch ----------------
__device__ float Qbuf[NTOK * DIMC];      // pre-rope normed q
__device__ float Kbuf[NTOK * DIMC];      // pre-rope normed k
__device__ float Vbuf[NTOK * DIMC];
__device__ float QRbuf[NTOK * DIMC];     // roped q
__device__ float KRbuf[NTOK * DIMC];     // roped k
__device__ float KVbuf[NHEAD * NBLK * HDIM * HDIM];
__device__ float KVMIXbuf[NHEAD * NBLK * HDIM * HDIM];
__device__ float QKbuf[NHEAD * NBLK * PBLK];
__device__ float NORMbuf[NHEAD * NBLK * PBLK];
__device__ float WBLKbuf[NBLK * NBLK];

// fp16 buffers: A operands plain fp16; weights split hi/lo fp16
__device__ __half Xh[MPAD * DIMC];
__device__ __half AOh[MPAD * DIMC];      // zero-init; pad rows never written
__device__ __half Wh4[4][DIMC * DIMC];
__device__ __half Wl4[4][DIMC * DIMC];

__device__ __forceinline__ int tok_of(int nb, int p) {
    int fb = nb / 50, hb = (nb / 10) % 5, wb = nb % 10;
    int p1 = p / 30, p2 = (p / 5) % 6, p3 = p % 5;
    int f = fb * 4 + p1, h = hb * 6 + p2, w = wb * 5 + p3;
    return (f * 30 + h) * 50 + w;
}

// ---------------- W_BLK ----------------
__global__ void wblk_kernel() {
    int j = blockIdx.x;
    int i = threadIdx.x;
    __shared__ double ssum[256];
    double m = 0.0;
    if (i < NBLK) {
        int fi = i / 50, hi = (i / 10) % 5, wi = i % 10;
        int fj = j / 50, hj = (j / 10) % 5, wj = j % 10;
        double df = fi - fj, dh = hi - hj, dw = wi - wj;
        double d = sqrt(df * df + dh * dh + dw * dw);
        m = 1.0 - d / sqrt(101.0);
    }
    ssum[i] = m;
    __syncthreads();
    for (int s = 128; s > 0; s >>= 1) {
        if (i < s) ssum[i] += ssum[i + s];
        __syncthreads();
    }
    if (i < NBLK) WBLKbuf[i * NBLK + j] = (float)(m / ssum[0]);
}

// ---------------- fp32 -> fp16 (plain) ----------------
__global__ void conv_half(const float* __restrict__ src, __half* __restrict__ dst, int n, int ntot) {
    int i = blockIdx.x * 256 + threadIdx.x;
    if (i >= ntot) return;
    float v = (i < n) ? src[i] : 0.f;
    dst[i] = __float2half(v);
}

// weights: hi/lo fp16 split, all 4 matrices
__global__ void conv_w4(const float* __restrict__ w0, const float* __restrict__ w1,
                        const float* __restrict__ w2, const float* __restrict__ w3) {
    int y = blockIdx.y;
    const float* src = (y == 0) ? w0 : (y == 1) ? w1 : (y == 2) ? w2 : w3;
    int i = blockIdx.x * 256 + threadIdx.x;
    float v = src[i];
    __half h = __float2half(v);
    Wh4[y][i] = h;
    Wl4[y][i] = __float2half(v - __half2float(h));
}

// ---------------- pipelined fp16 2-pass tensor-core GEMM ----------------
// C[m,n] = sum_k A[m,k]*(Bh[n,k]+Bl[n,k]) + bias[n]
// 128x128 tile, K-chunk 32 (64B rows), XOR swizzle, 4-stage cp.async ring.
#define KC      32
#define NCHUNK  (DIMC / KC)              // 48
#define TILEB   (128 * 64)               // 8192 B per operand tile
#define STAGEB  (3 * TILEB)              // 24576 B (Ah, Bh, Bl)
#define NSTAGE  4
#define GEMM_SMEM (NSTAGE * STAGEB)      // 98304 B -> 2 CTAs/SM

__device__ __forceinline__ void gemm_core(
    const __half* __restrict__ A,
    const __half* __restrict__ Bhi, const __half* __restrict__ Blo,
    const float* __restrict__ bias, float* __restrict__ C, int M,
    int m0, int n0, uint32_t sb)
{
    int tid = threadIdx.x;
    int wid = tid >> 5, lane = tid & 31;
    int wm = (wid & 1) * 64;
    int wn = (wid >> 1) * 32;
    int lr = lane >> 2, lc = lane & 3;
    int q = lane >> 3, rr = lane & 7;

    int a_row = (q & 1) * 8 + rr;
    int a_seg0 = q >> 1;
    int b_row = (q >> 1) * 8 + rr;
    int b_seg0 = q & 1;
    int swA = (a_row >> 1) & 3;
    int swB = (b_row >> 1) & 3;
    uint32_t rowbA = (uint32_t)(wm + a_row) * 64;
    uint32_t rowbB = (uint32_t)(wn + b_row) * 64;

    float acc[4][4][4];
#pragma unroll
    for (int i = 0; i < 4; i++)
#pragma unroll
        for (int j = 0; j < 4; j++)
#pragma unroll
            for (int r = 0; r < 4; r++) acc[i][j][r] = 0.f;

    // loader: 1536 x 16B segs per chunk -> 6 per thread
    auto load_chunk = [&](int c, int st) {
        size_t kof = (size_t)c * KC;
#pragma unroll
        for (int i = 0; i < 6; i++) {
            int idx = tid + i * 256;
            int t = idx >> 9, row = (idx >> 2) & 127, seg = idx & 3;
            const __half* g;
            if (t == 0)      g = A   + (size_t)(m0 + row) * DIMC + kof + seg * 8;
            else if (t == 1) g = Bhi + (size_t)(n0 + row) * DIMC + kof + seg * 8;
            else             g = Blo + (size_t)(n0 + row) * DIMC + kof + seg * 8;
            uint32_t dst = sb + st * STAGEB + t * TILEB + row * 64
                         + ((seg ^ ((row >> 1) & 3)) * 16);
            cp_async16(dst, g);
        }
        asm volatile("cp.async.commit_group;" ::: "memory");
    };

    load_chunk(0, 0);
    load_chunk(1, 1);
    load_chunk(2, 2);
    for (int c = 0; c < NCHUNK; c++) {
        if (c < NCHUNK - 2)
            asm volatile("cp.async.wait_group 2;" ::: "memory");
        else if (c == NCHUNK - 2)
            asm volatile("cp.async.wait_group 1;" ::: "memory");
        else
            asm volatile("cp.async.wait_group 0;" ::: "memory");
        __syncthreads();
        uint32_t tb = sb + (c & 3) * STAGEB;
        uint32_t bA  = tb + rowbA;
        uint32_t bBh = tb + TILEB + rowbB;
        uint32_t bBl = tb + 2 * TILEB + rowbB;

        // ks = 0
        {
            uint32_t offA = (uint32_t)((a_seg0 ^ swA) * 16);
            uint32_t offB = (uint32_t)((b_seg0 ^ swB) * 16);
            uint32_t ah[4][4], bh[2][4], bl[2][4];
#pragma unroll
            for (int mt = 0; mt < 4; mt++)
                ldm_x4(ah[mt], bA + mt * 1024 + offA);
#pragma unroll
            for (int nt2 = 0; nt2 < 2; nt2++) {
                ldm_x4(bh[nt2], bBh + nt2 * 1024 + offB);
                ldm_x4(bl[nt2], bBl + nt2 * 1024 + offB);
            }
#pragma unroll
            for (int mt = 0; mt < 4; mt++)
#pragma unroll
                for (int nt = 0; nt < 4; nt++) {
                    mma16816(acc[mt][nt], ah[mt], &bh[nt >> 1][(nt & 1) * 2]);
                    mma16816(acc[mt][nt], ah[mt], &bl[nt >> 1][(nt & 1) * 2]);
                }
        }
        // overlap next-chunk loads with compute
        if (c + 3 < NCHUNK) load_chunk(c + 3, (c + 3) & 3);
        // ks = 1
        {
            uint32_t offA = (uint32_t)(((a_seg0 + 2) ^ swA) * 16);
            uint32_t offB = (uint32_t)(((b_seg0 + 2) ^ swB) * 16);
            uint32_t ah[4][4], bh[2][4], bl[2][4];
#pragma unroll
            for (int mt = 0; mt < 4; mt++)
                ldm_x4(ah[mt], bA + mt * 1024 + offA);
#pragma unroll
            for (int nt2 = 0; nt2 < 2; nt2++) {
                ldm_x4(bh[nt2], bBh + nt2 * 1024 + offB);
                ldm_x4(bl[nt2], bBl + nt2 * 1024 + offB);
            }
#pragma unroll
            for (int mt = 0; mt < 4; mt++)
#pragma unroll
                for (int nt = 0; nt < 4; nt++) {
                    mma16816(acc[mt][nt], ah[mt], &bh[nt >> 1][(nt & 1) * 2]);
                    mma16816(acc[mt][nt], ah[mt], &bl[nt >> 1][(nt & 1) * 2]);
                }
        }
    }

#pragma unroll
    for (int mt = 0; mt < 4; mt++) {
        int m = m0 + wm + mt * 16 + lr;
#pragma unroll
        for (int nt = 0; nt < 4; nt++) {
            int col = n0 + wn + nt * 8 + lc * 2;
            float bx = bias[col], by = bias[col + 1];
            if (m < M) {
                float2 v = make_float2(acc[mt][nt][0] + bx, acc[mt][nt][1] + by);
                *(float2*)(C + (size_t)m * DIMC + col) = v;
            }
            if (m + 8 < M) {
                float2 v = make_float2(acc[mt][nt][2] + bx, acc[mt][nt][3] + by);
                *(float2*)(C + (size_t)(m + 8) * DIMC + col) = v;
            }
        }
    }
}

__global__ __launch_bounds__(256, 2) void gemm_qkv(
    const float* __restrict__ bq, const float* __restrict__ bk, const float* __restrict__ bv)
{
    extern __shared__ __align__(16) char smem[];
    uint32_t sb = smem_u32(smem);
    int z = blockIdx.z;
    const float* bias = (z == 0) ? bq : (z == 1) ? bk : bv;
    float* C = (z == 0) ? Qbuf : (z == 1) ? Kbuf : Vbuf;
    gemm_core(Xh, Wh4[z], Wl4[z], bias, C, NTOK, blockIdx.y * 128, blockIdx.x * 128, sb);
}

__global__ __launch_bounds__(256, 2) void gemm_out(const float* __restrict__ bo, float* __restrict__ out)
{
    extern __shared__ __align__(16) char smem[];
    uint32_t sb = smem_u32(smem);
    gemm_core(AOh, Wh4[3], Wl4[3], bo, out, NTOK, blockIdx.y * 128, blockIdx.x * 128, sb);
}

// ---------------- fused rmsnorm + relu + eps + RoPE ----------------
__global__ void rmsnorm_rope_kernel(const float* __restrict__ nqw, const float* __restrict__ nkw,
                                    const float* __restrict__ fc, const float* __restrict__ fs) {
    int n = blockIdx.x;
    bool isK = blockIdx.y;
    float* buf = isK ? Kbuf : Qbuf;
    float* rbuf = isK ? KRbuf : QRbuf;
    const float* w = isK ? nkw : nqw;
    int tid = threadIdx.x;
    size_t base = (size_t)n * DIMC;
    float2* b2 = (float2*)(buf + base);
    float2* r2 = (float2*)(rbuf + base);
    const float2* w2 = (const float2*)w;

    int f = n / 1500, rem = n % 1500;
    int hh = rem / 50, ww = rem % 50;

    float2 v[3];
    float ss = 0.f;
#pragma unroll
    for (int t = 0; t < 3; t++) {
        v[t] = b2[tid + t * 256];
        ss += v[t].x * v[t].x + v[t].y * v[t].y;
    }
    for (int o = 16; o > 0; o >>= 1) ss += __shfl_xor_sync(0xffffffffu, ss, o);
    __shared__ float red[8];
    __shared__ float stot;
    if ((tid & 31) == 0) red[tid >> 5] = ss;
    __syncthreads();
    if (tid == 0) {
        float t = 0.f;
        for (int i = 0; i < 8; i++) t += red[i];
        stot = t;
    }
    __syncthreads();
    float sc = 1.0f / sqrtf(stot * (1.0f / DIMC) + EPSF);
#pragma unroll
    for (int t = 0; t < 3; t++) {
        int idx = tid + t * 256;
        float2 wv = w2[idx];
        float x0 = fmaxf(v[t].x * sc * wv.x, 0.f) + EPSF;
        float x1 = fmaxf(v[t].y * sc * wv.y, 0.f) + EPSF;
        b2[idx] = make_float2(x0, x1);
        int c = idx & 63;
        int pos = (c < 22) ? f : ((c < 43) ? hh : ww);
        float cs = fc[pos * 64 + c];
        float sn = fs[pos * 64 + c];
        r2[idx] = make_float2(x0 * cs - x1 * sn, x0 * sn + x1 * cs);
    }
}

// ---------------- fused ksum + qk ----------------
__global__ void qk_kernel() {
    int b = blockIdx.x;
    int hh = b / NBLK, nb = b % NBLK;
    int tid = threadIdx.x;
    __shared__ float ks[HDIM];
    float acc = 0.f;
    for (int p = 0; p < PBLK; p++) {
        int t = tok_of(nb, p);
        acc += Kbuf[(size_t)t * DIMC + hh * HDIM + tid];
    }
    ks[tid] = acc;
    __syncthreads();
    if (tid < PBLK) {
        int t = tok_of(nb, tid);
        const float* qp = Qbuf + (size_t)t * DIMC + hh * HDIM;
        float a = 0.f;
#pragma unroll 4
        for (int d = 0; d < HDIM; d++) a += qp[d] * ks[d];
        QKbuf[b * PBLK + tid] = a;
    }
}

// ---------------- kv ----------------
__global__ __launch_bounds__(256) void kv_kernel() {
    extern __shared__ __align__(16) float sm[];
    float* sK = sm;
    float* sV = sm + PBLK * HDIM;
    int b = blockIdx.x;
    int hh = b / NBLK, nb = b % NBLK;
    int tid = threadIdx.x;
    for (int idx = tid; idx < PBLK * HDIM; idx += 256) {
        int p = idx >> 7, d = idx & 127;
        int t = tok_of(nb, p);
        size_t g = (size_t)t * DIMC + hh * HDIM + d;
        sK[idx] = KRbuf[g];
        sV[idx] = Vbuf[g];
    }
    __syncthreads();
    int tx = tid & 15, ty = tid >> 4;
    int e0 = tx * 8, d0 = ty * 8;
    ull acc[8][4];
#pragma unroll
    for (int i = 0; i < 8; i++)
#pragma unroll
        for (int jj = 0; jj < 4; jj++) acc[i][jj] = 0ULL;
    for (int p = 0; p < PBLK; p++) {
        float4 k1 = *(const float4*)&sK[p * HDIM + d0];
        float4 k2 = *(const float4*)&sK[p * HDIM + d0 + 4];
        ulonglong2 v1 = *(const ulonglong2*)&sV[p * HDIM + e0];
        ulonglong2 v2 = *(const ulonglong2*)&sV[p * HDIM + e0 + 4];
        ull bb0 = v1.x, bb1 = v1.y, bb2 = v2.x, bb3 = v2.y;
        float a[8] = {k1.x, k1.y, k1.z, k1.w, k2.x, k2.y, k2.z, k2.w};
#pragma unroll
        for (int i = 0; i < 8; i++) {
            ull a2 = pack2(a[i], a[i]);
            acc[i][0] = ffma2(a2, bb0, acc[i][0]);
            acc[i][1] = ffma2(a2, bb1, acc[i][1]);
            acc[i][2] = ffma2(a2, bb2, acc[i][2]);
            acc[i][3] = ffma2(a2, bb3, acc[i][3]);
        }
    }
    float* dst = KVbuf + (size_t)b * HDIM * HDIM;
#pragma unroll
    for (int i = 0; i < 8; i++) {
#pragma unroll
        for (int jj = 0; jj < 4; jj++) {
            float v0x, v1x;
            unpack2(acc[i][jj], v0x, v1x);
            int e = e0 + 2 * jj;
            dst[(d0 + i) * HDIM + e]     = v0x;
            dst[(d0 + i) * HDIM + e + 1] = v1x;
        }
    }
}

// ---------------- mix ----------------
__global__ __launch_bounds__(256) void mix_kernel() {
    extern __shared__ __align__(16) float sm[];
    float* Ws = sm;
    float* tB = sm + NBLK * NBLK;
    int hh = blockIdx.y, xt = blockIdx.x;
    int tid = threadIdx.x;
    for (int idx = tid; idx < NBLK * NBLK; idx += 256) Ws[idx] = WBLKbuf[idx];
    const float* src = KVbuf + (size_t)hh * NBLK * HDIM * HDIM + xt * 128;
    for (int idx = tid; idx < NBLK * 128; idx += 256) {
        int i = idx >> 7, c = idx & 127;
        tB[idx] = src[(size_t)i * HDIM * HDIM + c];
    }
    __syncthreads();
    int tx = tid & 15, ty = tid >> 4;
    ull acc[10][4];
#pragma unroll
    for (int oo = 0; oo < 10; oo++)
#pragma unroll
        for (int jj = 0; jj < 4; jj++) acc[oo][jj] = 0ULL;
    for (int i = 0; i < NBLK; i++) {
        ulonglong2 b1 = *(const ulonglong2*)&tB[i * 128 + tx * 8];
        ulonglong2 b2 = *(const ulonglong2*)&tB[i * 128 + tx * 8 + 4];
        ull bb0 = b1.x, bb1 = b1.y, bb2 = b2.x, bb3 = b2.y;
#pragma unroll
        for (int oo = 0; oo < 10; oo++) {
            int o = ty + 16 * oo;
            if (o < NBLK) {
                float w = Ws[o * NBLK + i];
                ull w2 = pack2(w, w);
                acc[oo][0] = ffma2(w2, bb0, acc[oo][0]);
                acc[oo][1] = ffma2(w2, bb1, acc[oo][1]);
                acc[oo][2] = ffma2(w2, bb2, acc[oo][2]);
                acc[oo][3] = ffma2(w2, bb3, acc[oo][3]);
            }
        }
    }
#pragma unroll
    for (int oo = 0; oo < 10; oo++) {
        int o = ty + 16 * oo;
        if (o < NBLK) {
            float* dst = KVMIXbuf + ((size_t)hh * NBLK + o) * HDIM * HDIM + xt * 128 + tx * 8;
#pragma unroll
            for (int jj = 0; jj < 4; jj++) {
                float v0x, v1x;
                unpack2(acc[oo][jj], v0x, v1x);
                dst[2 * jj]     = v0x;
                dst[2 * jj + 1] = v1x;
            }
        }
    }
}

// ---------------- norm ----------------
__global__ void norm_kernel() {
    int b = blockIdx.x;
    int hh = b / NBLK, o = b % NBLK;
    int p = threadIdx.x;
    if (p >= PBLK) return;
    float acc = EPSF;
    for (int i = 0; i < NBLK; i++)
        acc += WBLKbuf[o * NBLK + i] * QKbuf[(hh * NBLK + i) * PBLK + p];
    NORMbuf[b * PBLK + p] = acc;
}

// ---------------- out: writes AOh fp16 directly ----------------
__global__ __launch_bounds__(256) void out_kernel() {
    extern __shared__ __align__(16) float sm[];
    float* sQt = sm;                  // [128][120] d-major
    float* sKV = sm + HDIM * PBLK;    // [128][128]
    int b = blockIdx.x;
    int hh = b / NBLK, nb = b % NBLK;
    int tid = threadIdx.x;
    for (int idx = tid; idx < PBLK * HDIM; idx += 256) {
        int p = idx >> 7, d = idx & 127;
        int t = tok_of(nb, p);
        sQt[d * PBLK + p] = QRbuf[(size_t)t * DIMC + hh * HDIM + d];
    }
    const float* kvsrc = KVMIXbuf + (size_t)b * HDIM * HDIM;
    for (int idx = tid; idx < HDIM * HDIM; idx += 256) sKV[idx] = kvsrc[idx];
    __syncthreads();
    int tx = tid & 15, ty = tid >> 4;
    if (ty >= 15) return;
    int e0 = tx * 8, p0 = ty * 8;
    ull acc[8][4];
#pragma unroll
    for (int i = 0; i < 8; i++)
#pragma unroll
        for (int jj = 0; jj < 4; jj++) acc[i][jj] = 0ULL;
    for (int d = 0; d < HDIM; d++) {
        float4 q1 = *(const float4*)&sQt[d * PBLK + p0];
        float4 q2 = *(const float4*)&sQt[d * PBLK + p0 + 4];
        ulonglong2 k1 = *(const ulonglong2*)&sKV[d * HDIM + e0];
        ulonglong2 k2 = *(const ulonglong2*)&sKV[d * HDIM + e0 + 4];
        ull bb0 = k1.x, bb1 = k1.y, bb2 = k2.x, bb3 = k2.y;
        float a[8] = {q1.x, q1.y, q1.z, q1.w, q2.x, q2.y, q2.z, q2.w};
#pragma unroll
        for (int i = 0; i < 8; i++) {
            ull a2 = pack2(a[i], a[i]);
            acc[i][0] = ffma2(a2, bb0, acc[i][0]);
            acc[i][1] = ffma2(a2, bb1, acc[i][1]);
            acc[i][2] = ffma2(a2, bb2, acc[i][2]);
            acc[i][3] = ffma2(a2, bb3, acc[i][3]);
        }
    }
#pragma unroll
    for (int i = 0; i < 8; i++) {
        int p = p0 + i;
        float inv = 1.0f / NORMbuf[b * PBLK + p];
        int t = tok_of(nb, p);
        size_t gbase = (size_t)t * DIMC + hh * HDIM + e0;
        unsigned short hw[8];
#pragma unroll
        for (int jj = 0; jj < 4; jj++) {
            float v0x, v1x;
            unpack2(acc[i][jj], v0x, v1x);
            hw[2 * jj]     = __half_as_ushort(__float2half(v0x * inv));
            hw[2 * jj + 1] = __half_as_ushort(__float2half(v1x * inv));
        }
        *(uint4*)(AOh + gbase) = *(uint4*)hw;
    }
}

// ---------------- launch ----------------
extern "C" void kernel_launch(void* const* d_in, const int* in_sizes, int n_in,
                              void* d_out, int out_size) {
    const float* x   = (const float*)d_in[0];
    const float* fc  = (const float*)d_in[3];
    const float* fs  = (const float*)d_in[4];
    const float* wq  = (const float*)d_in[5];
    const float* bq  = (const float*)d_in[6];
    const float* wk  = (const float*)d_in[7];
    const float* bk  = (const float*)d_in[8];
    const float* wv  = (const float*)d_in[9];
    const float* bv  = (const float*)d_in[10];
    const float* wo  = (const float*)d_in[11];
    const float* bo  = (const float*)d_in[12];
    const float* nqw = (const float*)d_in[13];
    const float* nkw = (const float*)d_in[14];
    float* out = (float*)d_out;

    void* pxh;
    cudaGetSymbolAddress(&pxh, Xh);

    const int KV_SMEM  = (PBLK * HDIM * 2) * 4;
    const int MIX_SMEM = (NBLK * NBLK + NBLK * 128) * 4;
    const int OUT_SMEM = (HDIM * PBLK + HDIM * HDIM) * 4;
    cudaFuncSetAttribute(gemm_qkv,  cudaFuncAttributeMaxDynamicSharedMemorySize, GEMM_SMEM);
    cudaFuncSetAttribute(gemm_out,  cudaFuncAttributeMaxDynamicSharedMemorySize, GEMM_SMEM);
    cudaFuncSetAttribute(kv_kernel, cudaFuncAttributeMaxDynamicSharedMemorySize, KV_SMEM);
    cudaFuncSetAttribute(mix_kernel, cudaFuncAttributeMaxDynamicSharedMemorySize, MIX_SMEM);
    cudaFuncSetAttribute(out_kernel, cudaFuncAttributeMaxDynamicSharedMemorySize, OUT_SMEM);

    wblk_kernel<<<NBLK, 256>>>();
    conv_half<<<(MPAD * DIMC) / 256, 256>>>(x, (__half*)pxh, NTOK * DIMC, MPAD * DIMC);
    conv_w4<<<dim3((DIMC * DIMC) / 256, 4), 256>>>(wq, wk, wv, wo);

    dim3 gg(DIMC / 128, MPAD / 128, 3);    // (12, 141, 3)
    gemm_qkv<<<gg, 256, GEMM_SMEM>>>(bq, bk, bv);

    rmsnorm_rope_kernel<<<dim3(NTOK, 2), 256>>>(nqw, nkw, fc, fs);

    qk_kernel<<<NHEAD * NBLK, HDIM>>>();
    kv_kernel<<<NHEAD * NBLK, 256, KV_SMEM>>>();
    mix_kernel<<<dim3(128, NHEAD), 256, MIX_SMEM>>>();
    norm_kernel<<<NHEAD * NBLK, 128>>>();
    out_kernel<<<NHEAD * NBLK, 256, OUT_SMEM>>>();

    dim3 go(DIMC / 128, MPAD / 128);
    gemm_out<<<go, 256, GEMM_SMEM>>>(bo, out);
}

// round 7
// speedup vs baseline: 3.8207x; 1.2050x over previous
#include <cuda_runtime.h>
#include <cuda_fp16.h>
#include <cstdint>
#include <cstdio>

// ---------------- problem dims (fixed) ----------------
#define NTOK   18000      // F*H*W = 12*30*50
#define MPAD   18048      // padded to multiple of 128
#define DIMC   1536
#define NHEAD  12
#define HDIM   128
#define NBLK   150        // FB*HB*WB = 3*5*10
#define PBLK   120        // P1*P2*P3 = 4*6*5
#define EPSF   1e-6f

typedef unsigned long long ull;

// ---------------- f32x2 helpers ----------------
__device__ __forceinline__ ull ffma2(ull a, ull b, ull c) {
    ull d;
    asm("fma.rn.f32x2 %0, %1, %2, %3;" : "=l"(d) : "l"(a), "l"(b), "l"(c));
    return d;
}
__device__ __forceinline__ ull pack2(float x, float y) {
    ull r;
    asm("mov.b64 %0, {%1, %2};" : "=l"(r) : "f"(x), "f"(y));
    return r;
}
__device__ __forceinline__ void unpack2(ull v, float& x, float& y) {
    asm("mov.b64 {%0, %1}, %2;" : "=f"(x), "=f"(y) : "l"(v));
}

// ---------------- mma / ldmatrix helpers ----------------
__device__ __forceinline__ uint32_t smem_u32(const void* p) {
    uint32_t a;
    asm("{ .reg .u64 t; cvta.to.shared.u64 t, %1; cvt.u32.u64 %0, t; }" : "=r"(a) : "l"(p));
    return a;
}
__device__ __forceinline__ void cp_async16(uint32_t dst, const void* src) {
    asm volatile("cp.async.cg.shared.global [%0], [%1], 16;" :: "r"(dst), "l"(src) : "memory");
}
__device__ __forceinline__ void ldm_x4(uint32_t* r, uint32_t addr) {
    asm volatile("ldmatrix.sync.aligned.m8n8.x4.shared.b16 {%0,%1,%2,%3}, [%4];"
                 : "=r"(r[0]), "=r"(r[1]), "=r"(r[2]), "=r"(r[3]) : "r"(addr));
}
__device__ __forceinline__ void ldm_x4_t(uint32_t* r, uint32_t addr) {
    asm volatile("ldmatrix.sync.aligned.m8n8.x4.trans.shared.b16 {%0,%1,%2,%3}, [%4];"
                 : "=r"(r[0]), "=r"(r[1]), "=r"(r[2]), "=r"(r[3]) : "r"(addr));
}
__device__ __forceinline__ void mma16816(float* c, const uint32_t* a, const uint32_t* b) {
    asm volatile("mma.sync.aligned.m16n8k16.row.col.f32.f16.f16.f32 "
                 "{%0,%1,%2,%3}, {%4,%5,%6,%7}, {%8,%9}, {%0,%1,%2,%3};"
                 : "+f"(c[0]), "+f"(c[1]), "+f"(c[2]), "+f"(c[3])
                 : "r"(a[0]), "r"(a[1]), "r"(a[2]), "r"(a[3]), "r"(b[0]), "r"(b[1]));
}
__device__ __forceinline__ uint32_t h2pack(float a, float b) {
    __half2 h = __floats2half2_rn(a, b);
    return *(uint32_t*)&h;
}
__device__ __forceinline__ uint32_t h2packlo(float a, float b, uint32_t hp) {
    __half2 h = *(__half2*)&hp;
    float2 hf = __half22float2(h);
    __half2 l = __floats2half2_rn(a - hf.x, b - hf.y);
    return *(uint32_t*)&l;
}

// ---------------- scratch ----------------
__device__ float Qbuf[NTOK * DIMC];      // pre-rope normed q (fp32, for qk)
__device__ float Kbuf[NTOK * DIMC];      // pre-rope normed k (fp32, for qk)
__device__ float KVbuf[NHEAD * NBLK * HDIM * HDIM];   // fp32 (mix input)
__device__ float QKbuf[NHEAD * NBLK * PBLK];
__device__ float NORMbuf[NHEAD * NBLK * PBLK];
__device__ float WBLKbuf[NBLK * NBLK];

// fp16 operand buffers
__device__ __half Xh[MPAD * DIMC];
__device__ __half AOh[MPAD * DIMC];      // zero-init; pad rows never written
__device__ __half Wh4[4][DIMC * DIMC];
__device__ __half Wl4[4][DIMC * DIMC];
__device__ __half Vh[NTOK * DIMC];
__device__ __half Vl[NTOK * DIMC];
__device__ __half QRh[NTOK * DIMC];
__device__ __half QRl[NTOK * DIMC];
__device__ __half KRh[NTOK * DIMC];
__device__ __half KRl[NTOK * DIMC];
__device__ __half KVMh[NHEAD * NBLK * HDIM * HDIM];
__device__ __half KVMl[NHEAD * NBLK * HDIM * HDIM];

__device__ __forceinline__ int tok_of(int nb, int p) {
    int fb = nb / 50, hb = (nb / 10) % 5, wb = nb % 10;
    int p1 = p / 30, p2 = (p / 5) % 6, p3 = p % 5;
    int f = fb * 4 + p1, h = hb * 6 + p2, w = wb * 5 + p3;
    return (f * 30 + h) * 50 + w;
}

// ---------------- W_BLK ----------------
__global__ void wblk_kernel() {
    int j = blockIdx.x;
    int i = threadIdx.x;
    __shared__ double ssum[256];
    double m = 0.0;
    if (i < NBLK) {
        int fi = i / 50, hi = (i / 10) % 5, wi = i % 10;
        int fj = j / 50, hj = (j / 10) % 5, wj = j % 10;
        double df = fi - fj, dh = hi - hj, dw = wi - wj;
        double d = sqrt(df * df + dh * dh + dw * dw);
        m = 1.0 - d / sqrt(101.0);
    }
    ssum[i] = m;
    __syncthreads();
    for (int s = 128; s > 0; s >>= 1) {
        if (i < s) ssum[i] += ssum[i + s];
        __syncthreads();
    }
    if (i < NBLK) WBLKbuf[i * NBLK + j] = (float)(m / ssum[0]);
}

// ---------------- fp32 -> fp16 ----------------
__global__ void conv_half(const float* __restrict__ src, __half* __restrict__ dst, int n, int ntot) {
    int i = blockIdx.x * 256 + threadIdx.x;
    if (i >= ntot) return;
    float v = (i < n) ? src[i] : 0.f;
    dst[i] = __float2half(v);
}

__global__ void conv_w4(const float* __restrict__ w0, const float* __restrict__ w1,
                        const float* __restrict__ w2, const float* __restrict__ w3) {
    int y = blockIdx.y;
    const float* src = (y == 0) ? w0 : (y == 1) ? w1 : (y == 2) ? w2 : w3;
    int i = blockIdx.x * 256 + threadIdx.x;
    float v = src[i];
    __half h = __float2half(v);
    Wh4[y][i] = h;
    Wl4[y][i] = __float2half(v - __half2float(h));
}

// ---------------- pipelined fp16 2-pass tensor-core GEMM ----------------
#define KC      32
#define NCHUNK  (DIMC / KC)              // 48
#define TILEB   (128 * 64)               // 8192 B per operand tile
#define STAGEB  (3 * TILEB)              // 24576 B
#define NSTAGE  4
#define GEMM_SMEM (NSTAGE * STAGEB)      // 98304 B -> 2 CTAs/SM

__device__ __forceinline__ void gemm_core(
    const __half* __restrict__ A,
    const __half* __restrict__ Bhi, const __half* __restrict__ Blo,
    const float* __restrict__ bias, float* __restrict__ C,
    __half* __restrict__ VhOut, __half* __restrict__ VlOut, int M,
    int m0, int n0, uint32_t sb)
{
    int tid = threadIdx.x;
    int wid = tid >> 5, lane = tid & 31;
    int wm = (wid & 1) * 64;
    int wn = (wid >> 1) * 32;
    int lr = lane >> 2, lc = lane & 3;
    int q = lane >> 3, rr = lane & 7;

    int a_row = (q & 1) * 8 + rr;
    int a_seg0 = q >> 1;
    int b_row = (q >> 1) * 8 + rr;
    int b_seg0 = q & 1;
    int swA = (a_row >> 1) & 3;
    int swB = (b_row >> 1) & 3;
    uint32_t rowbA = (uint32_t)(wm + a_row) * 64;
    uint32_t rowbB = (uint32_t)(wn + b_row) * 64;

    float acc[4][4][4];
#pragma unroll
    for (int i = 0; i < 4; i++)
#pragma unroll
        for (int j = 0; j < 4; j++)
#pragma unroll
            for (int r = 0; r < 4; r++) acc[i][j][r] = 0.f;

    auto load_chunk = [&](int c, int st) {
        size_t kof = (size_t)c * KC;
#pragma unroll
        for (int i = 0; i < 6; i++) {
            int idx = tid + i * 256;
            int t = idx >> 9, row = (idx >> 2) & 127, seg = idx & 3;
            const __half* g;
            if (t == 0)      g = A   + (size_t)(m0 + row) * DIMC + kof + seg * 8;
            else if (t == 1) g = Bhi + (size_t)(n0 + row) * DIMC + kof + seg * 8;
            else             g = Blo + (size_t)(n0 + row) * DIMC + kof + seg * 8;
            uint32_t dst = sb + st * STAGEB + t * TILEB + row * 64
                         + ((seg ^ ((row >> 1) & 3)) * 16);
            cp_async16(dst, g);
        }
        asm volatile("cp.async.commit_group;" ::: "memory");
    };

    load_chunk(0, 0);
    load_chunk(1, 1);
    load_chunk(2, 2);
    for (int c = 0; c < NCHUNK; c++) {
        if (c < NCHUNK - 2)
            asm volatile("cp.async.wait_group 2;" ::: "memory");
        else if (c == NCHUNK - 2)
            asm volatile("cp.async.wait_group 1;" ::: "memory");
        else
            asm volatile("cp.async.wait_group 0;" ::: "memory");
        __syncthreads();
        uint32_t tb = sb + (c & 3) * STAGEB;
        uint32_t bA  = tb + rowbA;
        uint32_t bBh = tb + TILEB + rowbB;
        uint32_t bBl = tb + 2 * TILEB + rowbB;

        {
            uint32_t offA = (uint32_t)((a_seg0 ^ swA) * 16);
            uint32_t offB = (uint32_t)((b_seg0 ^ swB) * 16);
            uint32_t ah[4][4], bh[2][4], bl[2][4];
#pragma unroll
            for (int mt = 0; mt < 4; mt++)
                ldm_x4(ah[mt], bA + mt * 1024 + offA);
#pragma unroll
            for (int nt2 = 0; nt2 < 2; nt2++) {
                ldm_x4(bh[nt2], bBh + nt2 * 1024 + offB);
                ldm_x4(bl[nt2], bBl + nt2 * 1024 + offB);
            }
#pragma unroll
            for (int mt = 0; mt < 4; mt++)
#pragma unroll
                for (int nt = 0; nt < 4; nt++) {
                    mma16816(acc[mt][nt], ah[mt], &bh[nt >> 1][(nt & 1) * 2]);
                    mma16816(acc[mt][nt], ah[mt], &bl[nt >> 1][(nt & 1) * 2]);
                }
        }
        if (c + 3 < NCHUNK) load_chunk(c + 3, (c + 3) & 3);
        {
            uint32_t offA = (uint32_t)(((a_seg0 + 2) ^ swA) * 16);
            uint32_t offB = (uint32_t)(((b_seg0 + 2) ^ swB) * 16);
            uint32_t ah[4][4], bh[2][4], bl[2][4];
#pragma unroll
            for (int mt = 0; mt < 4; mt++)
                ldm_x4(ah[mt], bA + mt * 1024 + offA);
#pragma unroll
            for (int nt2 = 0; nt2 < 2; nt2++) {
                ldm_x4(bh[nt2], bBh + nt2 * 1024 + offB);
                ldm_x4(bl[nt2], bBl + nt2 * 1024 + offB);
            }
#pragma unroll
            for (int mt = 0; mt < 4; mt++)
#pragma unroll
                for (int nt = 0; nt < 4; nt++) {
                    mma16816(acc[mt][nt], ah[mt], &bh[nt >> 1][(nt & 1) * 2]);
                    mma16816(acc[mt][nt], ah[mt], &bl[nt >> 1][(nt & 1) * 2]);
                }
        }
    }

#pragma unroll
    for (int mt = 0; mt < 4; mt++) {
        int m = m0 + wm + mt * 16 + lr;
#pragma unroll
        for (int nt = 0; nt < 4; nt++) {
            int col = n0 + wn + nt * 8 + lc * 2;
            float bx = bias[col], by = bias[col + 1];
            if (VhOut) {
                if (m < M) {
                    float v0 = acc[mt][nt][0] + bx, v1 = acc[mt][nt][1] + by;
                    uint32_t hp = h2pack(v0, v1);
                    *(uint32_t*)(VhOut + (size_t)m * DIMC + col) = hp;
                    *(uint32_t*)(VlOut + (size_t)m * DIMC + col) = h2packlo(v0, v1, hp);
                }
                if (m + 8 < M) {
                    float v0 = acc[mt][nt][2] + bx, v1 = acc[mt][nt][3] + by;
                    uint32_t hp = h2pack(v0, v1);
                    *(uint32_t*)(VhOut + (size_t)(m + 8) * DIMC + col) = hp;
                    *(uint32_t*)(VlOut + (size_t)(m + 8) * DIMC + col) = h2packlo(v0, v1, hp);
                }
            } else {
                if (m < M) {
                    float2 v = make_float2(acc[mt][nt][0] + bx, acc[mt][nt][1] + by);
                    *(float2*)(C + (size_t)m * DIMC + col) = v;
                }
                if (m + 8 < M) {
                    float2 v = make_float2(acc[mt][nt][2] + bx, acc[mt][nt][3] + by);
                    *(float2*)(C + (size_t)(m + 8) * DIMC + col) = v;
                }
            }
        }
    }
}

__global__ __launch_bounds__(256, 2) void gemm_qkv(
    const float* __restrict__ bq, const float* __restrict__ bk, const float* __restrict__ bv)
{
    extern __shared__ __align__(16) char smem[];
    uint32_t sb = smem_u32(smem);
    int z = blockIdx.z;
    const float* bias = (z == 0) ? bq : (z == 1) ? bk : bv;
    float* C = (z == 0) ? Qbuf : Kbuf;
    __half* vh = (z == 2) ? Vh : (__half*)0;
    __half* vl = (z == 2) ? Vl : (__half*)0;
    gemm_core(Xh, Wh4[z], Wl4[z], bias, C, vh, vl, NTOK, blockIdx.y * 128, blockIdx.x * 128, sb);
}

__global__ __launch_bounds__(256, 2) void gemm_out(const float* __restrict__ bo, float* __restrict__ out)
{
    extern __shared__ __align__(16) char smem[];
    uint32_t sb = smem_u32(smem);
    gemm_core(AOh, Wh4[3], Wl4[3], bo, out, (__half*)0, (__half*)0, NTOK,
              blockIdx.y * 128, blockIdx.x * 128, sb);
}

// ---------------- fused rmsnorm + relu + eps + RoPE; fp16 hi/lo roped outputs ----------------
__global__ void rmsnorm_rope_kernel(const float* __restrict__ nqw, const float* __restrict__ nkw,
                                    const float* __restrict__ fc, const float* __restrict__ fs) {
    int n = blockIdx.x;
    bool isK = blockIdx.y;
    float* buf = isK ? Kbuf : Qbuf;
    __half* rh = isK ? KRh : QRh;
    __half* rl = isK ? KRl : QRl;
    const float* w = isK ? nkw : nqw;
    int tid = threadIdx.x;
    size_t base = (size_t)n * DIMC;
    float2* b2 = (float2*)(buf + base);
    const float2* w2 = (const float2*)w;

    int f = n / 1500, rem = n % 1500;
    int hh = rem / 50, ww = rem % 50;

    float2 v[3];
    float ss = 0.f;
#pragma unroll
    for (int t = 0; t < 3; t++) {
        v[t] = b2[tid + t * 256];
        ss += v[t].x * v[t].x + v[t].y * v[t].y;
    }
    for (int o = 16; o > 0; o >>= 1) ss += __shfl_xor_sync(0xffffffffu, ss, o);
    __shared__ float red[8];
    __shared__ float stot;
    if ((tid & 31) == 0) red[tid >> 5] = ss;
    __syncthreads();
    if (tid == 0) {
        float t = 0.f;
        for (int i = 0; i < 8; i++) t += red[i];
        stot = t;
    }
    __syncthreads();
    float sc = 1.0f / sqrtf(stot * (1.0f / DIMC) + EPSF);
#pragma unroll
    for (int t = 0; t < 3; t++) {
        int idx = tid + t * 256;
        float2 wv = w2[idx];
        float x0 = fmaxf(v[t].x * sc * wv.x, 0.f) + EPSF;
        float x1 = fmaxf(v[t].y * sc * wv.y, 0.f) + EPSF;
        b2[idx] = make_float2(x0, x1);
        int c = idx & 63;
        int pos = (c < 22) ? f : ((c < 43) ? hh : ww);
        float cs = fc[pos * 64 + c];
        float sn = fs[pos * 64 + c];
        float r0 = x0 * cs - x1 * sn;
        float r1 = x0 * sn + x1 * cs;
        uint32_t hp = h2pack(r0, r1);
        *(uint32_t*)(rh + base + 2 * idx) = hp;
        *(uint32_t*)(rl + base + 2 * idx) = h2packlo(r0, r1, hp);
    }
}

// ---------------- fused ksum + qk (fp32) ----------------
__global__ void qk_kernel() {
    int b = blockIdx.x;
    int hh = b / NBLK, nb = b % NBLK;
    int tid = threadIdx.x;
    __shared__ float ks[HDIM];
    float acc = 0.f;
    for (int p = 0; p < PBLK; p++) {
        int t = tok_of(nb, p);
        acc += Kbuf[(size_t)t * DIMC + hh * HDIM + tid];
    }
    ks[tid] = acc;
    __syncthreads();
    if (tid < PBLK) {
        int t = tok_of(nb, tid);
        const float* qp = Qbuf + (size_t)t * DIMC + hh * HDIM;
        float a = 0.f;
#pragma unroll 4
        for (int d = 0; d < HDIM; d++) a += qp[d] * ks[d];
        QKbuf[b * PBLK + tid] = a;
    }
}

// ---------------- kv: tensor-core fp16 3-pass;  KV[d,e] = sum_p KR[p,d]*V[p,e] ----------------
#define T2ST  136                       // halves per smem row (272 B, 4-bank rotation)
#define T2B   (128 * T2ST * 2)          // 34816 B per tile
#define KV2_SMEM (4 * T2B)              // 139264

__global__ __launch_bounds__(256) void kv_kernel() {
    extern __shared__ __align__(16) char smem[];
    uint32_t sb = smem_u32(smem);
    int b = blockIdx.x;
    int hh = b / NBLK, nb = b % NBLK;
    int tid = threadIdx.x;

    // zero k-pad rows 120..127 (first 256B of each row) in all 4 tiles
    for (int i = tid; i < 4 * 8 * 16; i += 256) {
        int t = i >> 7, r = (i >> 4) & 7, s = i & 15;
        *(uint4*)(smem + t * T2B + (120 + r) * (T2ST * 2) + s * 16) = make_uint4(0, 0, 0, 0);
    }
    // load tiles: 0=KRh 1=KRl 2=Vh 3=Vl; 1920 16B-segs each
#pragma unroll
    for (int i = 0; i < 30; i++) {
        int idx = tid + i * 256;
        int t = idx / 1920;
        int rem = idx - t * 1920;
        int row = rem >> 4, seg = rem & 15;
        int tok = tok_of(nb, row);
        const __half* g = (t == 0) ? KRh : (t == 1) ? KRl : (t == 2) ? Vh : Vl;
        g += (size_t)tok * DIMC + hh * HDIM + seg * 8;
        cp_async16(sb + t * T2B + row * (T2ST * 2) + seg * 16, g);
    }
    asm volatile("cp.async.commit_group;" ::: "memory");
    asm volatile("cp.async.wait_group 0;" ::: "memory");
    __syncthreads();

    int wid = tid >> 5, lane = tid & 31;
    int q = lane >> 3, rr = lane & 7;
    int wm = (wid & 3) * 32, wn = (wid >> 2) * 64;   // d, e
    uint32_t bKRh = sb, bKRl = sb + T2B, bVh = sb + 2 * T2B, bVl = sb + 3 * T2B;

    float acc[2][8][4];
#pragma unroll
    for (int i = 0; i < 2; i++)
#pragma unroll
        for (int j = 0; j < 8; j++)
#pragma unroll
            for (int r = 0; r < 4; r++) acc[i][j][r] = 0.f;

#pragma unroll
    for (int ks = 0; ks < 8; ks++) {
        int p0 = ks * 16;
        uint32_t ah[2][4], al[2][4], bh[4][4], bl[4][4];
#pragma unroll
        for (int mt = 0; mt < 2; mt++) {
            int d0 = wm + mt * 16;
            // A(trans): row = p0 + (q>>1)*8 + rr, col = d0 + (q&1)*8
            uint32_t ad = (uint32_t)((p0 + (q >> 1) * 8 + rr) * T2ST + d0 + (q & 1) * 8) * 2;
            ldm_x4_t(ah[mt], bKRh + ad);
            ldm_x4_t(al[mt], bKRl + ad);
        }
#pragma unroll
        for (int nt2 = 0; nt2 < 4; nt2++) {
            int e0 = wn + nt2 * 16;
            // B(trans): row = p0 + (q&1)*8 + rr, col = e0 + (q>>1)*8
            uint32_t bd = (uint32_t)((p0 + (q & 1) * 8 + rr) * T2ST + e0 + (q >> 1) * 8) * 2;
            ldm_x4_t(bh[nt2], bVh + bd);
            ldm_x4_t(bl[nt2], bVl + bd);
        }
#pragma unroll
        for (int mt = 0; mt < 2; mt++)
#pragma unroll
            for (int nt = 0; nt < 8; nt++) {
                const uint32_t* pbh = &bh[nt >> 1][(nt & 1) * 2];
                const uint32_t* pbl = &bl[nt >> 1][(nt & 1) * 2];
                mma16816(acc[mt][nt], ah[mt], pbh);
                mma16816(acc[mt][nt], ah[mt], pbl);
                mma16816(acc[mt][nt], al[mt], pbh);
            }
    }

    int lr = lane >> 2, lc = lane & 3;
    float* dst = KVbuf + (size_t)b * HDIM * HDIM;
#pragma unroll
    for (int mt = 0; mt < 2; mt++) {
        int d = wm + mt * 16 + lr;
#pragma unroll
        for (int nt = 0; nt < 8; nt++) {
            int e = wn + nt * 8 + lc * 2;
            *(float2*)(dst + d * HDIM + e) = make_float2(acc[mt][nt][0], acc[mt][nt][1]);
            *(float2*)(dst + (d + 8) * HDIM + e) = make_float2(acc[mt][nt][2], acc[mt][nt][3]);
        }
    }
}

// ---------------- mix (fp32 f32x2), writes fp16 hi/lo ----------------
__global__ __launch_bounds__(256) void mix_kernel() {
    extern __shared__ __align__(16) float sm[];
    float* Ws = sm;
    float* tB = sm + NBLK * NBLK;
    int hh = blockIdx.y, xt = blockIdx.x;
    int tid = threadIdx.x;
    for (int idx = tid; idx < NBLK * NBLK; idx += 256) Ws[idx] = WBLKbuf[idx];
    const float* src = KVbuf + (size_t)hh * NBLK * HDIM * HDIM + xt * 128;
    for (int idx = tid; idx < NBLK * 128; idx += 256) {
        int i = idx >> 7, c = idx & 127;
        tB[idx] = src[(size_t)i * HDIM * HDIM + c];
    }
    __syncthreads();
    int tx = tid & 15, ty = tid >> 4;
    ull acc[10][4];
#pragma unroll
    for (int oo = 0; oo < 10; oo++)
#pragma unroll
        for (int jj = 0; jj < 4; jj++) acc[oo][jj] = 0ULL;
    for (int i = 0; i < NBLK; i++) {
        ulonglong2 b1 = *(const ulonglong2*)&tB[i * 128 + tx * 8];
        ulonglong2 b2 = *(const ulonglong2*)&tB[i * 128 + tx * 8 + 4];
        ull bb0 = b1.x, bb1 = b1.y, bb2 = b2.x, bb3 = b2.y;
#pragma unroll
        for (int oo = 0; oo < 10; oo++) {
            int o = ty + 16 * oo;
            if (o < NBLK) {
                float w = Ws[o * NBLK + i];
                ull w2 = pack2(w, w);
                acc[oo][0] = ffma2(w2, bb0, acc[oo][0]);
                acc[oo][1] = ffma2(w2, bb1, acc[oo][1]);
                acc[oo][2] = ffma2(w2, bb2, acc[oo][2]);
                acc[oo][3] = ffma2(w2, bb3, acc[oo][3]);
            }
        }
    }
#pragma unroll
    for (int oo = 0; oo < 10; oo++) {
        int o = ty + 16 * oo;
        if (o < NBLK) {
            size_t gb = ((size_t)hh * NBLK + o) * HDIM * HDIM + xt * 128 + tx * 8;
#pragma unroll
            for (int jj = 0; jj < 4; jj++) {
                float v0x, v1x;
                unpack2(acc[oo][jj], v0x, v1x);
                uint32_t hp = h2pack(v0x, v1x);
                *(uint32_t*)(KVMh + gb + 2 * jj) = hp;
                *(uint32_t*)(KVMl + gb + 2 * jj) = h2packlo(v0x, v1x, hp);
            }
        }
    }
}

// ---------------- norm ----------------
__global__ void norm_kernel() {
    int b = blockIdx.x;
    int hh = b / NBLK, o = b % NBLK;
    int p = threadIdx.x;
    if (p >= PBLK) return;
    float acc = EPSF;
    for (int i = 0; i < NBLK; i++)
        acc += WBLKbuf[o * NBLK + i] * QKbuf[(hh * NBLK + i) * PBLK + p];
    NORMbuf[b * PBLK + p] = acc;
}

// ---------------- out: tc fp16 3-pass; C[p,e] = sum_d QR[p,d]*KVM[d,e]; /norm -> AOh ----------------
#define OUT2_SMEM (4 * T2B)

__global__ __launch_bounds__(256) void out_kernel() {
    extern __shared__ __align__(16) char smem[];
    uint32_t sb = smem_u32(smem);
    int b = blockIdx.x;
    int hh = b / NBLK, nb = b % NBLK;
    int tid = threadIdx.x;

    // tiles: 0=QRh 1=QRl (rows p, 120 valid) 2=KVMh 3=KVMl (rows d, 128)
    // loads: QR 2*1920 + KVM 2*2048 = 7936 segs = 31/thread
#pragma unroll
    for (int i = 0; i < 31; i++) {
        int idx = tid + i * 256;
        if (idx < 3840) {
            int t = idx / 1920;
            int rem = idx - t * 1920;
            int row = rem >> 4, seg = rem & 15;
            int tok = tok_of(nb, row);
            const __half* g = (t == 0) ? QRh : QRl;
            g += (size_t)tok * DIMC + hh * HDIM + seg * 8;
            cp_async16(sb + t * T2B + row * (T2ST * 2) + seg * 16, g);
        } else {
            int idx2 = idx - 3840;
            int t = idx2 >> 11;
            int rem = idx2 & 2047;
            int row = rem >> 4, seg = rem & 15;
            const __half* g = (t == 0) ? KVMh : KVMl;
            g += (size_t)b * HDIM * HDIM + row * HDIM + seg * 8;
            cp_async16(sb + (2 + t) * T2B + row * (T2ST * 2) + seg * 16, g);
        }
    }
    asm volatile("cp.async.commit_group;" ::: "memory");
    asm volatile("cp.async.wait_group 0;" ::: "memory");
    __syncthreads();

    int wid = tid >> 5, lane = tid & 31;
    int q = lane >> 3, rr = lane & 7;
    int wm = (wid & 1) * 64, wn = (wid >> 1) * 32;   // p, e
    uint32_t bQh = sb, bQl = sb + T2B, bMh = sb + 2 * T2B, bMl = sb + 3 * T2B;

    float acc[4][4][4];
#pragma unroll
    for (int i = 0; i < 4; i++)
#pragma unroll
        for (int j = 0; j < 4; j++)
#pragma unroll
            for (int r = 0; r < 4; r++) acc[i][j][r] = 0.f;

#pragma unroll
    for (int ks = 0; ks < 8; ks++) {
        int d0 = ks * 16;
        uint32_t ah[4][4], al[4][4], bh[2][4], bl[2][4];
#pragma unroll
        for (int mt = 0; mt < 4; mt++) {
            int m0 = wm + mt * 16;
            // A(non-trans): row = m0 + (q&1)*8 + rr, col = d0 + (q>>1)*8
            uint32_t ad = (uint32_t)((m0 + (q & 1) * 8 + rr) * T2ST + d0 + (q >> 1) * 8) * 2;
            ldm_x4(ah[mt], bQh + ad);
            ldm_x4(al[mt], bQl + ad);
        }
#pragma unroll
        for (int nt2 = 0; nt2 < 2; nt2++) {
            int e0 = wn + nt2 * 16;
            // B(trans): row = d0 + (q&1)*8 + rr, col = e0 + (q>>1)*8
            uint32_t bd = (uint32_t)((d0 + (q & 1) * 8 + rr) * T2ST + e0 + (q >> 1) * 8) * 2;
            ldm_x4_t(bh[nt2], bMh + bd);
            ldm_x4_t(bl[nt2], bMl + bd);
        }
#pragma unroll
        for (int mt = 0; mt < 4; mt++)
#pragma unroll
            for (int nt = 0; nt < 4; nt++) {
                const uint32_t* pbh = &bh[nt >> 1][(nt & 1) * 2];
                const uint32_t* pbl = &bl[nt >> 1][(nt & 1) * 2];
                mma16816(acc[mt][nt], ah[mt], pbh);
                mma16816(acc[mt][nt], ah[mt], pbl);
                mma16816(acc[mt][nt], al[mt], pbh);
            }
    }

    int lr = lane >> 2, lc = lane & 3;
#pragma unroll
    for (int mt = 0; mt < 4; mt++) {
        int p = wm + mt * 16 + lr;
#pragma unroll
        for (int half = 0; half < 2; half++) {
            int pp = p + half * 8;
            if (pp < PBLK) {
                float inv = 1.0f / NORMbuf[b * PBLK + pp];
                int tok = tok_of(nb, pp);
                size_t gb = (size_t)tok * DIMC + hh * HDIM;
#pragma unroll
                for (int nt = 0; nt < 4; nt++) {
                    int e = wn + nt * 8 + lc * 2;
                    float v0 = acc[mt][nt][2 * half]     * inv;
                    float v1 = acc[mt][nt][2 * half + 1] * inv;
                    *(uint32_t*)(AOh + gb + e) = h2pack(v0, v1);
                }
            }
        }
    }
}

// ---------------- launch ----------------
extern "C" void kernel_launch(void* const* d_in, const int* in_sizes, int n_in,
                              void* d_out, int out_size) {
    const float* x   = (const float*)d_in[0];
    const float* fc  = (const float*)d_in[3];
    const float* fs  = (const float*)d_in[4];
    const float* wq  = (const float*)d_in[5];
    const float* bq  = (const float*)d_in[6];
    const float* wk  = (const float*)d_in[7];
    const float* bk  = (const float*)d_in[8];
    const float* wv  = (const float*)d_in[9];
    const float* bv  = (const float*)d_in[10];
    const float* wo  = (const float*)d_in[11];
    const float* bo  = (const float*)d_in[12];
    const float* nqw = (const float*)d_in[13];
    const float* nkw = (const float*)d_in[14];
    float* out = (float*)d_out;

    void* pxh;
    cudaGetSymbolAddress(&pxh, Xh);

    const int MIX_SMEM = (NBLK * NBLK + NBLK * 128) * 4;
    cudaFuncSetAttribute(gemm_qkv,  cudaFuncAttributeMaxDynamicSharedMemorySize, GEMM_SMEM);
    cudaFuncSetAttribute(gemm_out,  cudaFuncAttributeMaxDynamicSharedMemorySize, GEMM_SMEM);
    cudaFuncSetAttribute(kv_kernel, cudaFuncAttributeMaxDynamicSharedMemorySize, KV2_SMEM);
    cudaFuncSetAttribute(mix_kernel, cudaFuncAttributeMaxDynamicSharedMemorySize, MIX_SMEM);
    cudaFuncSetAttribute(out_kernel, cudaFuncAttributeMaxDynamicSharedMemorySize, OUT2_SMEM);

    wblk_kernel<<<NBLK, 256>>>();
    conv_half<<<(MPAD * DIMC) / 256, 256>>>(x, (__half*)pxh, NTOK * DIMC, MPAD * DIMC);
    conv_w4<<<dim3((DIMC * DIMC) / 256, 4), 256>>>(wq, wk, wv, wo);

    dim3 gg(DIMC / 128, MPAD / 128, 3);
    gemm_qkv<<<gg, 256, GEMM_SMEM>>>(bq, bk, bv);

    rmsnorm_rope_kernel<<<dim3(NTOK, 2), 256>>>(nqw, nkw, fc, fs);

    qk_kernel<<<NHEAD * NBLK, HDIM>>>();
    kv_kernel<<<NHEAD * NBLK, 256, KV2_SMEM>>>();
    mix_kernel<<<dim3(128, NHEAD), 256, MIX_SMEM>>>();
    norm_kernel<<<NHEAD * NBLK, 128>>>();
    out_kernel<<<NHEAD * NBLK, 256, OUT2_SMEM>>>();

    dim3 go(DIMC / 128, MPAD / 128);
    gemm_out<<<go, 256, GEMM_SMEM>>>(bo, out);
}

// round 8
// speedup vs baseline: 4.6959x; 1.2291x over previous
#include <cuda_runtime.h>
#include <cuda_fp16.h>
#include <cstdint>
#include <cstdio>

// ---------------- problem dims (fixed) ----------------
#define NTOK   18000      // F*H*W = 12*30*50
#define MPAD   18048      // padded to multiple of 128
#define DIMC   1536
#define NHEAD  12
#define HDIM   128
#define NBLK   150        // FB*HB*WB = 3*5*10
#define PBLK   120        // P1*P2*P3 = 4*6*5
#define EPSF   1e-6f

typedef unsigned long long ull;

// ---------------- f32x2 helpers ----------------
__device__ __forceinline__ ull ffma2(ull a, ull b, ull c) {
    ull d;
    asm("fma.rn.f32x2 %0, %1, %2, %3;" : "=l"(d) : "l"(a), "l"(b), "l"(c));
    return d;
}
__device__ __forceinline__ ull pack2(float x, float y) {
    ull r;
    asm("mov.b64 %0, {%1, %2};" : "=l"(r) : "f"(x), "f"(y));
    return r;
}
__device__ __forceinline__ void unpack2(ull v, float& x, float& y) {
    asm("mov.b64 {%0, %1}, %2;" : "=f"(x), "=f"(y) : "l"(v));
}

// ---------------- mma / ldmatrix helpers ----------------
__device__ __forceinline__ uint32_t smem_u32(const void* p) {
    uint32_t a;
    asm("{ .reg .u64 t; cvta.to.shared.u64 t, %1; cvt.u32.u64 %0, t; }" : "=r"(a) : "l"(p));
    return a;
}
__device__ __forceinline__ void cp_async16(uint32_t dst, const void* src) {
    asm volatile("cp.async.cg.shared.global [%0], [%1], 16;" :: "r"(dst), "l"(src) : "memory");
}
__device__ __forceinline__ void ldm_x4(uint32_t* r, uint32_t addr) {
    asm volatile("ldmatrix.sync.aligned.m8n8.x4.shared.b16 {%0,%1,%2,%3}, [%4];"
                 : "=r"(r[0]), "=r"(r[1]), "=r"(r[2]), "=r"(r[3]) : "r"(addr));
}
__device__ __forceinline__ void ldm_x4_t(uint32_t* r, uint32_t addr) {
    asm volatile("ldmatrix.sync.aligned.m8n8.x4.trans.shared.b16 {%0,%1,%2,%3}, [%4];"
                 : "=r"(r[0]), "=r"(r[1]), "=r"(r[2]), "=r"(r[3]) : "r"(addr));
}
__device__ __forceinline__ void mma16816(float* c, const uint32_t* a, const uint32_t* b) {
    asm volatile("mma.sync.aligned.m16n8k16.row.col.f32.f16.f16.f32 "
                 "{%0,%1,%2,%3}, {%4,%5,%6,%7}, {%8,%9}, {%0,%1,%2,%3};"
                 : "+f"(c[0]), "+f"(c[1]), "+f"(c[2]), "+f"(c[3])
                 : "r"(a[0]), "r"(a[1]), "r"(a[2]), "r"(a[3]), "r"(b[0]), "r"(b[1]));
}
__device__ __forceinline__ uint32_t h2pack(float a, float b) {
    __half2 h = __floats2half2_rn(a, b);
    return *(uint32_t*)&h;
}
__device__ __forceinline__ uint32_t h2packlo(float a, float b, uint32_t hp) {
    __half2 h = *(__half2*)&hp;
    float2 hf = __half22float2(h);
    __half2 l = __floats2half2_rn(a - hf.x, b - hf.y);
    return *(uint32_t*)&l;
}

// ---------------- scratch ----------------
__device__ float Qbuf[NTOK * DIMC];      // pre-rope normed q (fp32, for qk)
__device__ float Kbuf[NTOK * DIMC];      // pre-rope normed k (fp32, for qk)
__device__ float KVbuf[NHEAD * NBLK * HDIM * HDIM];   // fp32 (mix input)
__device__ float QKbuf[NHEAD * NBLK * PBLK];
__device__ float NORMbuf[NHEAD * NBLK * PBLK];
__device__ float WBLKbuf[NBLK * NBLK];

// fp16 operand buffers
__device__ __half Xh[MPAD * DIMC];
__device__ __half AOh[MPAD * DIMC];      // zero-init; pad rows never written
__device__ __half Wh4[4][DIMC * DIMC];
__device__ __half Wl4[4][DIMC * DIMC];
__device__ __half Vh[NTOK * DIMC];
__device__ __half Vl[NTOK * DIMC];
__device__ __half QRh[NTOK * DIMC];
__device__ __half QRl[NTOK * DIMC];
__device__ __half KRh[NTOK * DIMC];
__device__ __half KRl[NTOK * DIMC];
__device__ __half KVMh[NHEAD * NBLK * HDIM * HDIM];
__device__ __half KVMl[NHEAD * NBLK * HDIM * HDIM];

__device__ __forceinline__ int tok_of(int nb, int p) {
    int fb = nb / 50, hb = (nb / 10) % 5, wb = nb % 10;
    int p1 = p / 30, p2 = (p / 5) % 6, p3 = p % 5;
    int f = fb * 4 + p1, h = hb * 6 + p2, w = wb * 5 + p3;
    return (f * 30 + h) * 50 + w;
}

// ---------------- W_BLK ----------------
__global__ void wblk_kernel() {
    int j = blockIdx.x;
    int i = threadIdx.x;
    __shared__ double ssum[256];
    double m = 0.0;
    if (i < NBLK) {
        int fi = i / 50, hi = (i / 10) % 5, wi = i % 10;
        int fj = j / 50, hj = (j / 10) % 5, wj = j % 10;
        double df = fi - fj, dh = hi - hj, dw = wi - wj;
        double d = sqrt(df * df + dh * dh + dw * dw);
        m = 1.0 - d / sqrt(101.0);
    }
    ssum[i] = m;
    __syncthreads();
    for (int s = 128; s > 0; s >>= 1) {
        if (i < s) ssum[i] += ssum[i + s];
        __syncthreads();
    }
    if (i < NBLK) WBLKbuf[i * NBLK + j] = (float)(m / ssum[0]);
}

// ---------------- fp32 -> fp16 ----------------
__global__ void conv_half(const float* __restrict__ src, __half* __restrict__ dst, int n, int ntot) {
    int i = blockIdx.x * 256 + threadIdx.x;
    if (i >= ntot) return;
    float v = (i < n) ? src[i] : 0.f;
    dst[i] = __float2half(v);
}

__global__ void conv_w4(const float* __restrict__ w0, const float* __restrict__ w1,
                        const float* __restrict__ w2, const float* __restrict__ w3) {
    int y = blockIdx.y;
    const float* src = (y == 0) ? w0 : (y == 1) ? w1 : (y == 2) ? w2 : w3;
    int i = blockIdx.x * 256 + threadIdx.x;
    float v = src[i];
    __half h = __float2half(v);
    Wh4[y][i] = h;
    Wl4[y][i] = __float2half(v - __half2float(h));
}

// ---------------- pipelined fp16 tensor-core GEMM (TP: 2-pass hi/lo or 1-pass) ----------------
#define KC      32
#define NCHUNK  (DIMC / KC)              // 48
#define TILEB   (128 * 64)               // 8192 B per operand tile
#define STAGEB  (3 * TILEB)              // 24576 B
#define NSTAGE  4
#define GEMM_SMEM (NSTAGE * STAGEB)      // 98304 B -> 2 CTAs/SM

template<bool TP>
__device__ __forceinline__ void gemm_core(
    const __half* __restrict__ A,
    const __half* __restrict__ Bhi, const __half* __restrict__ Blo,
    const float* __restrict__ bias, float* __restrict__ C,
    __half* __restrict__ VhOut, __half* __restrict__ VlOut, int M,
    int m0, int n0, uint32_t sb)
{
    int tid = threadIdx.x;
    int wid = tid >> 5, lane = tid & 31;
    int wm = (wid & 1) * 64;
    int wn = (wid >> 1) * 32;
    int lr = lane >> 2, lc = lane & 3;
    int q = lane >> 3, rr = lane & 7;

    int a_row = (q & 1) * 8 + rr;
    int a_seg0 = q >> 1;
    int b_row = (q >> 1) * 8 + rr;
    int b_seg0 = q & 1;
    int swA = (a_row >> 1) & 3;
    int swB = (b_row >> 1) & 3;
    uint32_t rowbA = (uint32_t)(wm + a_row) * 64;
    uint32_t rowbB = (uint32_t)(wn + b_row) * 64;

    float acc[4][4][4];
#pragma unroll
    for (int i = 0; i < 4; i++)
#pragma unroll
        for (int j = 0; j < 4; j++)
#pragma unroll
            for (int r = 0; r < 4; r++) acc[i][j][r] = 0.f;

    // hoisted loader addressing (constant per thread)
    const int NL = TP ? 6 : 4;
    const __half* gptr[6];
    uint32_t sof[6];
#pragma unroll
    for (int i = 0; i < 6; i++) {
        int idx = tid + i * 256;
        int t = idx >> 9, row = (idx >> 2) & 127, seg = idx & 3;
        const __half* g;
        if (t == 0)      g = A   + (size_t)(m0 + row) * DIMC + seg * 8;
        else if (t == 1) g = Bhi + (size_t)(n0 + row) * DIMC + seg * 8;
        else             g = Blo + (size_t)(n0 + row) * DIMC + seg * 8;
        gptr[i] = g;
        sof[i] = (uint32_t)(t * TILEB + row * 64 + ((seg ^ ((row >> 1) & 3)) * 16));
    }

    auto load_chunk = [&](int c, int st) {
        uint32_t sd = sb + st * STAGEB;
        size_t kof = (size_t)c * KC;
#pragma unroll
        for (int i = 0; i < NL; i++)
            cp_async16(sd + sof[i], gptr[i] + kof);
        asm volatile("cp.async.commit_group;" ::: "memory");
    };

    load_chunk(0, 0);
    load_chunk(1, 1);
    load_chunk(2, 2);
    for (int c = 0; c < NCHUNK; c++) {
        if (c < NCHUNK - 2)
            asm volatile("cp.async.wait_group 2;" ::: "memory");
        else if (c == NCHUNK - 2)
            asm volatile("cp.async.wait_group 1;" ::: "memory");
        else
            asm volatile("cp.async.wait_group 0;" ::: "memory");
        __syncthreads();
        uint32_t tb = sb + (c & 3) * STAGEB;
        uint32_t bA  = tb + rowbA;
        uint32_t bBh = tb + TILEB + rowbB;
        uint32_t bBl = tb + 2 * TILEB + rowbB;

        {
            uint32_t offA = (uint32_t)((a_seg0 ^ swA) * 16);
            uint32_t offB = (uint32_t)((b_seg0 ^ swB) * 16);
            uint32_t ah[4][4], bh[2][4], bl[2][4];
#pragma unroll
            for (int mt = 0; mt < 4; mt++)
                ldm_x4(ah[mt], bA + mt * 1024 + offA);
#pragma unroll
            for (int nt2 = 0; nt2 < 2; nt2++) {
                ldm_x4(bh[nt2], bBh + nt2 * 1024 + offB);
                if (TP) ldm_x4(bl[nt2], bBl + nt2 * 1024 + offB);
            }
#pragma unroll
            for (int mt = 0; mt < 4; mt++)
#pragma unroll
                for (int nt = 0; nt < 4; nt++) {
                    mma16816(acc[mt][nt], ah[mt], &bh[nt >> 1][(nt & 1) * 2]);
                    if (TP) mma16816(acc[mt][nt], ah[mt], &bl[nt >> 1][(nt & 1) * 2]);
                }
        }
        if (c + 3 < NCHUNK) load_chunk(c + 3, (c + 3) & 3);
        {
            uint32_t offA = (uint32_t)(((a_seg0 + 2) ^ swA) * 16);
            uint32_t offB = (uint32_t)(((b_seg0 + 2) ^ swB) * 16);
            uint32_t ah[4][4], bh[2][4], bl[2][4];
#pragma unroll
            for (int mt = 0; mt < 4; mt++)
                ldm_x4(ah[mt], bA + mt * 1024 + offA);
#pragma unroll
            for (int nt2 = 0; nt2 < 2; nt2++) {
                ldm_x4(bh[nt2], bBh + nt2 * 1024 + offB);
                if (TP) ldm_x4(bl[nt2], bBl + nt2 * 1024 + offB);
            }
#pragma unroll
            for (int mt = 0; mt < 4; mt++)
#pragma unroll
                for (int nt = 0; nt < 4; nt++) {
                    mma16816(acc[mt][nt], ah[mt], &bh[nt >> 1][(nt & 1) * 2]);
                    if (TP) mma16816(acc[mt][nt], ah[mt], &bl[nt >> 1][(nt & 1) * 2]);
                }
        }
    }

#pragma unroll
    for (int mt = 0; mt < 4; mt++) {
        int m = m0 + wm + mt * 16 + lr;
#pragma unroll
        for (int nt = 0; nt < 4; nt++) {
            int col = n0 + wn + nt * 8 + lc * 2;
            float bx = bias[col], by = bias[col + 1];
            if (VhOut) {
                if (m < M) {
                    float v0 = acc[mt][nt][0] + bx, v1 = acc[mt][nt][1] + by;
                    uint32_t hp = h2pack(v0, v1);
                    *(uint32_t*)(VhOut + (size_t)m * DIMC + col) = hp;
                    *(uint32_t*)(VlOut + (size_t)m * DIMC + col) = h2packlo(v0, v1, hp);
                }
                if (m + 8 < M) {
                    float v0 = acc[mt][nt][2] + bx, v1 = acc[mt][nt][3] + by;
                    uint32_t hp = h2pack(v0, v1);
                    *(uint32_t*)(VhOut + (size_t)(m + 8) * DIMC + col) = hp;
                    *(uint32_t*)(VlOut + (size_t)(m + 8) * DIMC + col) = h2packlo(v0, v1, hp);
                }
            } else {
                if (m < M) {
                    float2 v = make_float2(acc[mt][nt][0] + bx, acc[mt][nt][1] + by);
                    *(float2*)(C + (size_t)m * DIMC + col) = v;
                }
                if (m + 8 < M) {
                    float2 v = make_float2(acc[mt][nt][2] + bx, acc[mt][nt][3] + by);
                    *(float2*)(C + (size_t)(m + 8) * DIMC + col) = v;
                }
            }
        }
    }
}

__global__ __launch_bounds__(256, 2) void gemm_qkv(
    const float* __restrict__ bq, const float* __restrict__ bk, const float* __restrict__ bv)
{
    extern __shared__ __align__(16) char smem[];
    uint32_t sb = smem_u32(smem);
    int z = blockIdx.z;
    if (z == 2) {
        // V projection: 1-pass (weight-rounding error flows linearly; within budget)
        gemm_core<false>(Xh, Wh4[2], Wl4[2], bv, (float*)0, Vh, Vl, NTOK,
                         blockIdx.y * 128, blockIdx.x * 128, sb);
    } else {
        const float* bias = (z == 0) ? bq : bk;
        float* C = (z == 0) ? Qbuf : Kbuf;
        gemm_core<true>(Xh, Wh4[z], Wl4[z], bias, C, (__half*)0, (__half*)0, NTOK,
                        blockIdx.y * 128, blockIdx.x * 128, sb);
    }
}

__global__ __launch_bounds__(256, 2) void gemm_out(const float* __restrict__ bo, float* __restrict__ out)
{
    extern __shared__ __align__(16) char smem[];
    uint32_t sb = smem_u32(smem);
    // out projection: 1-pass
    gemm_core<false>(AOh, Wh4[3], Wl4[3], bo, out, (__half*)0, (__half*)0, NTOK,
                     blockIdx.y * 128, blockIdx.x * 128, sb);
}

// ---------------- fused rmsnorm + relu + eps + RoPE; fp16 hi/lo roped outputs ----------------
__global__ void rmsnorm_rope_kernel(const float* __restrict__ nqw, const float* __restrict__ nkw,
                                    const float* __restrict__ fc, const float* __restrict__ fs) {
    int n = blockIdx.x;
    bool isK = blockIdx.y;
    float* buf = isK ? Kbuf : Qbuf;
    __half* rh = isK ? KRh : QRh;
    __half* rl = isK ? KRl : QRl;
    const float* w = isK ? nkw : nqw;
    int tid = threadIdx.x;
    size_t base = (size_t)n * DIMC;
    float2* b2 = (float2*)(buf + base);
    const float2* w2 = (const float2*)w;

    int f = n / 1500, rem = n % 1500;
    int hh = rem / 50, ww = rem % 50;

    float2 v[3];
    float ss = 0.f;
#pragma unroll
    for (int t = 0; t < 3; t++) {
        v[t] = b2[tid + t * 256];
        ss += v[t].x * v[t].x + v[t].y * v[t].y;
    }
    for (int o = 16; o > 0; o >>= 1) ss += __shfl_xor_sync(0xffffffffu, ss, o);
    __shared__ float red[8];
    __shared__ float stot;
    if ((tid & 31) == 0) red[tid >> 5] = ss;
    __syncthreads();
    if (tid == 0) {
        float t = 0.f;
        for (int i = 0; i < 8; i++) t += red[i];
        stot = t;
    }
    __syncthreads();
    float sc = 1.0f / sqrtf(stot * (1.0f / DIMC) + EPSF);
#pragma unroll
    for (int t = 0; t < 3; t++) {
        int idx = tid + t * 256;
        float2 wv = w2[idx];
        float x0 = fmaxf(v[t].x * sc * wv.x, 0.f) + EPSF;
        float x1 = fmaxf(v[t].y * sc * wv.y, 0.f) + EPSF;
        b2[idx] = make_float2(x0, x1);
        int c = idx & 63;
        int pos = (c < 22) ? f : ((c < 43) ? hh : ww);
        float cs = fc[pos * 64 + c];
        float sn = fs[pos * 64 + c];
        float r0 = x0 * cs - x1 * sn;
        float r1 = x0 * sn + x1 * cs;
        uint32_t hp = h2pack(r0, r1);
        *(uint32_t*)(rh + base + 2 * idx) = hp;
        *(uint32_t*)(rl + base + 2 * idx) = h2packlo(r0, r1, hp);
    }
}

// ---------------- fused ksum + qk (fp32) ----------------
__global__ void qk_kernel() {
    int b = blockIdx.x;
    int hh = b / NBLK, nb = b % NBLK;
    int tid = threadIdx.x;
    __shared__ float ks[HDIM];
    float acc = 0.f;
    for (int p = 0; p < PBLK; p++) {
        int t = tok_of(nb, p);
        acc += Kbuf[(size_t)t * DIMC + hh * HDIM + tid];
    }
    ks[tid] = acc;
    __syncthreads();
    if (tid < PBLK) {
        int t = tok_of(nb, tid);
        const float* qp = Qbuf + (size_t)t * DIMC + hh * HDIM;
        float a = 0.f;
#pragma unroll 4
        for (int d = 0; d < HDIM; d++) a += qp[d] * ks[d];
        QKbuf[b * PBLK + tid] = a;
    }
}

// ---------------- kv: tensor-core fp16 3-pass;  KV[d,e] = sum_p KR[p,d]*V[p,e] ----------------
#define T2ST  136                       // halves per smem row (272 B, 4-bank rotation)
#define T2B   (128 * T2ST * 2)          // 34816 B per tile
#define KV2_SMEM (4 * T2B)              // 139264

__global__ __launch_bounds__(256) void kv_kernel() {
    extern __shared__ __align__(16) char smem[];
    uint32_t sb = smem_u32(smem);
    int b = blockIdx.x;
    int hh = b / NBLK, nb = b % NBLK;
    int tid = threadIdx.x;

    // zero k-pad rows 120..127 (first 256B of each row) in all 4 tiles
    for (int i = tid; i < 4 * 8 * 16; i += 256) {
        int t = i >> 7, r = (i >> 4) & 7, s = i & 15;
        *(uint4*)(smem + t * T2B + (120 + r) * (T2ST * 2) + s * 16) = make_uint4(0, 0, 0, 0);
    }
    // load tiles: 0=KRh 1=KRl 2=Vh 3=Vl; 1920 16B-segs each
#pragma unroll
    for (int i = 0; i < 30; i++) {
        int idx = tid + i * 256;
        int t = idx / 1920;
        int rem = idx - t * 1920;
        int row = rem >> 4, seg = rem & 15;
        int tok = tok_of(nb, row);
        const __half* g = (t == 0) ? KRh : (t == 1) ? KRl : (t == 2) ? Vh : Vl;
        g += (size_t)tok * DIMC + hh * HDIM + seg * 8;
        cp_async16(sb + t * T2B + row * (T2ST * 2) + seg * 16, g);
    }
    asm volatile("cp.async.commit_group;" ::: "memory");
    asm volatile("cp.async.wait_group 0;" ::: "memory");
    __syncthreads();

    int wid = tid >> 5, lane = tid & 31;
    int q = lane >> 3, rr = lane & 7;
    int wm = (wid & 3) * 32, wn = (wid >> 2) * 64;   // d, e
    uint32_t bKRh = sb, bKRl = sb + T2B, bVh = sb + 2 * T2B, bVl = sb + 3 * T2B;

    float acc[2][8][4];
#pragma unroll
    for (int i = 0; i < 2; i++)
#pragma unroll
        for (int j = 0; j < 8; j++)
#pragma unroll
            for (int r = 0; r < 4; r++) acc[i][j][r] = 0.f;

#pragma unroll
    for (int ks = 0; ks < 8; ks++) {
        int p0 = ks * 16;
        uint32_t ah[2][4], al[2][4], bh[4][4], bl[4][4];
#pragma unroll
        for (int mt = 0; mt < 2; mt++) {
            int d0 = wm + mt * 16;
            uint32_t ad = (uint32_t)((p0 + (q >> 1) * 8 + rr) * T2ST + d0 + (q & 1) * 8) * 2;
            ldm_x4_t(ah[mt], bKRh + ad);
            ldm_x4_t(al[mt], bKRl + ad);
        }
#pragma unroll
        for (int nt2 = 0; nt2 < 4; nt2++) {
            int e0 = wn + nt2 * 16;
            uint32_t bd = (uint32_t)((p0 + (q & 1) * 8 + rr) * T2ST + e0 + (q >> 1) * 8) * 2;
            ldm_x4_t(bh[nt2], bVh + bd);
            ldm_x4_t(bl[nt2], bVl + bd);
        }
#pragma unroll
        for (int mt = 0; mt < 2; mt++)
#pragma unroll
            for (int nt = 0; nt < 8; nt++) {
                const uint32_t* pbh = &bh[nt >> 1][(nt & 1) * 2];
                const uint32_t* pbl = &bl[nt >> 1][(nt & 1) * 2];
                mma16816(acc[mt][nt], ah[mt], pbh);
                mma16816(acc[mt][nt], ah[mt], pbl);
                mma16816(acc[mt][nt], al[mt], pbh);
            }
    }

    int lr = lane >> 2, lc = lane & 3;
    float* dst = KVbuf + (size_t)b * HDIM * HDIM;
#pragma unroll
    for (int mt = 0; mt < 2; mt++) {
        int d = wm + mt * 16 + lr;
#pragma unroll
        for (int nt = 0; nt < 8; nt++) {
            int e = wn + nt * 8 + lc * 2;
            *(float2*)(dst + d * HDIM + e) = make_float2(acc[mt][nt][0], acc[mt][nt][1]);
            *(float2*)(dst + (d + 8) * HDIM + e) = make_float2(acc[mt][nt][2], acc[mt][nt][3]);
        }
    }
}

// ---------------- mix (fp32 f32x2), writes fp16 hi/lo ----------------
__global__ __launch_bounds__(256) void mix_kernel() {
    extern __shared__ __align__(16) float sm[];
    float* Ws = sm;
    float* tB = sm + NBLK * NBLK;
    int hh = blockIdx.y, xt = blockIdx.x;
    int tid = threadIdx.x;
    for (int idx = tid; idx < NBLK * NBLK; idx += 256) Ws[idx] = WBLKbuf[idx];
    const float* src = KVbuf + (size_t)hh * NBLK * HDIM * HDIM + xt * 128;
    for (int idx = tid; idx < NBLK * 128; idx += 256) {
        int i = idx >> 7, c = idx & 127;
        tB[idx] = src[(size_t)i * HDIM * HDIM + c];
    }
    __syncthreads();
    int tx = tid & 15, ty = tid >> 4;
    ull acc[10][4];
#pragma unroll
    for (int oo = 0; oo < 10; oo++)
#pragma unroll
        for (int jj = 0; jj < 4; jj++) acc[oo][jj] = 0ULL;
    for (int i = 0; i < NBLK; i++) {
        ulonglong2 b1 = *(const ulonglong2*)&tB[i * 128 + tx * 8];
        ulonglong2 b2 = *(const ulonglong2*)&tB[i * 128 + tx * 8 + 4];
        ull bb0 = b1.x, bb1 = b1.y, bb2 = b2.x, bb3 = b2.y;
#pragma unroll
        for (int oo = 0; oo < 10; oo++) {
            int o = ty + 16 * oo;
            if (o < NBLK) {
                float w = Ws[o * NBLK + i];
                ull w2 = pack2(w, w);
                acc[oo][0] = ffma2(w2, bb0, acc[oo][0]);
                acc[oo][1] = ffma2(w2, bb1, acc[oo][1]);
                acc[oo][2] = ffma2(w2, bb2, acc[oo][2]);
                acc[oo][3] = ffma2(w2, bb3, acc[oo][3]);
            }
        }
    }
#pragma unroll
    for (int oo = 0; oo < 10; oo++) {
        int o = ty + 16 * oo;
        if (o < NBLK) {
            size_t gb = ((size_t)hh * NBLK + o) * HDIM * HDIM + xt * 128 + tx * 8;
#pragma unroll
            for (int jj = 0; jj < 4; jj++) {
                float v0x, v1x;
                unpack2(acc[oo][jj], v0x, v1x);
                uint32_t hp = h2pack(v0x, v1x);
                *(uint32_t*)(KVMh + gb + 2 * jj) = hp;
                *(uint32_t*)(KVMl + gb + 2 * jj) = h2packlo(v0x, v1x, hp);
            }
        }
    }
}

// ---------------- norm ----------------
__global__ void norm_kernel() {
    int b = blockIdx.x;
    int hh = b / NBLK, o = b % NBLK;
    int p = threadIdx.x;
    if (p >= PBLK) return;
    float acc = EPSF;
    for (int i = 0; i < NBLK; i++)
        acc += WBLKbuf[o * NBLK + i] * QKbuf[(hh * NBLK + i) * PBLK + p];
    NORMbuf[b * PBLK + p] = acc;
}

// ---------------- out: tc fp16 3-pass; C[p,e] = sum_d QR[p,d]*KVM[d,e]; /norm -> AOh ----------------
#define OUT2_SMEM (4 * T2B)

__global__ __launch_bounds__(256) void out_kernel() {
    extern __shared__ __align__(16) char smem[];
    uint32_t sb = smem_u32(smem);
    int b = blockIdx.x;
    int hh = b / NBLK, nb = b % NBLK;
    int tid = threadIdx.x;

#pragma unroll
    for (int i = 0; i < 31; i++) {
        int idx = tid + i * 256;
        if (idx < 3840) {
            int t = idx / 1920;
            int rem = idx - t * 1920;
            int row = rem >> 4, seg = rem & 15;
            int tok = tok_of(nb, row);
            const __half* g = (t == 0) ? QRh : QRl;
            g += (size_t)tok * DIMC + hh * HDIM + seg * 8;
            cp_async16(sb + t * T2B + row * (T2ST * 2) + seg * 16, g);
        } else {
            int idx2 = idx - 3840;
            int t = idx2 >> 11;
            int rem = idx2 & 2047;
            int row = rem >> 4, seg = rem & 15;
            const __half* g = (t == 0) ? KVMh : KVMl;
            g += (size_t)b * HDIM * HDIM + row * HDIM + seg * 8;
            cp_async16(sb + (2 + t) * T2B + row * (T2ST * 2) + seg * 16, g);
        }
    }
    asm volatile("cp.async.commit_group;" ::: "memory");
    asm volatile("cp.async.wait_group 0;" ::: "memory");
    __syncthreads();

    int wid = tid >> 5, lane = tid & 31;
    int q = lane >> 3, rr = lane & 7;
    int wm = (wid & 1) * 64, wn = (wid >> 1) * 32;   // p, e
    uint32_t bQh = sb, bQl = sb + T2B, bMh = sb + 2 * T2B, bMl = sb + 3 * T2B;

    float acc[4][4][4];
#pragma unroll
    for (int i = 0; i < 4; i++)
#pragma unroll
        for (int j = 0; j < 4; j++)
#pragma unroll
            for (int r = 0; r < 4; r++) acc[i][j][r] = 0.f;

#pragma unroll
    for (int ks = 0; ks < 8; ks++) {
        int d0 = ks * 16;
        uint32_t ah[4][4], al[4][4], bh[2][4], bl[2][4];
#pragma unroll
        for (int mt = 0; mt < 4; mt++) {
            int m0 = wm + mt * 16;
            uint32_t ad = (uint32_t)((m0 + (q & 1) * 8 + rr) * T2ST + d0 + (q >> 1) * 8) * 2;
            ldm_x4(ah[mt], bQh + ad);
            ldm_x4(al[mt], bQl + ad);
        }
#pragma unroll
        for (int nt2 = 0; nt2 < 2; nt2++) {
            int e0 = wn + nt2 * 16;
            uint32_t bd = (uint32_t)((d0 + (q & 1) * 8 + rr) * T2ST + e0 + (q >> 1) * 8) * 2;
            ldm_x4_t(bh[nt2], bMh + bd);
            ldm_x4_t(bl[nt2], bMl + bd);
        }
#pragma unroll
        for (int mt = 0; mt < 4; mt++)
#pragma unroll
            for (int nt = 0; nt < 4; nt++) {
                const uint32_t* pbh = &bh[nt >> 1][(nt & 1) * 2];
                const uint32_t* pbl = &bl[nt >> 1][(nt & 1) * 2];
                mma16816(acc[mt][nt], ah[mt], pbh);
                mma16816(acc[mt][nt], ah[mt], pbl);
                mma16816(acc[mt][nt], al[mt], pbh);
            }
    }

    int lr = lane >> 2, lc = lane & 3;
#pragma unroll
    for (int mt = 0; mt < 4; mt++) {
        int p = wm + mt * 16 + lr;
#pragma unroll
        for (int half = 0; half < 2; half++) {
            int pp = p + half * 8;
            if (pp < PBLK) {
                float inv = 1.0f / NORMbuf[b * PBLK + pp];
                int tok = tok_of(nb, pp);
                size_t gb = (size_t)tok * DIMC + hh * HDIM;
#pragma unroll
                for (int nt = 0; nt < 4; nt++) {
                    int e = wn + nt * 8 + lc * 2;
                    float v0 = acc[mt][nt][2 * half]     * inv;
                    float v1 = acc[mt][nt][2 * half + 1] * inv;
                    *(uint32_t*)(AOh + gb + e) = h2pack(v0, v1);
                }
            }
        }
    }
}

// ---------------- launch ----------------
extern "C" void kernel_launch(void* const* d_in, const int* in_sizes, int n_in,
                              void* d_out, int out_size) {
    const float* x   = (const float*)d_in[0];
    const float* fc  = (const float*)d_in[3];
    const float* fs  = (const float*)d_in[4];
    const float* wq  = (const float*)d_in[5];
    const float* bq  = (const float*)d_in[6];
    const float* wk  = (const float*)d_in[7];
    const float* bk  = (const float*)d_in[8];
    const float* wv  = (const float*)d_in[9];
    const float* bv  = (const float*)d_in[10];
    const float* wo  = (const float*)d_in[11];
    const float* bo  = (const float*)d_in[12];
    const float* nqw = (const float*)d_in[13];
    const float* nkw = (const float*)d_in[14];
    float* out = (float*)d_out;

    void* pxh;
    cudaGetSymbolAddress(&pxh, Xh);

    const int MIX_SMEM = (NBLK * NBLK + NBLK * 128) * 4;
    cudaFuncSetAttribute(gemm_qkv,  cudaFuncAttributeMaxDynamicSharedMemorySize, GEMM_SMEM);
    cudaFuncSetAttribute(gemm_out,  cudaFuncAttributeMaxDynamicSharedMemorySize, GEMM_SMEM);
    cudaFuncSetAttribute(kv_kernel, cudaFuncAttributeMaxDynamicSharedMemorySize, KV2_SMEM);
    cudaFuncSetAttribute(mix_kernel, cudaFuncAttributeMaxDynamicSharedMemorySize, MIX_SMEM);
    cudaFuncSetAttribute(out_kernel, cudaFuncAttributeMaxDynamicSharedMemorySize, OUT2_SMEM);

    wblk_kernel<<<NBLK, 256>>>();
    conv_half<<<(MPAD * DIMC) / 256, 256>>>(x, (__half*)pxh, NTOK * DIMC, MPAD * DIMC);
    conv_w4<<<dim3((DIMC * DIMC) / 256, 4), 256>>>(wq, wk, wv, wo);

    dim3 gg(DIMC / 128, MPAD / 128, 3);
    gemm_qkv<<<gg, 256, GEMM_SMEM>>>(bq, bk, bv);

    rmsnorm_rope_kernel<<<dim3(NTOK, 2), 256>>>(nqw, nkw, fc, fs);

    qk_kernel<<<NHEAD * NBLK, HDIM>>>();
    kv_kernel<<<NHEAD * NBLK, 256, KV2_SMEM>>>();
    mix_kernel<<<dim3(128, NHEAD), 256, MIX_SMEM>>>();
    norm_kernel<<<NHEAD * NBLK, 128>>>();
    out_kernel<<<NHEAD * NBLK, 256, OUT2_SMEM>>>();

    dim3 go(DIMC / 128, MPAD / 128);
    gemm_out<<<go, 256, GEMM_SMEM>>>(bo, out);
}

// round 9
// speedup vs baseline: 5.5602x; 1.1840x over previous
#include <cuda_runtime.h>
#include <cuda_fp16.h>
#include <cstdint>
#include <cstdio>

// ---------------- problem dims (fixed) ----------------
#define NTOK   18000      // F*H*W = 12*30*50
#define MPAD   18048      // padded to multiple of 128
#define DIMC   1536
#define NHEAD  12
#define HDIM   128
#define NBLK   150        // FB*HB*WB = 3*5*10
#define PBLK   120        // P1*P2*P3 = 4*6*5
#define EPSF   1e-6f

typedef unsigned long long ull;

// ---------------- f32x2 helpers ----------------
__device__ __forceinline__ ull ffma2(ull a, ull b, ull c) {
    ull d;
    asm("fma.rn.f32x2 %0, %1, %2, %3;" : "=l"(d) : "l"(a), "l"(b), "l"(c));
    return d;
}
__device__ __forceinline__ ull pack2(float x, float y) {
    ull r;
    asm("mov.b64 %0, {%1, %2};" : "=l"(r) : "f"(x), "f"(y));
    return r;
}
__device__ __forceinline__ void unpack2(ull v, float& x, float& y) {
    asm("mov.b64 {%0, %1}, %2;" : "=f"(x), "=f"(y) : "l"(v));
}

// ---------------- mma / ldmatrix helpers ----------------
__device__ __forceinline__ uint32_t smem_u32(const void* p) {
    uint32_t a;
    asm("{ .reg .u64 t; cvta.to.shared.u64 t, %1; cvt.u32.u64 %0, t; }" : "=r"(a) : "l"(p));
    return a;
}
__device__ __forceinline__ void cp_async16(uint32_t dst, const void* src) {
    asm volatile("cp.async.cg.shared.global [%0], [%1], 16;" :: "r"(dst), "l"(src) : "memory");
}
__device__ __forceinline__ void ldm_x4(uint32_t* r, uint32_t addr) {
    asm volatile("ldmatrix.sync.aligned.m8n8.x4.shared.b16 {%0,%1,%2,%3}, [%4];"
                 : "=r"(r[0]), "=r"(r[1]), "=r"(r[2]), "=r"(r[3]) : "r"(addr));
}
__device__ __forceinline__ void ldm_x4_t(uint32_t* r, uint32_t addr) {
    asm volatile("ldmatrix.sync.aligned.m8n8.x4.trans.shared.b16 {%0,%1,%2,%3}, [%4];"
                 : "=r"(r[0]), "=r"(r[1]), "=r"(r[2]), "=r"(r[3]) : "r"(addr));
}
__device__ __forceinline__ void mma16816(float* c, const uint32_t* a, const uint32_t* b) {
    asm volatile("mma.sync.aligned.m16n8k16.row.col.f32.f16.f16.f32 "
                 "{%0,%1,%2,%3}, {%4,%5,%6,%7}, {%8,%9}, {%0,%1,%2,%3};"
                 : "+f"(c[0]), "+f"(c[1]), "+f"(c[2]), "+f"(c[3])
                 : "r"(a[0]), "r"(a[1]), "r"(a[2]), "r"(a[3]), "r"(b[0]), "r"(b[1]));
}
__device__ __forceinline__ uint32_t h2pack(float a, float b) {
    __half2 h = __floats2half2_rn(a, b);
    return *(uint32_t*)&h;
}
__device__ __forceinline__ uint32_t h2packlo(float a, float b, uint32_t hp) {
    __half2 h = *(__half2*)&hp;
    float2 hf = __half22float2(h);
    __half2 l = __floats2half2_rn(a - hf.x, b - hf.y);
    return *(uint32_t*)&l;
}

// ---------------- scratch ----------------
__device__ float Qbuf[NTOK * DIMC];      // pre-rope normed q (fp32, for qk)
__device__ float Kbuf[NTOK * DIMC];      // pre-rope normed k (fp32, for qk)
__device__ float KVbuf[NHEAD * NBLK * HDIM * HDIM];   // fp32 (mix input)
__device__ float QKbuf[NHEAD * NBLK * PBLK];
__device__ float NORMbuf[NHEAD * NBLK * PBLK];
__device__ float WBLKbuf[NBLK * NBLK];

// fp16 operand buffers
__device__ __half Xh[MPAD * DIMC];
__device__ __half AOh[MPAD * DIMC];      // zero-init; pad rows never written
__device__ __half Wh4[4][DIMC * DIMC];
__device__ __half Vh[NTOK * DIMC];
__device__ __half Vl[NTOK * DIMC];
__device__ __half QRh[NTOK * DIMC];
__device__ __half QRl[NTOK * DIMC];
__device__ __half KRh[NTOK * DIMC];
__device__ __half KRl[NTOK * DIMC];
__device__ __half KVMh[NHEAD * NBLK * HDIM * HDIM];
__device__ __half KVMl[NHEAD * NBLK * HDIM * HDIM];

__device__ __forceinline__ int tok_of(int nb, int p) {
    int fb = nb / 50, hb = (nb / 10) % 5, wb = nb % 10;
    int p1 = p / 30, p2 = (p / 5) % 6, p3 = p % 5;
    int f = fb * 4 + p1, h = hb * 6 + p2, w = wb * 5 + p3;
    return (f * 30 + h) * 50 + w;
}

// ---------------- W_BLK ----------------
__global__ void wblk_kernel() {
    int j = blockIdx.x;
    int i = threadIdx.x;
    __shared__ double ssum[256];
    double m = 0.0;
    if (i < NBLK) {
        int fi = i / 50, hi = (i / 10) % 5, wi = i % 10;
        int fj = j / 50, hj = (j / 10) % 5, wj = j % 10;
        double df = fi - fj, dh = hi - hj, dw = wi - wj;
        double d = sqrt(df * df + dh * dh + dw * dw);
        m = 1.0 - d / sqrt(101.0);
    }
    ssum[i] = m;
    __syncthreads();
    for (int s = 128; s > 0; s >>= 1) {
        if (i < s) ssum[i] += ssum[i + s];
        __syncthreads();
    }
    if (i < NBLK) WBLKbuf[i * NBLK + j] = (float)(m / ssum[0]);
}

// ---------------- fp32 -> fp16 ----------------
__global__ void conv_half(const float* __restrict__ src, __half* __restrict__ dst, int n, int ntot) {
    int i = blockIdx.x * 256 + threadIdx.x;
    if (i >= ntot) return;
    float v = (i < n) ? src[i] : 0.f;
    dst[i] = __float2half(v);
}

__global__ void conv_w4(const float* __restrict__ w0, const float* __restrict__ w1,
                        const float* __restrict__ w2, const float* __restrict__ w3) {
    int y = blockIdx.y;
    const float* src = (y == 0) ? w0 : (y == 1) ? w1 : (y == 2) ? w2 : w3;
    int i = blockIdx.x * 256 + threadIdx.x;
    Wh4[y][i] = __float2half(src[i]);
}

// ---------------- pipelined fp16 1-pass tensor-core GEMM ----------------
#define KC      32
#define NCHUNK  (DIMC / KC)              // 48
#define TILEB   (128 * 64)               // 8192 B per operand tile
#define STAGEB  (2 * TILEB)              // 16384 B (A, B)
#define NSTAGE  4
#define GEMM_SMEM (NSTAGE * STAGEB)      // 65536 B -> 2 CTAs/SM

__device__ __forceinline__ void gemm_core(
    const __half* __restrict__ A, const __half* __restrict__ B,
    const float* __restrict__ bias, float* __restrict__ C,
    __half* __restrict__ VhOut, __half* __restrict__ VlOut, int M,
    int m0, int n0, uint32_t sb)
{
    int tid = threadIdx.x;
    int wid = tid >> 5, lane = tid & 31;
    int wm = (wid & 1) * 64;
    int wn = (wid >> 1) * 32;
    int lr = lane >> 2, lc = lane & 3;
    int q = lane >> 3, rr = lane & 7;

    int a_row = (q & 1) * 8 + rr;
    int a_seg0 = q >> 1;
    int b_row = (q >> 1) * 8 + rr;
    int b_seg0 = q & 1;
    int swA = (a_row >> 1) & 3;
    int swB = (b_row >> 1) & 3;
    uint32_t rowbA = (uint32_t)(wm + a_row) * 64;
    uint32_t rowbB = (uint32_t)(wn + b_row) * 64;

    float acc[4][4][4];
#pragma unroll
    for (int i = 0; i < 4; i++)
#pragma unroll
        for (int j = 0; j < 4; j++)
#pragma unroll
            for (int r = 0; r < 4; r++) acc[i][j][r] = 0.f;

    // hoisted loader addressing (constant per thread); 1024 segs -> 4/thread
    const __half* gptr[4];
    uint32_t sof[4];
#pragma unroll
    for (int i = 0; i < 4; i++) {
        int idx = tid + i * 256;
        int t = idx >> 9, row = (idx >> 2) & 127, seg = idx & 3;
        const __half* g = (t == 0) ? (A + (size_t)(m0 + row) * DIMC + seg * 8)
                                   : (B + (size_t)(n0 + row) * DIMC + seg * 8);
        gptr[i] = g;
        sof[i] = (uint32_t)(t * TILEB + row * 64 + ((seg ^ ((row >> 1) & 3)) * 16));
    }

    auto load_chunk = [&](int c, int st) {
        uint32_t sd = sb + st * STAGEB;
        size_t kof = (size_t)c * KC;
#pragma unroll
        for (int i = 0; i < 4; i++)
            cp_async16(sd + sof[i], gptr[i] + kof);
        asm volatile("cp.async.commit_group;" ::: "memory");
    };

    load_chunk(0, 0);
    load_chunk(1, 1);
    load_chunk(2, 2);
    for (int c = 0; c < NCHUNK; c++) {
        if (c < NCHUNK - 2)
            asm volatile("cp.async.wait_group 2;" ::: "memory");
        else if (c == NCHUNK - 2)
            asm volatile("cp.async.wait_group 1;" ::: "memory");
        else
            asm volatile("cp.async.wait_group 0;" ::: "memory");
        __syncthreads();
        uint32_t tb = sb + (c & 3) * STAGEB;
        uint32_t bA = tb + rowbA;
        uint32_t bB = tb + TILEB + rowbB;

        {
            uint32_t offA = (uint32_t)((a_seg0 ^ swA) * 16);
            uint32_t offB = (uint32_t)((b_seg0 ^ swB) * 16);
            uint32_t ah[4][4], bh[2][4];
#pragma unroll
            for (int mt = 0; mt < 4; mt++)
                ldm_x4(ah[mt], bA + mt * 1024 + offA);
#pragma unroll
            for (int nt2 = 0; nt2 < 2; nt2++)
                ldm_x4(bh[nt2], bB + nt2 * 1024 + offB);
#pragma unroll
            for (int mt = 0; mt < 4; mt++)
#pragma unroll
                for (int nt = 0; nt < 4; nt++)
                    mma16816(acc[mt][nt], ah[mt], &bh[nt >> 1][(nt & 1) * 2]);
        }
        if (c + 3 < NCHUNK) load_chunk(c + 3, (c + 3) & 3);
        {
            uint32_t offA = (uint32_t)(((a_seg0 + 2) ^ swA) * 16);
            uint32_t offB = (uint32_t)(((b_seg0 + 2) ^ swB) * 16);
            uint32_t ah[4][4], bh[2][4];
#pragma unroll
            for (int mt = 0; mt < 4; mt++)
                ldm_x4(ah[mt], bA + mt * 1024 + offA);
#pragma unroll
            for (int nt2 = 0; nt2 < 2; nt2++)
                ldm_x4(bh[nt2], bB + nt2 * 1024 + offB);
#pragma unroll
            for (int mt = 0; mt < 4; mt++)
#pragma unroll
                for (int nt = 0; nt < 4; nt++)
                    mma16816(acc[mt][nt], ah[mt], &bh[nt >> 1][(nt & 1) * 2]);
        }
    }

#pragma unroll
    for (int mt = 0; mt < 4; mt++) {
        int m = m0 + wm + mt * 16 + lr;
#pragma unroll
        for (int nt = 0; nt < 4; nt++) {
            int col = n0 + wn + nt * 8 + lc * 2;
            float bx = bias[col], by = bias[col + 1];
            if (VhOut) {
                if (m < M) {
                    float v0 = acc[mt][nt][0] + bx, v1 = acc[mt][nt][1] + by;
                    uint32_t hp = h2pack(v0, v1);
                    *(uint32_t*)(VhOut + (size_t)m * DIMC + col) = hp;
                    *(uint32_t*)(VlOut + (size_t)m * DIMC + col) = h2packlo(v0, v1, hp);
                }
                if (m + 8 < M) {
                    float v0 = acc[mt][nt][2] + bx, v1 = acc[mt][nt][3] + by;
                    uint32_t hp = h2pack(v0, v1);
                    *(uint32_t*)(VhOut + (size_t)(m + 8) * DIMC + col) = hp;
                    *(uint32_t*)(VlOut + (size_t)(m + 8) * DIMC + col) = h2packlo(v0, v1, hp);
                }
            } else {
                if (m < M) {
                    float2 v = make_float2(acc[mt][nt][0] + bx, acc[mt][nt][1] + by);
                    *(float2*)(C + (size_t)m * DIMC + col) = v;
                }
                if (m + 8 < M) {
                    float2 v = make_float2(acc[mt][nt][2] + bx, acc[mt][nt][3] + by);
                    *(float2*)(C + (size_t)(m + 8) * DIMC + col) = v;
                }
            }
        }
    }
}

__global__ __launch_bounds__(256, 2) void gemm_qkv(
    const float* __restrict__ bq, const float* __restrict__ bk, const float* __restrict__ bv)
{
    extern __shared__ __align__(16) char smem[];
    uint32_t sb = smem_u32(smem);
    int z = blockIdx.z;
    if (z == 2) {
        gemm_core(Xh, Wh4[2], bv, (float*)0, Vh, Vl, NTOK,
                  blockIdx.y * 128, blockIdx.x * 128, sb);
    } else {
        const float* bias = (z == 0) ? bq : bk;
        float* C = (z == 0) ? Qbuf : Kbuf;
        gemm_core(Xh, Wh4[z], bias, C, (__half*)0, (__half*)0, NTOK,
                  blockIdx.y * 128, blockIdx.x * 128, sb);
    }
}

__global__ __launch_bounds__(256, 2) void gemm_out(const float* __restrict__ bo, float* __restrict__ out)
{
    extern __shared__ __align__(16) char smem[];
    uint32_t sb = smem_u32(smem);
    gemm_core(AOh, Wh4[3], bo, out, (__half*)0, (__half*)0, NTOK,
              blockIdx.y * 128, blockIdx.x * 128, sb);
}

// ---------------- fused rmsnorm + relu + eps + RoPE; fp16 hi/lo roped outputs ----------------
__global__ void rmsnorm_rope_kernel(const float* __restrict__ nqw, const float* __restrict__ nkw,
                                    const float* __restrict__ fc, const float* __restrict__ fs) {
    int n = blockIdx.x;
    bool isK = blockIdx.y;
    float* buf = isK ? Kbuf : Qbuf;
    __half* rh = isK ? KRh : QRh;
    __half* rl = isK ? KRl : QRl;
    const float* w = isK ? nkw : nqw;
    int tid = threadIdx.x;
    size_t base = (size_t)n * DIMC;
    float2* b2 = (float2*)(buf + base);
    const float2* w2 = (const float2*)w;

    int f = n / 1500, rem = n % 1500;
    int hh = rem / 50, ww = rem % 50;

    float2 v[3];
    float ss = 0.f;
#pragma unroll
    for (int t = 0; t < 3; t++) {
        v[t] = b2[tid + t * 256];
        ss += v[t].x * v[t].x + v[t].y * v[t].y;
    }
    for (int o = 16; o > 0; o >>= 1) ss += __shfl_xor_sync(0xffffffffu, ss, o);
    __shared__ float red[8];
    __shared__ float stot;
    if ((tid & 31) == 0) red[tid >> 5] = ss;
    __syncthreads();
    if (tid == 0) {
        float t = 0.f;
        for (int i = 0; i < 8; i++) t += red[i];
        stot = t;
    }
    __syncthreads();
    float sc = 1.0f / sqrtf(stot * (1.0f / DIMC) + EPSF);
#pragma unroll
    for (int t = 0; t < 3; t++) {
        int idx = tid + t * 256;
        float2 wv = w2[idx];
        float x0 = fmaxf(v[t].x * sc * wv.x, 0.f) + EPSF;
        float x1 = fmaxf(v[t].y * sc * wv.y, 0.f) + EPSF;
        b2[idx] = make_float2(x0, x1);
        int c = idx & 63;
        int pos = (c < 22) ? f : ((c < 43) ? hh : ww);
        float cs = fc[pos * 64 + c];
        float sn = fs[pos * 64 + c];
        float r0 = x0 * cs - x1 * sn;
        float r1 = x0 * sn + x1 * cs;
        uint32_t hp = h2pack(r0, r1);
        *(uint32_t*)(rh + base + 2 * idx) = hp;
        *(uint32_t*)(rl + base + 2 * idx) = h2packlo(r0, r1, hp);
    }
}

// ---------------- fused ksum + qk (fp32) ----------------
__global__ void qk_kernel() {
    int b = blockIdx.x;
    int hh = b / NBLK, nb = b % NBLK;
    int tid = threadIdx.x;
    __shared__ float ks[HDIM];
    float acc = 0.f;
    for (int p = 0; p < PBLK; p++) {
        int t = tok_of(nb, p);
        acc += Kbuf[(size_t)t * DIMC + hh * HDIM + tid];
    }
    ks[tid] = acc;
    __syncthreads();
    if (tid < PBLK) {
        int t = tok_of(nb, tid);
        const float* qp = Qbuf + (size_t)t * DIMC + hh * HDIM;
        float a = 0.f;
#pragma unroll 4
        for (int d = 0; d < HDIM; d++) a += qp[d] * ks[d];
        QKbuf[b * PBLK + tid] = a;
    }
}

// ---------------- kv: tensor-core fp16 3-pass;  KV[d,e] = sum_p KR[p,d]*V[p,e] ----------------
#define T2ST  136                       // halves per smem row (272 B, 4-bank rotation)
#define T2B   (128 * T2ST * 2)          // 34816 B per tile
#define KV2_SMEM (4 * T2B)              // 139264

__global__ __launch_bounds__(256) void kv_kernel() {
    extern __shared__ __align__(16) char smem[];
    uint32_t sb = smem_u32(smem);
    int b = blockIdx.x;
    int hh = b / NBLK, nb = b % NBLK;
    int tid = threadIdx.x;

    // zero k-pad rows 120..127 (first 256B of each row) in all 4 tiles
    for (int i = tid; i < 4 * 8 * 16; i += 256) {
        int t = i >> 7, r = (i >> 4) & 7, s = i & 15;
        *(uint4*)(smem + t * T2B + (120 + r) * (T2ST * 2) + s * 16) = make_uint4(0, 0, 0, 0);
    }
    // group A: rows 0..63 of all 4 tiles (4096 segs -> 16/thread)
#pragma unroll
    for (int i = 0; i < 16; i++) {
        int idx = tid + i * 256;
        int t = idx >> 10;
        int rem = idx & 1023;
        int row = rem >> 4, seg = rem & 15;
        int tok = tok_of(nb, row);
        const __half* g = (t == 0) ? KRh : (t == 1) ? KRl : (t == 2) ? Vh : Vl;
        g += (size_t)tok * DIMC + hh * HDIM + seg * 8;
        cp_async16(sb + t * T2B + row * (T2ST * 2) + seg * 16, g);
    }
    asm volatile("cp.async.commit_group;" ::: "memory");
    // group B: rows 64..119 (4 * 56 * 16 = 3584 segs -> 14/thread)
#pragma unroll
    for (int i = 0; i < 14; i++) {
        int idx = tid + i * 256;
        int t = idx / 896;
        int rem = idx - t * 896;
        int row = 64 + (rem >> 4), seg = rem & 15;
        int tok = tok_of(nb, row);
        const __half* g = (t == 0) ? KRh : (t == 1) ? KRl : (t == 2) ? Vh : Vl;
        g += (size_t)tok * DIMC + hh * HDIM + seg * 8;
        cp_async16(sb + t * T2B + row * (T2ST * 2) + seg * 16, g);
    }
    asm volatile("cp.async.commit_group;" ::: "memory");

    int wid = tid >> 5, lane = tid & 31;
    int q = lane >> 3, rr = lane & 7;
    int wm = (wid & 3) * 32, wn = (wid >> 2) * 64;   // d, e
    uint32_t bKRh = sb, bKRl = sb + T2B, bVh = sb + 2 * T2B, bVl = sb + 3 * T2B;

    float acc[2][8][4];
#pragma unroll
    for (int i = 0; i < 2; i++)
#pragma unroll
        for (int j = 0; j < 8; j++)
#pragma unroll
            for (int r = 0; r < 4; r++) acc[i][j][r] = 0.f;

    asm volatile("cp.async.wait_group 1;" ::: "memory");
    __syncthreads();

#pragma unroll
    for (int ks = 0; ks < 8; ks++) {
        if (ks == 4) {
            asm volatile("cp.async.wait_group 0;" ::: "memory");
            __syncthreads();
        }
        int p0 = ks * 16;
        uint32_t ah[2][4], al[2][4], bh[4][4], bl[4][4];
#pragma unroll
        for (int mt = 0; mt < 2; mt++) {
            int d0 = wm + mt * 16;
            uint32_t ad = (uint32_t)((p0 + (q >> 1) * 8 + rr) * T2ST + d0 + (q & 1) * 8) * 2;
            ldm_x4_t(ah[mt], bKRh + ad);
            ldm_x4_t(al[mt], bKRl + ad);
        }
#pragma unroll
        for (int nt2 = 0; nt2 < 4; nt2++) {
            int e0 = wn + nt2 * 16;
            uint32_t bd = (uint32_t)((p0 + (q & 1) * 8 + rr) * T2ST + e0 + (q >> 1) * 8) * 2;
            ldm_x4_t(bh[nt2], bVh + bd);
            ldm_x4_t(bl[nt2], bVl + bd);
        }
#pragma unroll
        for (int mt = 0; mt < 2; mt++)
#pragma unroll
            for (int nt = 0; nt < 8; nt++) {
                const uint32_t* pbh = &bh[nt >> 1][(nt & 1) * 2];
                const uint32_t* pbl = &bl[nt >> 1][(nt & 1) * 2];
                mma16816(acc[mt][nt], ah[mt], pbh);
                mma16816(acc[mt][nt], ah[mt], pbl);
                mma16816(acc[mt][nt], al[mt], pbh);
            }
    }

    int lr = lane >> 2, lc = lane & 3;
    float* dst = KVbuf + (size_t)b * HDIM * HDIM;
#pragma unroll
    for (int mt = 0; mt < 2; mt++) {
        int d = wm + mt * 16 + lr;
#pragma unroll
        for (int nt = 0; nt < 8; nt++) {
            int e = wn + nt * 8 + lc * 2;
            *(float2*)(dst + d * HDIM + e) = make_float2(acc[mt][nt][0], acc[mt][nt][1]);
            *(float2*)(dst + (d + 8) * HDIM + e) = make_float2(acc[mt][nt][2], acc[mt][nt][3]);
        }
    }
}

// ---------------- mix (fp32 f32x2), writes fp16 hi/lo ----------------
__global__ __launch_bounds__(256) void mix_kernel() {
    extern __shared__ __align__(16) float sm[];
    float* Ws = sm;
    float* tB = sm + NBLK * NBLK;
    int hh = blockIdx.y, xt = blockIdx.x;
    int tid = threadIdx.x;
    for (int idx = tid; idx < NBLK * NBLK; idx += 256) Ws[idx] = WBLKbuf[idx];
    const float* src = KVbuf + (size_t)hh * NBLK * HDIM * HDIM + xt * 128;
    for (int idx = tid; idx < NBLK * 128; idx += 256) {
        int i = idx >> 7, c = idx & 127;
        tB[idx] = src[(size_t)i * HDIM * HDIM + c];
    }
    __syncthreads();
    int tx = tid & 15, ty = tid >> 4;
    ull acc[10][4];
#pragma unroll
    for (int oo = 0; oo < 10; oo++)
#pragma unroll
        for (int jj = 0; jj < 4; jj++) acc[oo][jj] = 0ULL;
    for (int i = 0; i < NBLK; i++) {
        ulonglong2 b1 = *(const ulonglong2*)&tB[i * 128 + tx * 8];
        ulonglong2 b2 = *(const ulonglong2*)&tB[i * 128 + tx * 8 + 4];
        ull bb0 = b1.x, bb1 = b1.y, bb2 = b2.x, bb3 = b2.y;
#pragma unroll
        for (int oo = 0; oo < 10; oo++) {
            int o = ty + 16 * oo;
            if (o < NBLK) {
                float w = Ws[o * NBLK + i];
                ull w2 = pack2(w, w);
                acc[oo][0] = ffma2(w2, bb0, acc[oo][0]);
                acc[oo][1] = ffma2(w2, bb1, acc[oo][1]);
                acc[oo][2] = ffma2(w2, bb2, acc[oo][2]);
                acc[oo][3] = ffma2(w2, bb3, acc[oo][3]);
            }
        }
    }
#pragma unroll
    for (int oo = 0; oo < 10; oo++) {
        int o = ty + 16 * oo;
        if (o < NBLK) {
            size_t gb = ((size_t)hh * NBLK + o) * HDIM * HDIM + xt * 128 + tx * 8;
#pragma unroll
            for (int jj = 0; jj < 4; jj++) {
                float v0x, v1x;
                unpack2(acc[oo][jj], v0x, v1x);
                uint32_t hp = h2pack(v0x, v1x);
                *(uint32_t*)(KVMh + gb + 2 * jj) = hp;
                *(uint32_t*)(KVMl + gb + 2 * jj) = h2packlo(v0x, v1x, hp);
            }
        }
    }
}

// ---------------- norm ----------------
__global__ void norm_kernel() {
    int b = blockIdx.x;
    int hh = b / NBLK, o = b % NBLK;
    int p = threadIdx.x;
    if (p >= PBLK) return;
    float acc = EPSF;
    for (int i = 0; i < NBLK; i++)
        acc += WBLKbuf[o * NBLK + i] * QKbuf[(hh * NBLK + i) * PBLK + p];
    NORMbuf[b * PBLK + p] = acc;
}

// ---------------- out: tc fp16 3-pass; C[p,e] = sum_d QR[p,d]*KVM[d,e]; /norm -> AOh ----------------
#define OUT2_SMEM (4 * T2B)

__global__ __launch_bounds__(256) void out_kernel() {
    extern __shared__ __align__(16) char smem[];
    uint32_t sb = smem_u32(smem);
    int b = blockIdx.x;
    int hh = b / NBLK, nb = b % NBLK;
    int tid = threadIdx.x;

    // group A: QR both tiles (3840) + KVM rows 0..63 (2048) = 5888 segs -> 23/thread
#pragma unroll
    for (int i = 0; i < 23; i++) {
        int idx = tid + i * 256;
        if (idx < 3840) {
            int t = idx / 1920;
            int rem = idx - t * 1920;
            int row = rem >> 4, seg = rem & 15;
            int tok = tok_of(nb, row);
            const __half* g = (t == 0) ? QRh : QRl;
            g += (size_t)tok * DIMC + hh * HDIM + seg * 8;
            cp_async16(sb + t * T2B + row * (T2ST * 2) + seg * 16, g);
        } else if (idx < 5888) {
            int idx2 = idx - 3840;
            int t = idx2 >> 10;
            int rem = idx2 & 1023;
            int row = rem >> 4, seg = rem & 15;
            const __half* g = (t == 0) ? KVMh : KVMl;
            g += (size_t)b * HDIM * HDIM + row * HDIM + seg * 8;
            cp_async16(sb + (2 + t) * T2B + row * (T2ST * 2) + seg * 16, g);
        }
    }
    asm volatile("cp.async.commit_group;" ::: "memory");
    // group B: KVM rows 64..127 (2048 segs -> 8/thread)
#pragma unroll
    for (int i = 0; i < 8; i++) {
        int idx = tid + i * 256;
        int t = idx >> 10;
        int rem = idx & 1023;
        int row = 64 + (rem >> 4), seg = rem & 15;
        const __half* g = (t == 0) ? KVMh : KVMl;
        g += (size_t)b * HDIM * HDIM + row * HDIM + seg * 8;
        cp_async16(sb + (2 + t) * T2B + row * (T2ST * 2) + seg * 16, g);
    }
    asm volatile("cp.async.commit_group;" ::: "memory");

    int wid = tid >> 5, lane = tid & 31;
    int q = lane >> 3, rr = lane & 7;
    int wm = (wid & 1) * 64, wn = (wid >> 1) * 32;   // p, e
    uint32_t bQh = sb, bQl = sb + T2B, bMh = sb + 2 * T2B, bMl = sb + 3 * T2B;

    float acc[4][4][4];
#pragma unroll
    for (int i = 0; i < 4; i++)
#pragma unroll
        for (int j = 0; j < 4; j++)
#pragma unroll
            for (int r = 0; r < 4; r++) acc[i][j][r] = 0.f;

    asm volatile("cp.async.wait_group 1;" ::: "memory");
    __syncthreads();

#pragma unroll
    for (int ks = 0; ks < 8; ks++) {
        if (ks == 4) {
            asm volatile("cp.async.wait_group 0;" ::: "memory");
            __syncthreads();
        }
        int d0 = ks * 16;
        uint32_t ah[4][4], al[4][4], bh[2][4], bl[2][4];
#pragma unroll
        for (int mt = 0; mt < 4; mt++) {
            int m0 = wm + mt * 16;
            uint32_t ad = (uint32_t)((m0 + (q & 1) * 8 + rr) * T2ST + d0 + (q >> 1) * 8) * 2;
            ldm_x4(ah[mt], bQh + ad);
            ldm_x4(al[mt], bQl + ad);
        }
#pragma unroll
        for (int nt2 = 0; nt2 < 2; nt2++) {
            int e0 = wn + nt2 * 16;
            uint32_t bd = (uint32_t)((d0 + (q & 1) * 8 + rr) * T2ST + e0 + (q >> 1) * 8) * 2;
            ldm_x4_t(bh[nt2], bMh + bd);
            ldm_x4_t(bl[nt2], bMl + bd);
        }
#pragma unroll
        for (int mt = 0; mt < 4; mt++)
#pragma unroll
            for (int nt = 0; nt < 4; nt++) {
                const uint32_t* pbh = &bh[nt >> 1][(nt & 1) * 2];
                const uint32_t* pbl = &bl[nt >> 1][(nt & 1) * 2];
                mma16816(acc[mt][nt], ah[mt], pbh);
                mma16816(acc[mt][nt], ah[mt], pbl);
                mma16816(acc[mt][nt], al[mt], pbh);
            }
    }

    int lr = lane >> 2, lc = lane & 3;
#pragma unroll
    for (int mt = 0; mt < 4; mt++) {
        int p = wm + mt * 16 + lr;
#pragma unroll
        for (int half = 0; half < 2; half++) {
            int pp = p + half * 8;
            if (pp < PBLK) {
                float inv = 1.0f / NORMbuf[b * PBLK + pp];
                int tok = tok_of(nb, pp);
                size_t gb = (size_t)tok * DIMC + hh * HDIM;
#pragma unroll
                for (int nt = 0; nt < 4; nt++) {
                    int e = wn + nt * 8 + lc * 2;
                    float v0 = acc[mt][nt][2 * half]     * inv;
                    float v1 = acc[mt][nt][2 * half + 1] * inv;
                    *(uint32_t*)(AOh + gb + e) = h2pack(v0, v1);
                }
            }
        }
    }
}

// ---------------- launch ----------------
extern "C" void kernel_launch(void* const* d_in, const int* in_sizes, int n_in,
                              void* d_out, int out_size) {
    const float* x   = (const float*)d_in[0];
    const float* fc  = (const float*)d_in[3];
    const float* fs  = (const float*)d_in[4];
    const float* wq  = (const float*)d_in[5];
    const float* bq  = (const float*)d_in[6];
    const float* wk  = (const float*)d_in[7];
    const float* bk  = (const float*)d_in[8];
    const float* wv  = (const float*)d_in[9];
    const float* bv  = (const float*)d_in[10];
    const float* wo  = (const float*)d_in[11];
    const float* bo  = (const float*)d_in[12];
    const float* nqw = (const float*)d_in[13];
    const float* nkw = (const float*)d_in[14];
    float* out = (float*)d_out;

    void* pxh;
    cudaGetSymbolAddress(&pxh, Xh);

    const int MIX_SMEM = (NBLK * NBLK + NBLK * 128) * 4;
    cudaFuncSetAttribute(gemm_qkv,  cudaFuncAttributeMaxDynamicSharedMemorySize, GEMM_SMEM);
    cudaFuncSetAttribute(gemm_out,  cudaFuncAttributeMaxDynamicSharedMemorySize, GEMM_SMEM);
    cudaFuncSetAttribute(kv_kernel, cudaFuncAttributeMaxDynamicSharedMemorySize, KV2_SMEM);
    cudaFuncSetAttribute(mix_kernel, cudaFuncAttributeMaxDynamicSharedMemorySize, MIX_SMEM);
    cudaFuncSetAttribute(out_kernel, cudaFuncAttributeMaxDynamicSharedMemorySize, OUT2_SMEM);

    wblk_kernel<<<NBLK, 256>>>();
    conv_half<<<(MPAD * DIMC) / 256, 256>>>(x, (__half*)pxh, NTOK * DIMC, MPAD * DIMC);
    conv_w4<<<dim3((DIMC * DIMC) / 256, 4), 256>>>(wq, wk, wv, wo);

    dim3 gg(DIMC / 128, MPAD / 128, 3);
    gemm_qkv<<<gg, 256, GEMM_SMEM>>>(bq, bk, bv);

    rmsnorm_rope_kernel<<<dim3(NTOK, 2), 256>>>(nqw, nkw, fc, fs);

    qk_kernel<<<NHEAD * NBLK, HDIM>>>();
    kv_kernel<<<NHEAD * NBLK, 256, KV2_SMEM>>>();
    mix_kernel<<<dim3(128, NHEAD), 256, MIX_SMEM>>>();
    norm_kernel<<<NHEAD * NBLK, 128>>>();
    out_kernel<<<NHEAD * NBLK, 256, OUT2_SMEM>>>();

    dim3 go(DIMC / 128, MPAD / 128);
    gemm_out<<<go, 256, GEMM_SMEM>>>(bo, out);
}

// round 10
// speedup vs baseline: 6.5797x; 1.1833x over previous
#include <cuda_runtime.h>
#include <cuda_fp16.h>
#include <cstdint>
#include <cstdio>

// ---------------- problem dims (fixed) ----------------
#define NTOK   18000      // F*H*W = 12*30*50
#define MPAD   18048      // padded to multiple of 128
#define DIMC   1536
#define NHEAD  12
#define HDIM   128
#define NBLK   150        // FB*HB*WB = 3*5*10
#define PBLK   120        // P1*P2*P3 = 4*6*5
#define EPSF   1e-6f

typedef unsigned long long ull;

// ---------------- mma / ldmatrix helpers ----------------
__device__ __forceinline__ uint32_t smem_u32(const void* p) {
    uint32_t a;
    asm("{ .reg .u64 t; cvta.to.shared.u64 t, %1; cvt.u32.u64 %0, t; }" : "=r"(a) : "l"(p));
    return a;
}
__device__ __forceinline__ void cp_async16(uint32_t dst, const void* src) {
    asm volatile("cp.async.cg.shared.global [%0], [%1], 16;" :: "r"(dst), "l"(src) : "memory");
}
__device__ __forceinline__ void ldm_x4(uint32_t* r, uint32_t addr) {
    asm volatile("ldmatrix.sync.aligned.m8n8.x4.shared.b16 {%0,%1,%2,%3}, [%4];"
                 : "=r"(r[0]), "=r"(r[1]), "=r"(r[2]), "=r"(r[3]) : "r"(addr));
}
__device__ __forceinline__ void ldm_x4_t(uint32_t* r, uint32_t addr) {
    asm volatile("ldmatrix.sync.aligned.m8n8.x4.trans.shared.b16 {%0,%1,%2,%3}, [%4];"
                 : "=r"(r[0]), "=r"(r[1]), "=r"(r[2]), "=r"(r[3]) : "r"(addr));
}
__device__ __forceinline__ void mma16816(float* c, const uint32_t* a, const uint32_t* b) {
    asm volatile("mma.sync.aligned.m16n8k16.row.col.f32.f16.f16.f32 "
                 "{%0,%1,%2,%3}, {%4,%5,%6,%7}, {%8,%9}, {%0,%1,%2,%3};"
                 : "+f"(c[0]), "+f"(c[1]), "+f"(c[2]), "+f"(c[3])
                 : "r"(a[0]), "r"(a[1]), "r"(a[2]), "r"(a[3]), "r"(b[0]), "r"(b[1]));
}
__device__ __forceinline__ uint32_t h2pack(float a, float b) {
    __half2 h = __floats2half2_rn(a, b);
    return *(uint32_t*)&h;
}
__device__ __forceinline__ uint32_t h2packlo(float a, float b, uint32_t hp) {
    __half2 h = *(__half2*)&hp;
    float2 hf = __half22float2(h);
    __half2 l = __floats2half2_rn(a - hf.x, b - hf.y);
    return *(uint32_t*)&l;
}

// ---------------- scratch ----------------
__device__ float Qbuf[NTOK * DIMC];      // pre-rope normed q (fp32, for qk)
__device__ float Kbuf[NTOK * DIMC];      // pre-rope normed k (fp32, for qk)
__device__ float QKbuf[NHEAD * NBLK * PBLK];
__device__ float NORMbuf[NHEAD * NBLK * PBLK];
__device__ float WBLKbuf[NBLK * NBLK];

// fp16 operand buffers
__device__ __half Xh[MPAD * DIMC];
__device__ __half AOh[MPAD * DIMC];      // zero-init; pad rows never written
__device__ __half Wh4[4][DIMC * DIMC];
__device__ __half Vh[NTOK * DIMC];
__device__ __half Vl[NTOK * DIMC];
__device__ __half QRh[NTOK * DIMC];
__device__ __half QRl[NTOK * DIMC];
__device__ __half KRh[NTOK * DIMC];
__device__ __half KRl[NTOK * DIMC];
__device__ __half KVah[NHEAD * NBLK * HDIM * HDIM];   // kv output, fp16 hi
__device__ __half KVal[NHEAD * NBLK * HDIM * HDIM];   // kv output, fp16 lo
__device__ __half KVMh[NHEAD * NBLK * HDIM * HDIM];
__device__ __half KVMl[NHEAD * NBLK * HDIM * HDIM];
// block-mix matrix, fp16 hi/lo, zero-padded to 160x160 (zero-init covers pad)
__device__ __half WBh[160 * 160];
__device__ __half WBl[160 * 160];

__device__ __forceinline__ int tok_of(int nb, int p) {
    int fb = nb / 50, hb = (nb / 10) % 5, wb = nb % 10;
    int p1 = p / 30, p2 = (p / 5) % 6, p3 = p % 5;
    int f = fb * 4 + p1, h = hb * 6 + p2, w = wb * 5 + p3;
    return (f * 30 + h) * 50 + w;
}

// ---------------- W_BLK ----------------
__global__ void wblk_kernel() {
    int j = blockIdx.x;
    int i = threadIdx.x;
    __shared__ double ssum[256];
    double m = 0.0;
    if (i < NBLK) {
        int fi = i / 50, hi = (i / 10) % 5, wi = i % 10;
        int fj = j / 50, hj = (j / 10) % 5, wj = j % 10;
        double df = fi - fj, dh = hi - hj, dw = wi - wj;
        double d = sqrt(df * df + dh * dh + dw * dw);
        m = 1.0 - d / sqrt(101.0);
    }
    ssum[i] = m;
    __syncthreads();
    for (int s = 128; s > 0; s >>= 1) {
        if (i < s) ssum[i] += ssum[i + s];
        __syncthreads();
    }
    if (i < NBLK) {
        float w = (float)(m / ssum[0]);
        WBLKbuf[i * NBLK + j] = w;
        __half h = __float2half(w);
        WBh[i * 160 + j] = h;
        WBl[i * 160 + j] = __float2half(w - __half2float(h));
    }
}

// ---------------- fp32 -> fp16 ----------------
__global__ void conv_half(const float* __restrict__ src, __half* __restrict__ dst, int n, int ntot) {
    int i = blockIdx.x * 256 + threadIdx.x;
    if (i >= ntot) return;
    float v = (i < n) ? src[i] : 0.f;
    dst[i] = __float2half(v);
}

__global__ void conv_w4(const float* __restrict__ w0, const float* __restrict__ w1,
                        const float* __restrict__ w2, const float* __restrict__ w3) {
    int y = blockIdx.y;
    const float* src = (y == 0) ? w0 : (y == 1) ? w1 : (y == 2) ? w2 : w3;
    int i = blockIdx.x * 256 + threadIdx.x;
    Wh4[y][i] = __float2half(src[i]);
}

// ---------------- pipelined fp16 1-pass tensor-core GEMM ----------------
#define KC      32
#define NCHUNK  (DIMC / KC)              // 48
#define TILEB   (128 * 64)               // 8192 B per operand tile
#define STAGEB  (2 * TILEB)              // 16384 B (A, B)
#define NSTAGE  4
#define GEMM_SMEM (NSTAGE * STAGEB)      // 65536 B -> 2 CTAs/SM

__device__ __forceinline__ void gemm_core(
    const __half* __restrict__ A, const __half* __restrict__ B,
    const float* __restrict__ bias, float* __restrict__ C,
    __half* __restrict__ VhOut, __half* __restrict__ VlOut, int M,
    int m0, int n0, uint32_t sb)
{
    int tid = threadIdx.x;
    int wid = tid >> 5, lane = tid & 31;
    int wm = (wid & 1) * 64;
    int wn = (wid >> 1) * 32;
    int lr = lane >> 2, lc = lane & 3;
    int q = lane >> 3, rr = lane & 7;

    int a_row = (q & 1) * 8 + rr;
    int a_seg0 = q >> 1;
    int b_row = (q >> 1) * 8 + rr;
    int b_seg0 = q & 1;
    int swA = (a_row >> 1) & 3;
    int swB = (b_row >> 1) & 3;
    uint32_t rowbA = (uint32_t)(wm + a_row) * 64;
    uint32_t rowbB = (uint32_t)(wn + b_row) * 64;

    float acc[4][4][4];
#pragma unroll
    for (int i = 0; i < 4; i++)
#pragma unroll
        for (int j = 0; j < 4; j++)
#pragma unroll
            for (int r = 0; r < 4; r++) acc[i][j][r] = 0.f;

    const __half* gptr[4];
    uint32_t sof[4];
#pragma unroll
    for (int i = 0; i < 4; i++) {
        int idx = tid + i * 256;
        int t = idx >> 9, row = (idx >> 2) & 127, seg = idx & 3;
        const __half* g = (t == 0) ? (A + (size_t)(m0 + row) * DIMC + seg * 8)
                                   : (B + (size_t)(n0 + row) * DIMC + seg * 8);
        gptr[i] = g;
        sof[i] = (uint32_t)(t * TILEB + row * 64 + ((seg ^ ((row >> 1) & 3)) * 16));
    }

    auto load_chunk = [&](int c, int st) {
        uint32_t sd = sb + st * STAGEB;
        size_t kof = (size_t)c * KC;
#pragma unroll
        for (int i = 0; i < 4; i++)
            cp_async16(sd + sof[i], gptr[i] + kof);
        asm volatile("cp.async.commit_group;" ::: "memory");
    };

    load_chunk(0, 0);
    load_chunk(1, 1);
    load_chunk(2, 2);
    for (int c = 0; c < NCHUNK; c++) {
        if (c < NCHUNK - 2)
            asm volatile("cp.async.wait_group 2;" ::: "memory");
        else if (c == NCHUNK - 2)
            asm volatile("cp.async.wait_group 1;" ::: "memory");
        else
            asm volatile("cp.async.wait_group 0;" ::: "memory");
        __syncthreads();
        uint32_t tb = sb + (c & 3) * STAGEB;
        uint32_t bA = tb + rowbA;
        uint32_t bB = tb + TILEB + rowbB;

        {
            uint32_t offA = (uint32_t)((a_seg0 ^ swA) * 16);
            uint32_t offB = (uint32_t)((b_seg0 ^ swB) * 16);
            uint32_t ah[4][4], bh[2][4];
#pragma unroll
            for (int mt = 0; mt < 4; mt++)
                ldm_x4(ah[mt], bA + mt * 1024 + offA);
#pragma unroll
            for (int nt2 = 0; nt2 < 2; nt2++)
                ldm_x4(bh[nt2], bB + nt2 * 1024 + offB);
#pragma unroll
            for (int mt = 0; mt < 4; mt++)
#pragma unroll
                for (int nt = 0; nt < 4; nt++)
                    mma16816(acc[mt][nt], ah[mt], &bh[nt >> 1][(nt & 1) * 2]);
        }
        if (c + 3 < NCHUNK) load_chunk(c + 3, (c + 3) & 3);
        {
            uint32_t offA = (uint32_t)(((a_seg0 + 2) ^ swA) * 16);
            uint32_t offB = (uint32_t)(((b_seg0 + 2) ^ swB) * 16);
            uint32_t ah[4][4], bh[2][4];
#pragma unroll
            for (int mt = 0; mt < 4; mt++)
                ldm_x4(ah[mt], bA + mt * 1024 + offA);
#pragma unroll
            for (int nt2 = 0; nt2 < 2; nt2++)
                ldm_x4(bh[nt2], bB + nt2 * 1024 + offB);
#pragma unroll
            for (int mt = 0; mt < 4; mt++)
#pragma unroll
                for (int nt = 0; nt < 4; nt++)
                    mma16816(acc[mt][nt], ah[mt], &bh[nt >> 1][(nt & 1) * 2]);
        }
    }

#pragma unroll
    for (int mt = 0; mt < 4; mt++) {
        int m = m0 + wm + mt * 16 + lr;
#pragma unroll
        for (int nt = 0; nt < 4; nt++) {
            int col = n0 + wn + nt * 8 + lc * 2;
            float bx = bias[col], by = bias[col + 1];
            if (VhOut) {
                if (m < M) {
                    float v0 = acc[mt][nt][0] + bx, v1 = acc[mt][nt][1] + by;
                    uint32_t hp = h2pack(v0, v1);
                    *(uint32_t*)(VhOut + (size_t)m * DIMC + col) = hp;
                    *(uint32_t*)(VlOut + (size_t)m * DIMC + col) = h2packlo(v0, v1, hp);
                }
                if (m + 8 < M) {
                    float v0 = acc[mt][nt][2] + bx, v1 = acc[mt][nt][3] + by;
                    uint32_t hp = h2pack(v0, v1);
                    *(uint32_t*)(VhOut + (size_t)(m + 8) * DIMC + col) = hp;
                    *(uint32_t*)(VlOut + (size_t)(m + 8) * DIMC + col) = h2packlo(v0, v1, hp);
                }
            } else {
                if (m < M) {
                    float2 v = make_float2(acc[mt][nt][0] + bx, acc[mt][nt][1] + by);
                    *(float2*)(C + (size_t)m * DIMC + col) = v;
                }
                if (m + 8 < M) {
                    float2 v = make_float2(acc[mt][nt][2] + bx, acc[mt][nt][3] + by);
                    *(float2*)(C + (size_t)(m + 8) * DIMC + col) = v;
                }
            }
        }
    }
}

__global__ __launch_bounds__(256, 2) void gemm_qkv(
    const float* __restrict__ bq, const float* __restrict__ bk, const float* __restrict__ bv)
{
    extern __shared__ __align__(16) char smem[];
    uint32_t sb = smem_u32(smem);
    int z = blockIdx.z;
    if (z == 2) {
        gemm_core(Xh, Wh4[2], bv, (float*)0, Vh, Vl, NTOK,
                  blockIdx.y * 128, blockIdx.x * 128, sb);
    } else {
        const float* bias = (z == 0) ? bq : bk;
        float* C = (z == 0) ? Qbuf : Kbuf;
        gemm_core(Xh, Wh4[z], bias, C, (__half*)0, (__half*)0, NTOK,
                  blockIdx.y * 128, blockIdx.x * 128, sb);
    }
}

__global__ __launch_bounds__(256, 2) void gemm_out(const float* __restrict__ bo, float* __restrict__ out)
{
    extern __shared__ __align__(16) char smem[];
    uint32_t sb = smem_u32(smem);
    gemm_core(AOh, Wh4[3], bo, out, (__half*)0, (__half*)0, NTOK,
              blockIdx.y * 128, blockIdx.x * 128, sb);
}

// ---------------- fused rmsnorm + relu + eps + RoPE; fp16 hi/lo roped outputs ----------------
__global__ void rmsnorm_rope_kernel(const float* __restrict__ nqw, const float* __restrict__ nkw,
                                    const float* __restrict__ fc, const float* __restrict__ fs) {
    int n = blockIdx.x;
    bool isK = blockIdx.y;
    float* buf = isK ? Kbuf : Qbuf;
    __half* rh = isK ? KRh : QRh;
    __half* rl = isK ? KRl : QRl;
    const float* w = isK ? nkw : nqw;
    int tid = threadIdx.x;
    size_t base = (size_t)n * DIMC;
    float2* b2 = (float2*)(buf + base);
    const float2* w2 = (const float2*)w;

    int f = n / 1500, rem = n % 1500;
    int hh = rem / 50, ww = rem % 50;

    float2 v[3];
    float ss = 0.f;
#pragma unroll
    for (int t = 0; t < 3; t++) {
        v[t] = b2[tid + t * 256];
        ss += v[t].x * v[t].x + v[t].y * v[t].y;
    }
    for (int o = 16; o > 0; o >>= 1) ss += __shfl_xor_sync(0xffffffffu, ss, o);
    __shared__ float red[8];
    __shared__ float stot;
    if ((tid & 31) == 0) red[tid >> 5] = ss;
    __syncthreads();
    if (tid == 0) {
        float t = 0.f;
        for (int i = 0; i < 8; i++) t += red[i];
        stot = t;
    }
    __syncthreads();
    float sc = 1.0f / sqrtf(stot * (1.0f / DIMC) + EPSF);
#pragma unroll
    for (int t = 0; t < 3; t++) {
        int idx = tid + t * 256;
        float2 wv = w2[idx];
        float x0 = fmaxf(v[t].x * sc * wv.x, 0.f) + EPSF;
        float x1 = fmaxf(v[t].y * sc * wv.y, 0.f) + EPSF;
        b2[idx] = make_float2(x0, x1);
        int c = idx & 63;
        int pos = (c < 22) ? f : ((c < 43) ? hh : ww);
        float cs = fc[pos * 64 + c];
        float sn = fs[pos * 64 + c];
        float r0 = x0 * cs - x1 * sn;
        float r1 = x0 * sn + x1 * cs;
        uint32_t hp = h2pack(r0, r1);
        *(uint32_t*)(rh + base + 2 * idx) = hp;
        *(uint32_t*)(rl + base + 2 * idx) = h2packlo(r0, r1, hp);
    }
}

// ---------------- fused ksum + qk (fp32) ----------------
__global__ void qk_kernel() {
    int b = blockIdx.x;
    int hh = b / NBLK, nb = b % NBLK;
    int tid = threadIdx.x;
    __shared__ float ks[HDIM];
    float acc = 0.f;
    for (int p = 0; p < PBLK; p++) {
        int t = tok_of(nb, p);
        acc += Kbuf[(size_t)t * DIMC + hh * HDIM + tid];
    }
    ks[tid] = acc;
    __syncthreads();
    if (tid < PBLK) {
        int t = tok_of(nb, tid);
        const float* qp = Qbuf + (size_t)t * DIMC + hh * HDIM;
        float a = 0.f;
#pragma unroll 4
        for (int d = 0; d < HDIM; d++) a += qp[d] * ks[d];
        QKbuf[b * PBLK + tid] = a;
    }
}

// ---------------- kv: tensor-core fp16 3-pass;  KV[d,e] = sum_p KR[p,d]*V[p,e] ----------------
#define T2ST  136                       // halves per smem row (272 B, 4-bank rotation)
#define T2B   (128 * T2ST * 2)          // 34816 B per tile
#define KV2_SMEM (4 * T2B)              // 139264

__global__ __launch_bounds__(256) void kv_kernel() {
    extern __shared__ __align__(16) char smem[];
    uint32_t sb = smem_u32(smem);
    int b = blockIdx.x;
    int hh = b / NBLK, nb = b % NBLK;
    int tid = threadIdx.x;

    // zero k-pad rows 120..127 (first 256B of each row) in all 4 tiles
    for (int i = tid; i < 4 * 8 * 16; i += 256) {
        int t = i >> 7, r = (i >> 4) & 7, s = i & 15;
        *(uint4*)(smem + t * T2B + (120 + r) * (T2ST * 2) + s * 16) = make_uint4(0, 0, 0, 0);
    }
    // group A: rows 0..63 of all 4 tiles
#pragma unroll
    for (int i = 0; i < 16; i++) {
        int idx = tid + i * 256;
        int t = idx >> 10;
        int rem = idx & 1023;
        int row = rem >> 4, seg = rem & 15;
        int tok = tok_of(nb, row);
        const __half* g = (t == 0) ? KRh : (t == 1) ? KRl : (t == 2) ? Vh : Vl;
        g += (size_t)tok * DIMC + hh * HDIM + seg * 8;
        cp_async16(sb + t * T2B + row * (T2ST * 2) + seg * 16, g);
    }
    asm volatile("cp.async.commit_group;" ::: "memory");
    // group B: rows 64..119
#pragma unroll
    for (int i = 0; i < 14; i++) {
        int idx = tid + i * 256;
        int t = idx / 896;
        int rem = idx - t * 896;
        int row = 64 + (rem >> 4), seg = rem & 15;
        int tok = tok_of(nb, row);
        const __half* g = (t == 0) ? KRh : (t == 1) ? KRl : (t == 2) ? Vh : Vl;
        g += (size_t)tok * DIMC + hh * HDIM + seg * 8;
        cp_async16(sb + t * T2B + row * (T2ST * 2) + seg * 16, g);
    }
    asm volatile("cp.async.commit_group;" ::: "memory");

    int wid = tid >> 5, lane = tid & 31;
    int q = lane >> 3, rr = lane & 7;
    int wm = (wid & 3) * 32, wn = (wid >> 2) * 64;   // d, e
    uint32_t bKRh = sb, bKRl = sb + T2B, bVh = sb + 2 * T2B, bVl = sb + 3 * T2B;

    float acc[2][8][4];
#pragma unroll
    for (int i = 0; i < 2; i++)
#pragma unroll
        for (int j = 0; j < 8; j++)
#pragma unroll
            for (int r = 0; r < 4; r++) acc[i][j][r] = 0.f;

    asm volatile("cp.async.wait_group 1;" ::: "memory");
    __syncthreads();

#pragma unroll
    for (int ks = 0; ks < 8; ks++) {
        if (ks == 4) {
            asm volatile("cp.async.wait_group 0;" ::: "memory");
            __syncthreads();
        }
        int p0 = ks * 16;
        uint32_t ah[2][4], al[2][4], bh[4][4], bl[4][4];
#pragma unroll
        for (int mt = 0; mt < 2; mt++) {
            int d0 = wm + mt * 16;
            uint32_t ad = (uint32_t)((p0 + (q >> 1) * 8 + rr) * T2ST + d0 + (q & 1) * 8) * 2;
            ldm_x4_t(ah[mt], bKRh + ad);
            ldm_x4_t(al[mt], bKRl + ad);
        }
#pragma unroll
        for (int nt2 = 0; nt2 < 4; nt2++) {
            int e0 = wn + nt2 * 16;
            uint32_t bd = (uint32_t)((p0 + (q & 1) * 8 + rr) * T2ST + e0 + (q >> 1) * 8) * 2;
            ldm_x4_t(bh[nt2], bVh + bd);
            ldm_x4_t(bl[nt2], bVl + bd);
        }
#pragma unroll
        for (int mt = 0; mt < 2; mt++)
#pragma unroll
            for (int nt = 0; nt < 8; nt++) {
                const uint32_t* pbh = &bh[nt >> 1][(nt & 1) * 2];
                const uint32_t* pbl = &bl[nt >> 1][(nt & 1) * 2];
                mma16816(acc[mt][nt], ah[mt], pbh);
                mma16816(acc[mt][nt], ah[mt], pbl);
                mma16816(acc[mt][nt], al[mt], pbh);
            }
    }

    int lr = lane >> 2, lc = lane & 3;
    size_t db = (size_t)b * HDIM * HDIM;
#pragma unroll
    for (int mt = 0; mt < 2; mt++) {
        int d = wm + mt * 16 + lr;
#pragma unroll
        for (int nt = 0; nt < 8; nt++) {
            int e = wn + nt * 8 + lc * 2;
            {
                float v0 = acc[mt][nt][0], v1 = acc[mt][nt][1];
                uint32_t hp = h2pack(v0, v1);
                *(uint32_t*)(KVah + db + d * HDIM + e) = hp;
                *(uint32_t*)(KVal + db + d * HDIM + e) = h2packlo(v0, v1, hp);
            }
            {
                float v0 = acc[mt][nt][2], v1 = acc[mt][nt][3];
                uint32_t hp = h2pack(v0, v1);
                *(uint32_t*)(KVah + db + (d + 8) * HDIM + e) = hp;
                *(uint32_t*)(KVal + db + (d + 8) * HDIM + e) = h2packlo(v0, v1, hp);
            }
        }
    }
}

// ---------------- mix on tensor cores: KVM[h,o,:] = sum_i W[o,i] * KV[h,i,:] ----------------
// A = W (160x160 padded, hi/lo), B = KV slice [i, e] via trans ldm. 3-pass.
#define MXST  168                       // W smem row stride halves (336 B)
#define MWB   (160 * MXST * 2)          // 53760 B per W tile
#define MKST  136                       // kv smem row stride halves (272 B)
#define MKB   (160 * MKST * 2)          // 43520 B per kv tile
#define MIX2_SMEM (2 * MWB + 2 * MKB)   // 194560 B

__global__ __launch_bounds__(256) void mix_tc_kernel() {
    extern __shared__ __align__(16) char smem[];
    uint32_t sb = smem_u32(smem);
    int hh = blockIdx.y, xt = blockIdx.x;     // e-slice of 128 (16384/128)
    int tid = threadIdx.x;

    uint32_t bWh = sb, bWl = sb + MWB, bKh = sb + 2 * MWB, bKl = sb + 2 * MWB + MKB;

    // zero kv pad rows 150..159 (both tiles): 2 * 10 rows * 17 segs = 340
    for (int i = tid; i < 340; i += 256) {
        int t = i / 170, rem = i % 170;
        int r = rem / 17, s = rem % 17;
        *(uint4*)(smem + 2 * MWB + t * MKB + (150 + r) * (MKST * 2) + s * 16) = make_uint4(0, 0, 0, 0);
    }
    // load W tiles: 160 rows x 20 segs each = 3200 per tile, 6400 both -> 25/thread
#pragma unroll
    for (int i = 0; i < 25; i++) {
        int idx = tid + i * 256;
        int t = idx / 3200, rem = idx % 3200;
        int row = rem / 20, seg = rem % 20;
        const __half* g = ((t == 0) ? WBh : WBl) + row * 160 + seg * 8;
        cp_async16(sb + t * MWB + row * (MXST * 2) + seg * 16, g);
    }
    // load kv slices: 150 rows x 16 segs x 2 tiles = 4800 -> 19/thread (guard)
#pragma unroll
    for (int i = 0; i < 19; i++) {
        int idx = tid + i * 256;
        if (idx < 4800) {
            int t = idx >> 11, rem = idx & 2047;       // 2048-aligned? 4800 = 2*2400
            t = idx / 2400; rem = idx % 2400;
            int row = rem >> 4, seg = rem & 15;
            const __half* g = ((t == 0) ? KVah : KVal)
                            + ((size_t)(hh * NBLK + row)) * (HDIM * HDIM) + xt * 128 + seg * 8;
            cp_async16(sb + 2 * MWB + t * MKB + row * (MKST * 2) + seg * 16, g);
        }
    }
    asm volatile("cp.async.commit_group;" ::: "memory");
    asm volatile("cp.async.wait_group 0;" ::: "memory");
    __syncthreads();

    int wid = tid >> 5, lane = tid & 31;
    int q = lane >> 3, rr = lane & 7;
    int wm = (wid & 1) * 80;                 // o: 5 m16 tiles per warp
    int wn = (wid >> 1) * 32;                // e

    float acc[5][4][4];
#pragma unroll
    for (int i = 0; i < 5; i++)
#pragma unroll
        for (int j = 0; j < 4; j++)
#pragma unroll
            for (int r = 0; r < 4; r++) acc[i][j][r] = 0.f;

#pragma unroll
    for (int ks = 0; ks < 10; ks++) {
        int k0 = ks * 16;
        uint32_t ah[5][4], al[5][4], bh[2][4], bl[2][4];
#pragma unroll
        for (int mt = 0; mt < 5; mt++) {
            int m0 = wm + mt * 16;
            uint32_t ad = (uint32_t)((m0 + (q & 1) * 8 + rr) * MXST + k0 + (q >> 1) * 8) * 2;
            ldm_x4(ah[mt], bWh + ad);
            ldm_x4(al[mt], bWl + ad);
        }
#pragma unroll
        for (int nt2 = 0; nt2 < 2; nt2++) {
            int e0 = wn + nt2 * 16;
            uint32_t bd = (uint32_t)((k0 + (q & 1) * 8 + rr) * MKST + e0 + (q >> 1) * 8) * 2;
            ldm_x4_t(bh[nt2], bKh + bd);
            ldm_x4_t(bl[nt2], bKl + bd);
        }
#pragma unroll
        for (int mt = 0; mt < 5; mt++)
#pragma unroll
            for (int nt = 0; nt < 4; nt++) {
                const uint32_t* pbh = &bh[nt >> 1][(nt & 1) * 2];
                const uint32_t* pbl = &bl[nt >> 1][(nt & 1) * 2];
                mma16816(acc[mt][nt], ah[mt], pbh);
                mma16816(acc[mt][nt], ah[mt], pbl);
                mma16816(acc[mt][nt], al[mt], pbh);
            }
    }

    int lr = lane >> 2, lc = lane & 3;
#pragma unroll
    for (int mt = 0; mt < 5; mt++) {
        int o = wm + mt * 16 + lr;
#pragma unroll
        for (int half = 0; half < 2; half++) {
            int oo = o + half * 8;
            if (oo < NBLK) {
                size_t gb = ((size_t)(hh * NBLK + oo)) * (HDIM * HDIM) + xt * 128 + wn;
#pragma unroll
                for (int nt = 0; nt < 4; nt++) {
                    int e = nt * 8 + lc * 2;
                    float v0 = acc[mt][nt][2 * half];
                    float v1 = acc[mt][nt][2 * half + 1];
                    uint32_t hp = h2pack(v0, v1);
                    *(uint32_t*)(KVMh + gb + e) = hp;
                    *(uint32_t*)(KVMl + gb + e) = h2packlo(v0, v1, hp);
                }
            }
        }
    }
}

// ---------------- norm ----------------
__global__ void norm_kernel() {
    int b = blockIdx.x;
    int hh = b / NBLK, o = b % NBLK;
    int p = threadIdx.x;
    if (p >= PBLK) return;
    float acc = EPSF;
    for (int i = 0; i < NBLK; i++)
        acc += WBLKbuf[o * NBLK + i] * QKbuf[(hh * NBLK + i) * PBLK + p];
    NORMbuf[b * PBLK + p] = acc;
}

// ---------------- out: tc fp16 3-pass; C[p,e] = sum_d QR[p,d]*KVM[d,e]; /norm -> AOh ----------------
#define OUT2_SMEM (4 * T2B)

__global__ __launch_bounds__(256) void out_kernel() {
    extern __shared__ __align__(16) char smem[];
    uint32_t sb = smem_u32(smem);
    int b = blockIdx.x;
    int hh = b / NBLK, nb = b % NBLK;
    int tid = threadIdx.x;

    // group A: QR both tiles (3840) + KVM rows 0..63 (2048) = 5888 segs -> 23/thread
#pragma unroll
    for (int i = 0; i < 23; i++) {
        int idx = tid + i * 256;
        if (idx < 3840) {
            int t = idx / 1920;
            int rem = idx - t * 1920;
            int row = rem >> 4, seg = rem & 15;
            int tok = tok_of(nb, row);
            const __half* g = (t == 0) ? QRh : QRl;
            g += (size_t)tok * DIMC + hh * HDIM + seg * 8;
            cp_async16(sb + t * T2B + row * (T2ST * 2) + seg * 16, g);
        } else if (idx < 5888) {
            int idx2 = idx - 3840;
            int t = idx2 >> 10;
            int rem = idx2 & 1023;
            int row = rem >> 4, seg = rem & 15;
            const __half* g = (t == 0) ? KVMh : KVMl;
            g += (size_t)b * HDIM * HDIM + row * HDIM + seg * 8;
            cp_async16(sb + (2 + t) * T2B + row * (T2ST * 2) + seg * 16, g);
        }
    }
    asm volatile("cp.async.commit_group;" ::: "memory");
    // group B: KVM rows 64..127 (2048 segs -> 8/thread)
#pragma unroll
    for (int i = 0; i < 8; i++) {
        int idx = tid + i * 256;
        int t = idx >> 10;
        int rem = idx & 1023;
        int row = 64 + (rem >> 4), seg = rem & 15;
        const __half* g = (t == 0) ? KVMh : KVMl;
        g += (size_t)b * HDIM * HDIM + row * HDIM + seg * 8;
        cp_async16(sb + (2 + t) * T2B + row * (T2ST * 2) + seg * 16, g);
    }
    asm volatile("cp.async.commit_group;" ::: "memory");

    int wid = tid >> 5, lane = tid & 31;
    int q = lane >> 3, rr = lane & 7;
    int wm = (wid & 1) * 64, wn = (wid >> 1) * 32;   // p, e
    uint32_t bQh = sb, bQl = sb + T2B, bMh = sb + 2 * T2B, bMl = sb + 3 * T2B;

    float acc[4][4][4];
#pragma unroll
    for (int i = 0; i < 4; i++)
#pragma unroll
        for (int j = 0; j < 4; j++)
#pragma unroll
            for (int r = 0; r < 4; r++) acc[i][j][r] = 0.f;

    asm volatile("cp.async.wait_group 1;" ::: "memory");
    __syncthreads();

#pragma unroll
    for (int ks = 0; ks < 8; ks++) {
        if (ks == 4) {
            asm volatile("cp.async.wait_group 0;" ::: "memory");
            __syncthreads();
        }
        int d0 = ks * 16;
        uint32_t ah[4][4], al[4][4], bh[2][4], bl[2][4];
#pragma unroll
        for (int mt = 0; mt < 4; mt++) {
            int m0 = wm + mt * 16;
            uint32_t ad = (uint32_t)((m0 + (q & 1) * 8 + rr) * T2ST + d0 + (q >> 1) * 8) * 2;
            ldm_x4(ah[mt], bQh + ad);
            ldm_x4(al[mt], bQl + ad);
        }
#pragma unroll
        for (int nt2 = 0; nt2 < 2; nt2++) {
            int e0 = wn + nt2 * 16;
            uint32_t bd = (uint32_t)((d0 + (q & 1) * 8 + rr) * T2ST + e0 + (q >> 1) * 8) * 2;
            ldm_x4_t(bh[nt2], bMh + bd);
            ldm_x4_t(bl[nt2], bMl + bd);
        }
#pragma unroll
        for (int mt = 0; mt < 4; mt++)
#pragma unroll
            for (int nt = 0; nt < 4; nt++) {
                const uint32_t* pbh = &bh[nt >> 1][(nt & 1) * 2];
                const uint32_t* pbl = &bl[nt >> 1][(nt & 1) * 2];
                mma16816(acc[mt][nt], ah[mt], pbh);
                mma16816(acc[mt][nt], ah[mt], pbl);
                mma16816(acc[mt][nt], al[mt], pbh);
            }
    }

    int lr = lane >> 2, lc = lane & 3;
#pragma unroll
    for (int mt = 0; mt < 4; mt++) {
        int p = wm + mt * 16 + lr;
#pragma unroll
        for (int half = 0; half < 2; half++) {
            int pp = p + half * 8;
            if (pp < PBLK) {
                float inv = 1.0f / NORMbuf[b * PBLK + pp];
                int tok = tok_of(nb, pp);
                size_t gb = (size_t)tok * DIMC + hh * HDIM;
#pragma unroll
                for (int nt = 0; nt < 4; nt++) {
                    int e = wn + nt * 8 + lc * 2;
                    float v0 = acc[mt][nt][2 * half]     * inv;
                    float v1 = acc[mt][nt][2 * half + 1] * inv;
                    *(uint32_t*)(AOh + gb + e) = h2pack(v0, v1);
                }
            }
        }
    }
}

// ---------------- launch ----------------
extern "C" void kernel_launch(void* const* d_in, const int* in_sizes, int n_in,
                              void* d_out, int out_size) {
    const float* x   = (const float*)d_in[0];
    const float* fc  = (const float*)d_in[3];
    const float* fs  = (const float*)d_in[4];
    const float* wq  = (const float*)d_in[5];
    const float* bq  = (const float*)d_in[6];
    const float* wk  = (const float*)d_in[7];
    const float* bk  = (const float*)d_in[8];
    const float* wv  = (const float*)d_in[9];
    const float* bv  = (const float*)d_in[10];
    const float* wo  = (const float*)d_in[11];
    const float* bo  = (const float*)d_in[12];
    const float* nqw = (const float*)d_in[13];
    const float* nkw = (const float*)d_in[14];
    float* out = (float*)d_out;

    void* pxh;
    cudaGetSymbolAddress(&pxh, Xh);

    cudaFuncSetAttribute(gemm_qkv,  cudaFuncAttributeMaxDynamicSharedMemorySize, GEMM_SMEM);
    cudaFuncSetAttribute(gemm_out,  cudaFuncAttributeMaxDynamicSharedMemorySize, GEMM_SMEM);
    cudaFuncSetAttribute(kv_kernel, cudaFuncAttributeMaxDynamicSharedMemorySize, KV2_SMEM);
    cudaFuncSetAttribute(mix_tc_kernel, cudaFuncAttributeMaxDynamicSharedMemorySize, MIX2_SMEM);
    cudaFuncSetAttribute(out_kernel, cudaFuncAttributeMaxDynamicSharedMemorySize, OUT2_SMEM);

    wblk_kernel<<<NBLK, 256>>>();
    conv_half<<<(MPAD * DIMC) / 256, 256>>>(x, (__half*)pxh, NTOK * DIMC, MPAD * DIMC);
    conv_w4<<<dim3((DIMC * DIMC) / 256, 4), 256>>>(wq, wk, wv, wo);

    dim3 gg(DIMC / 128, MPAD / 128, 3);
    gemm_qkv<<<gg, 256, GEMM_SMEM>>>(bq, bk, bv);

    rmsnorm_rope_kernel<<<dim3(NTOK, 2), 256>>>(nqw, nkw, fc, fs);

    qk_kernel<<<NHEAD * NBLK, HDIM>>>();
    kv_kernel<<<NHEAD * NBLK, 256, KV2_SMEM>>>();
    mix_tc_kernel<<<dim3(128, NHEAD), 256, MIX2_SMEM>>>();
    norm_kernel<<<NHEAD * NBLK, 128>>>();
    out_kernel<<<NHEAD * NBLK, 256, OUT2_SMEM>>>();

    dim3 go(DIMC / 128, MPAD / 128);
    gemm_out<<<go, 256, GEMM_SMEM>>>(bo, out);
}